// round 10
// baseline (speedup 1.0000x reference)
#include <cuda_runtime.h>
#include <math.h>
#include <stdint.h>

// ---------------- problem constants ----------------
constexpr int Bc   = 2;
constexpr int Sc   = 2048;
constexpr int Hc   = 2048;
constexpr int Tc   = Bc * Sc;      // 4096 tokens
constexpr int Ec   = 8;
constexpr int IM   = 1408;
constexpr int ISH  = 5632;
constexpr int NQc  = 16;
constexpr int NKVc = 2;
constexpr int DHc  = 128;
constexpr float EPSc = 1e-5f;

// rounded-weight scratch offsets (original [k][n] layout)
constexpr size_t OFF_WQ  = 0;
constexpr size_t OFF_WK  = OFF_WQ  + (size_t)2048 * 2048;
constexpr size_t OFF_WV  = OFF_WK  + (size_t)2048 * 256;
constexpr size_t OFF_WO  = OFF_WV  + (size_t)2048 * 256;
constexpr size_t OFF_WG  = OFF_WO  + (size_t)2048 * 2048;
constexpr size_t OFF_WU  = OFF_WG  + (size_t)Ec * 2048 * IM;
constexpr size_t OFF_WD  = OFF_WU  + (size_t)Ec * 2048 * IM;
constexpr size_t OFF_SWG = OFF_WD  + (size_t)Ec * IM * 2048;
constexpr size_t OFF_SWU = OFF_SWG + (size_t)2048 * ISH;
constexpr size_t OFF_SWD = OFF_SWU + (size_t)2048 * ISH;
constexpr size_t WR_TOT  = OFF_SWD + (size_t)ISH * 2048;

// ---------------- scratch (device globals; no allocations allowed) ----------------
__device__ float g_wr [WR_TOT];                      // tf32-rounded weights
__device__ float g_h  [(size_t)Tc * Hc];
__device__ float g_q  [(size_t)Tc * NQc * DHc];
__device__ float g_k  [(size_t)Tc * NKVc * DHc];
__device__ float g_v  [(size_t)Tc * NKVc * DHc];
__device__ float g_kT [(size_t)Bc * NKVc * DHc * Sc];
__device__ float g_sc [(size_t)Bc * NQc * Sc * Sc];  // scores -> probs in place
__device__ float g_ao [(size_t)Tc * Hc];
__device__ float g_x  [(size_t)Tc * Hc];
__device__ float g_t2 [(size_t)Tc * Hc];             // exact (router/sgate)
__device__ float g_t2r[(size_t)Tc * Hc];             // tf32-rounded (GEMM A)
__device__ float g_dw [Tc * Ec];
__device__ int   g_cnt[Ec];
__device__ int   g_list[Ec * Tc];
__device__ float g_mg [(size_t)Ec * Tc * IM];
__device__ float g_mu [(size_t)Ec * Tc * IM];
__device__ float g_moe[(size_t)Tc * Hc];
__device__ float g_sgv[(size_t)Tc * ISH];
__device__ float g_suv[(size_t)Tc * ISH];
__device__ float g_sh [(size_t)Tc * Hc];
__device__ float g_sgate[Tc];

__device__ __forceinline__ float tf32r(float x) {
    uint32_t u;
    asm("cvt.rna.tf32.f32 %0, %1;" : "=r"(u) : "f"(x));
    return __uint_as_float(u);
}

// ---------------- weight rounding ----------------
template<size_t OFF>
__global__ void round_copy_kernel(const float* __restrict__ src, int n) {
    const int i = blockIdx.x * 256 + threadIdx.x;
    if (i < n) g_wr[OFF + i] = tf32r(src[i]);
}

// ---------------- small kernels ----------------
__global__ void clear_cnt_kernel() {
    if (threadIdx.x < Ec) g_cnt[threadIdx.x] = 0;
}
__global__ void clear_moe_kernel() {
    g_moe[(size_t)blockIdx.x * 256 + threadIdx.x] = 0.f;
}

template<int PHASE>
__global__ void rmsnorm_kernel(const float* __restrict__ xin,
                               const float* __restrict__ scale) {
    __shared__ float red[256];
    const int row = blockIdx.x;
    const float* x = (PHASE == 0) ? (xin + (size_t)row * Hc) : (g_x + (size_t)row * Hc);
    float s = 0.f;
    for (int i = threadIdx.x; i < Hc; i += 256) { float v = x[i]; s += v * v; }
    red[threadIdx.x] = s; __syncthreads();
    for (int o = 128; o > 0; o >>= 1) {
        if (threadIdx.x < o) red[threadIdx.x] += red[threadIdx.x + o];
        __syncthreads();
    }
    const float inv = rsqrtf(red[0] / (float)Hc + EPSc);
    for (int i = threadIdx.x; i < Hc; i += 256) {
        const float v = x[i] * inv * scale[i];
        if (PHASE == 0) {
            g_h[(size_t)row * Hc + i] = tf32r(v);
        } else {
            g_t2 [(size_t)row * Hc + i] = v;
            g_t2r[(size_t)row * Hc + i] = tf32r(v);
        }
    }
}

__global__ void rope_kernel() {
    const int tok  = blockIdx.x;
    const int head = blockIdx.y;
    const int j    = threadIdx.x;         // 0..63
    const int s    = tok & (Sc - 1);
    const float inv = powf(10000.f, -(float)(2 * j) / 128.f);
    const float ang = (float)s * inv;
    float si, c;
    sincosf(ang, &si, &c);
    float* p = (head < NQc) ? (g_q + (size_t)tok * (NQc * DHc) + head * DHc)
                            : (g_k + (size_t)tok * (NKVc * DHc) + (head - NQc) * DHc);
    const float x1 = p[j], x2 = p[j + 64];
    p[j]      = tf32r(x1 * c - x2 * si);
    p[j + 64] = tf32r(x2 * c + x1 * si);
}

__global__ void kT_kernel() {
    const int i  = blockIdx.x * 256 + threadIdx.x;
    const int s  = i & (Sc - 1);
    const int d  = (i >> 11) & 127;
    const int bk = i >> 18;
    g_kT[i] = g_k[((size_t)((bk >> 1) * Sc + s)) * (NKVc * DHc) + (bk & 1) * DHc + d];
}

// single-pass register-resident causal softmax
__global__ void softmax_kernel() {
    __shared__ float red[256];
    const size_t rid = blockIdx.x;
    const int r   = (int)(rid & (Sc - 1));
    float* sc = g_sc + rid * Sc;
    const int lim = r + 1;
    const int nf4 = (lim + 3) >> 2;
    const int tid = threadIdx.x;

    float4 v4[2];
    float m = -1e30f;
#pragma unroll
    for (int s4 = 0; s4 < 2; s4++) {
        const int j = tid + s4 * 256;
        if (j < nf4) {
            float4 v = *(const float4*)(sc + j * 4);
            const int c0 = j * 4;
            if (c0 + 0 >= lim) v.x = -1e30f;
            if (c0 + 1 >= lim) v.y = -1e30f;
            if (c0 + 2 >= lim) v.z = -1e30f;
            if (c0 + 3 >= lim) v.w = -1e30f;
            v4[s4] = v;
            m = fmaxf(m, fmaxf(fmaxf(v.x, v.y), fmaxf(v.z, v.w)));
        } else {
            v4[s4] = make_float4(-1e30f, -1e30f, -1e30f, -1e30f);
        }
    }
    red[tid] = m; __syncthreads();
    for (int o = 128; o > 0; o >>= 1) {
        if (tid < o) red[tid] = fmaxf(red[tid], red[tid + o]);
        __syncthreads();
    }
    m = red[0]; __syncthreads();

    float s = 0.f;
#pragma unroll
    for (int s4 = 0; s4 < 2; s4++) {
        float4& v = v4[s4];
        v.x = (v.x > -1e29f) ? expf(v.x - m) : 0.f;
        v.y = (v.y > -1e29f) ? expf(v.y - m) : 0.f;
        v.z = (v.z > -1e29f) ? expf(v.z - m) : 0.f;
        v.w = (v.w > -1e29f) ? expf(v.w - m) : 0.f;
        s += v.x + v.y + v.z + v.w;
    }
    red[tid] = s; __syncthreads();
    for (int o = 128; o > 0; o >>= 1) {
        if (tid < o) red[tid] += red[tid + o];
        __syncthreads();
    }
    const float inv = 1.f / red[0];

#pragma unroll
    for (int s4 = 0; s4 < 2; s4++) {
        const int j = tid + s4 * 256;
        float4 o4;
        const float4 v = v4[s4];
        o4.x = tf32r(v.x * inv); o4.y = tf32r(v.y * inv);
        o4.z = tf32r(v.z * inv); o4.w = tf32r(v.w * inv);
        *(float4*)(sc + j * 4) = o4;
    }
}

__global__ void router_kernel(const float* __restrict__ rw) {
    const int tok  = blockIdx.x * 8 + (threadIdx.x >> 5);
    const int lane = threadIdx.x & 31;
    const float* tr = g_t2 + (size_t)tok * Hc;
    float acc[8];
#pragma unroll
    for (int e = 0; e < 8; e++) acc[e] = 0.f;
    for (int h = lane; h < Hc; h += 32) {
        const float tv = tr[h];
        const float* rp = rw + h * 8;
#pragma unroll
        for (int e = 0; e < 8; e++) acc[e] += tv * rp[e];
    }
#pragma unroll
    for (int e = 0; e < 8; e++)
        for (int o = 16; o; o >>= 1) acc[e] += __shfl_xor_sync(0xffffffffu, acc[e], o);
    if (lane == 0) {
        float m = acc[0];
        for (int e = 1; e < 8; e++) m = fmaxf(m, acc[e]);
        float p[8], s = 0.f;
        for (int e = 0; e < 8; e++) { p[e] = expf(acc[e] - m); s += p[e]; }
        for (int e = 0; e < 8; e++) p[e] /= s;
        bool used[8] = {false,false,false,false,false,false,false,false};
        int isel[4]; float wsel[4]; float tsum = 0.f;
        for (int kk = 0; kk < 4; kk++) {
            int best = 0; float bv = -1.f;
            for (int e = 0; e < 8; e++)
                if (!used[e] && p[e] > bv) { bv = p[e]; best = e; }
            used[best] = true; isel[kk] = best; wsel[kk] = bv; tsum += bv;
        }
        float outw[8] = {0,0,0,0,0,0,0,0};
        for (int kk = 0; kk < 4; kk++) outw[isel[kk]] = wsel[kk] / tsum;
        for (int e = 0; e < 8; e++) g_dw[tok * 8 + e] = outw[e];
        for (int kk = 0; kk < 4; kk++) {
            const int pos = atomicAdd(&g_cnt[isel[kk]], 1);
            g_list[isel[kk] * Tc + pos] = tok;
        }
    }
}

__global__ void moe_act_kernel() {
    const int e = blockIdx.z, row = blockIdx.y;
    if (row >= g_cnt[e]) return;
    const int col = blockIdx.x * 256 + threadIdx.x;
    if (col >= IM) return;
    const size_t i = ((size_t)e * Tc + row) * IM + col;
    const float g = g_mg[i], u = g_mu[i];
    g_mg[i] = tf32r(g / (1.f + expf(-g)) * u);
}

__global__ void shared_act_kernel() {
    const size_t i = (size_t)blockIdx.x * 256 + threadIdx.x;
    const float g = g_sgv[i], u = g_suv[i];
    g_sgv[i] = tf32r(g / (1.f + expf(-g)) * u);
}

__global__ void sgate_kernel(const float* __restrict__ sgw) {
    const int tok  = blockIdx.x * 8 + (threadIdx.x >> 5);
    const int lane = threadIdx.x & 31;
    const float* tr = g_t2 + (size_t)tok * Hc;
    float s = 0.f;
    for (int h = lane; h < Hc; h += 32) s += tr[h] * sgw[h];
    for (int o = 16; o; o >>= 1) s += __shfl_xor_sync(0xffffffffu, s, o);
    if (lane == 0) g_sgate[tok] = 1.f / (1.f + expf(-s));
}

__global__ void final_kernel(float* __restrict__ out) {
    const size_t i = (size_t)blockIdx.x * 256 + threadIdx.x;
    const int row = (int)(i >> 11);
    out[i] = g_x[i] + g_moe[i] + g_sgate[row] * g_sh[i];
}

// ---------------- tf32 GEMM: cp.async + ldmatrix-A, 64x64 warp tile ----------------
enum GMode { GM_Q, GM_K, GM_V, GM_SCORES, GM_PV, GM_O,
             GM_MG, GM_MU, GM_MD, GM_SG, GM_SU, GM_SD };

__device__ __forceinline__ void mma_tf32(float* c, const uint32_t* a, const uint32_t* b) {
    asm volatile(
        "mma.sync.aligned.m16n8k8.row.col.f32.tf32.tf32.f32 "
        "{%0,%1,%2,%3}, {%4,%5,%6,%7}, {%8,%9}, {%0,%1,%2,%3};"
        : "+f"(c[0]), "+f"(c[1]), "+f"(c[2]), "+f"(c[3])
        : "r"(a[0]), "r"(a[1]), "r"(a[2]), "r"(a[3]), "r"(b[0]), "r"(b[1]));
}

__device__ __forceinline__ void ldsm4(uint32_t& r0, uint32_t& r1, uint32_t& r2, uint32_t& r3,
                                      uint32_t addr) {
    asm volatile("ldmatrix.sync.aligned.m8n8.x4.shared.b16 {%0,%1,%2,%3}, [%4];"
                 : "=r"(r0), "=r"(r1), "=r"(r2), "=r"(r3) : "r"(addr));
}

__device__ __forceinline__ void cpa16(uint32_t dst, const void* src, int sz) {
    asm volatile("cp.async.cg.shared.global [%0], [%1], 16, %2;\n"
                 :: "r"(dst), "l"(src), "r"(sz));
}
__device__ __forceinline__ void cpa_commit() {
    asm volatile("cp.async.commit_group;\n");
}
__device__ __forceinline__ void cpa_wait0() {
    asm volatile("cp.async.wait_group 0;\n" ::: "memory");
}

constexpr int AST = 20;    // As stride (floats): conflict-free LDSM + cp.async
constexpr int BST = 136;   // Bs stride (floats)

// BM=128, BN=128, BK=16; 128 threads = 4 warps (2x2), warp tile 64x64.
// 4 CTAs/SM (16 warps) to hide LDS/LDSM latency and barrier stalls.
template<int MODE>
__global__ __launch_bounds__(128, 4) void gemm_kernel(const float* __restrict__ extra) {
    constexpr int Kv =
        (MODE==GM_SCORES) ? 128 :
        (MODE==GM_PV) ? Sc :
        (MODE==GM_MD) ? IM :
        (MODE==GM_SD) ? ISH : 2048;

    const int tid = threadIdx.x;
    const int z   = blockIdx.z;
    const int m0  = blockIdx.y * 128, n0 = blockIdx.x * 128;

    int Mz;
    if (MODE==GM_SCORES || MODE==GM_PV) Mz = Sc;
    else if (MODE==GM_MG || MODE==GM_MU || MODE==GM_MD) Mz = g_cnt[z];
    else Mz = Tc;
    if (m0 >= Mz) return;
    if (MODE==GM_SCORES && n0 > m0 + 127) return;   // fully masked tile

    int bb = 0, hh = 0;
    if (MODE==GM_SCORES || MODE==GM_PV) { bb = z >> 4; hh = z & 15; }

    const float* A; const float* Bp; int lda, ldb;
    if (MODE==GM_Q) {
        A = g_h; lda = Hc; Bp = g_wr + OFF_WQ; ldb = 2048;
    } else if (MODE==GM_K) {
        A = g_h; lda = Hc; Bp = g_wr + OFF_WK; ldb = 256;
    } else if (MODE==GM_V) {
        A = g_h; lda = Hc; Bp = g_wr + OFF_WV; ldb = 256;
    } else if (MODE==GM_SCORES) {
        A = g_q + (size_t)bb * Sc * 2048 + hh * 128; lda = 2048;
        Bp = g_kT + (size_t)(bb * 2 + (hh >> 3)) * 128 * Sc; ldb = Sc;
    } else if (MODE==GM_PV) {
        A = g_sc + (size_t)z * Sc * Sc; lda = Sc;
        Bp = g_v + (size_t)bb * Sc * 256 + (hh >> 3) * 128; ldb = 256;
    } else if (MODE==GM_O) {
        A = g_ao; lda = 2048; Bp = g_wr + OFF_WO; ldb = 2048;
    } else if (MODE==GM_MG) {
        A = g_t2r; lda = 2048; Bp = g_wr + OFF_WG + (size_t)z * 2048 * IM; ldb = IM;
    } else if (MODE==GM_MU) {
        A = g_t2r; lda = 2048; Bp = g_wr + OFF_WU + (size_t)z * 2048 * IM; ldb = IM;
    } else if (MODE==GM_MD) {
        A = g_mg + (size_t)z * Tc * IM; lda = IM;
        Bp = g_wr + OFF_WD + (size_t)z * IM * 2048; ldb = 2048;
    } else if (MODE==GM_SG) {
        A = g_t2r; lda = 2048; Bp = g_wr + OFF_SWG; ldb = ISH;
    } else if (MODE==GM_SU) {
        A = g_t2r; lda = 2048; Bp = g_wr + OFF_SWU; ldb = ISH;
    } else { // GM_SD
        A = g_sgv; lda = ISH; Bp = g_wr + OFF_SWD; ldb = 2048;
    }

    __shared__ float As[2][128][AST];   // [stage][m][k]
    __shared__ float Bs[2][16][BST];    // [stage][k][n]

    float acc[4][8][4];
#pragma unroll
    for (int i = 0; i < 4; i++)
#pragma unroll
        for (int j = 0; j < 8; j++)
#pragma unroll
            for (int r = 0; r < 4; r++) acc[i][j][r] = 0.f;

    const int lane = tid & 31, wid = tid >> 5;
    const int wm = (wid >> 1) * 64;
    const int wn = (wid & 1) * 64;

    // A loader: one row per thread
    const int lm = tid;
    const int agl = m0 + lm;
    const bool aval = agl < Mz;
    const float* arp;
    if (MODE==GM_MG || MODE==GM_MU)
        arp = A + (size_t)(aval ? g_list[z * Tc + agl] : 0) * lda;
    else
        arp = A + (size_t)(aval ? agl : 0) * lda;
    const int asz = aval ? 16 : 0;
    const int arot = (lm >> 3) & 3;   // chunk rotation -> conflict-free cp.async stores

    // B loader: per warp one k-row per chunk, 128 cols split across lanes
    const int bw = tid >> 5;          // k sub-row
    const int bn = (tid & 31) * 4;
    const float* bbase = Bp + n0;

    const int Kend = (MODE==GM_PV) ? (m0 + 128) : Kv;
    const int nt = Kend / 16;

    uint32_t sA[2], sB[2];
    sA[0] = (uint32_t)__cvta_generic_to_shared(&As[0][0][0]);
    sA[1] = (uint32_t)__cvta_generic_to_shared(&As[1][0][0]);
    sB[0] = (uint32_t)__cvta_generic_to_shared(&Bs[0][0][0]);
    sB[1] = (uint32_t)__cvta_generic_to_shared(&Bs[1][0][0]);

    auto load_stage = [&](int s, int k0) {
#pragma unroll
        for (int c = 0; c < 4; c++) {
            const int cc = (c + arot) & 3;
            cpa16(sA[s] + (uint32_t)(lm * AST + cc * 4) * 4, arp + k0 + cc * 4, asz);
        }
#pragma unroll
        for (int c = 0; c < 4; c++) {
            const int k = c * 4 + bw;
            cpa16(sB[s] + (uint32_t)(k * BST + bn) * 4,
                  bbase + (size_t)(k0 + k) * ldb + bn, 16);
        }
    };

    load_stage(0, 0);
    cpa_commit();

    const int cb = wn + (lane >> 2);
    const int kq = lane & 3;
    const int lrow = lane & 15;
    const int lcol = (lane >> 4) << 2;

    for (int t = 0; t < nt; t++) {
        cpa_wait0();
        __syncthreads();
        if (t + 1 < nt) load_stage((t + 1) & 1, (t + 1) * 16);
        cpa_commit();

        const int buf = t & 1;
#pragma unroll
        for (int ks = 0; ks < 2; ks++) {
            const int klo = ks * 8;
            const int kk = klo + kq;
            uint32_t af[4][4], bf[8][2];
#pragma unroll
            for (int i = 0; i < 4; i++) {
                const uint32_t addr = sA[buf] +
                    (uint32_t)((wm + i * 16 + lrow) * AST + klo + lcol) * 4;
                ldsm4(af[i][0], af[i][1], af[i][2], af[i][3], addr);
            }
#pragma unroll
            for (int j = 0; j < 8; j++) {
                bf[j][0] = __float_as_uint(Bs[buf][kk][cb + j * 8]);
                bf[j][1] = __float_as_uint(Bs[buf][kk + 4][cb + j * 8]);
            }
#pragma unroll
            for (int i = 0; i < 4; i++)
#pragma unroll
                for (int j = 0; j < 8; j++)
                    mma_tf32(acc[i][j], af[i], bf[j]);
        }
        __syncthreads();
    }

    // ---------------- epilogues ----------------
    const float scl = 0.08838834764831845f;  // 1/sqrt(128)
    constexpr bool RND = (MODE==GM_V || MODE==GM_PV);
#pragma unroll
    for (int i = 0; i < 4; i++) {
#pragma unroll
        for (int rr = 0; rr < 2; rr++) {
            const int r = m0 + wm + i * 16 + (lane >> 2) + rr * 8;
            if (r >= Mz) continue;
            if (MODE==GM_SCORES) {
                const size_t base = (size_t)z * Sc * Sc + (size_t)r * Sc;
#pragma unroll
                for (int j = 0; j < 8; j++) {
                    const int c = n0 + wn + j * 8 + (lane & 3) * 2;
                    float v0 = acc[i][j][rr * 2 + 0] * scl;
                    float v1 = acc[i][j][rr * 2 + 1] * scl;
                    if (c > r)     v0 = -1e9f;
                    if (c + 1 > r) v1 = -1e9f;
                    g_sc[base + c]     = v0;
                    g_sc[base + c + 1] = v1;
                }
            } else if (MODE==GM_MD) {
                const int tok = g_list[z * Tc + r];
                const float w = g_dw[tok * Ec + z];
                float* dst = g_moe + (size_t)tok * 2048;
#pragma unroll
                for (int j = 0; j < 8; j++) {
                    const int c = n0 + wn + j * 8 + (lane & 3) * 2;
                    atomicAdd(dst + c,     acc[i][j][rr * 2 + 0] * w);
                    atomicAdd(dst + c + 1, acc[i][j][rr * 2 + 1] * w);
                }
            } else {
                float* Cp; int ldc; const float* bias = nullptr; const float* res = nullptr;
                if (MODE==GM_Q)       { Cp = g_q;  ldc = 2048; bias = extra; }
                else if (MODE==GM_K)  { Cp = g_k;  ldc = 256;  bias = extra; }
                else if (MODE==GM_V)  { Cp = g_v;  ldc = 256;  bias = extra; }
                else if (MODE==GM_PV) { Cp = g_ao + (size_t)bb * Sc * 2048 + hh * 128; ldc = 2048; }
                else if (MODE==GM_O)  { Cp = g_x;  ldc = 2048; res = extra; }
                else if (MODE==GM_MG) { Cp = g_mg + (size_t)z * Tc * IM; ldc = IM; }
                else if (MODE==GM_MU) { Cp = g_mu + (size_t)z * Tc * IM; ldc = IM; }
                else if (MODE==GM_SG) { Cp = g_sgv; ldc = ISH; }
                else if (MODE==GM_SU) { Cp = g_suv; ldc = ISH; }
                else                  { Cp = g_sh;  ldc = 2048; }
                const size_t rowoff = (size_t)r * ldc;
#pragma unroll
                for (int j = 0; j < 8; j++) {
                    const int c = n0 + wn + j * 8 + (lane & 3) * 2;
                    float v0 = acc[i][j][rr * 2 + 0];
                    float v1 = acc[i][j][rr * 2 + 1];
                    if (bias) { v0 += bias[c]; v1 += bias[c + 1]; }
                    if (res)  { v0 += res[rowoff + c]; v1 += res[rowoff + c + 1]; }
                    if (RND)  { v0 = tf32r(v0); v1 = tf32r(v1); }
                    Cp[rowoff + c]     = v0;
                    Cp[rowoff + c + 1] = v1;
                }
            }
        }
    }
}

// ---------------- launch ----------------
extern "C" void kernel_launch(void* const* d_in, const int* in_sizes, int n_in,
                              void* d_out, int out_size) {
    (void)in_sizes; (void)n_in; (void)out_size;
    const float* x0  = (const float*)d_in[0];
    const float* ln1 = (const float*)d_in[1];
    const float* wq  = (const float*)d_in[2];
    const float* bq  = (const float*)d_in[3];
    const float* wk  = (const float*)d_in[4];
    const float* bk  = (const float*)d_in[5];
    const float* wv  = (const float*)d_in[6];
    const float* bv  = (const float*)d_in[7];
    const float* wo  = (const float*)d_in[8];
    const float* ln2 = (const float*)d_in[9];
    const float* rw  = (const float*)d_in[10];
    const float* wg  = (const float*)d_in[11];
    const float* wu  = (const float*)d_in[12];
    const float* wd  = (const float*)d_in[13];
    const float* swg = (const float*)d_in[14];
    const float* swu = (const float*)d_in[15];
    const float* swd = (const float*)d_in[16];
    const float* sgw = (const float*)d_in[17];
    float* out = (float*)d_out;

    auto blocks = [](size_t n) { return (unsigned)((n + 255) / 256); };

    round_copy_kernel<OFF_WQ ><<<blocks((size_t)2048*2048), 256>>>(wq,  2048*2048);
    round_copy_kernel<OFF_WK ><<<blocks((size_t)2048*256),  256>>>(wk,  2048*256);
    round_copy_kernel<OFF_WV ><<<blocks((size_t)2048*256),  256>>>(wv,  2048*256);
    round_copy_kernel<OFF_WO ><<<blocks((size_t)2048*2048), 256>>>(wo,  2048*2048);
    round_copy_kernel<OFF_WG ><<<blocks((size_t)Ec*2048*IM),256>>>(wg,  Ec*2048*IM);
    round_copy_kernel<OFF_WU ><<<blocks((size_t)Ec*2048*IM),256>>>(wu,  Ec*2048*IM);
    round_copy_kernel<OFF_WD ><<<blocks((size_t)Ec*IM*2048),256>>>(wd,  Ec*IM*2048);
    round_copy_kernel<OFF_SWG><<<blocks((size_t)2048*ISH),  256>>>(swg, 2048*ISH);
    round_copy_kernel<OFF_SWU><<<blocks((size_t)2048*ISH),  256>>>(swu, 2048*ISH);
    round_copy_kernel<OFF_SWD><<<blocks((size_t)ISH*2048),  256>>>(swd, ISH*2048);

    clear_cnt_kernel<<<1, 32>>>();
    clear_moe_kernel<<<(Tc * Hc) / 256, 256>>>();

    // attention
    rmsnorm_kernel<0><<<Tc, 256>>>(x0, ln1);
    gemm_kernel<GM_Q><<<dim3(16, 32, 1), 128>>>(bq);
    gemm_kernel<GM_K><<<dim3(2, 32, 1), 128>>>(bk);
    gemm_kernel<GM_V><<<dim3(2, 32, 1), 128>>>(bv);
    rope_kernel<<<dim3(Tc, NQc + NKVc), 64>>>();
    kT_kernel<<<(Bc * NKVc * DHc * Sc) / 256, 256>>>();
    gemm_kernel<GM_SCORES><<<dim3(16, 16, 32), 128>>>(nullptr);
    softmax_kernel<<<Bc * NQc * Sc, 256>>>();
    gemm_kernel<GM_PV><<<dim3(1, 16, 32), 128>>>(nullptr);
    gemm_kernel<GM_O><<<dim3(16, 32, 1), 128>>>(x0);

    // MoE block
    rmsnorm_kernel<1><<<Tc, 256>>>(nullptr, ln2);
    router_kernel<<<Tc / 8, 256>>>(rw);
    gemm_kernel<GM_MG><<<dim3(11, 32, 8), 128>>>(nullptr);
    gemm_kernel<GM_MU><<<dim3(11, 32, 8), 128>>>(nullptr);
    moe_act_kernel<<<dim3(6, Tc, 8), 256>>>();
    gemm_kernel<GM_MD><<<dim3(16, 32, 8), 128>>>(nullptr);

    // shared expert
    gemm_kernel<GM_SG><<<dim3(44, 32, 1), 128>>>(nullptr);
    gemm_kernel<GM_SU><<<dim3(44, 32, 1), 128>>>(nullptr);
    shared_act_kernel<<<(size_t)(Tc) * ISH / 256, 256>>>();
    sgate_kernel<<<Tc / 8, 256>>>(sgw);
    gemm_kernel<GM_SD><<<dim3(16, 32, 1), 128>>>(nullptr);

    final_kernel<<<(Tc * Hc) / 256, 256>>>(out);
}

// round 11
// speedup vs baseline: 1.9166x; 1.9166x over previous
#include <cuda_runtime.h>
#include <math.h>
#include <stdint.h>

// ---------------- problem constants ----------------
constexpr int Bc   = 2;
constexpr int Sc   = 2048;
constexpr int Hc   = 2048;
constexpr int Tc   = Bc * Sc;      // 4096 tokens
constexpr int Ec   = 8;
constexpr int IM   = 1408;
constexpr int ISH  = 5632;
constexpr int NQc  = 16;
constexpr int NKVc = 2;
constexpr int DHc  = 128;
constexpr float EPSc = 1e-5f;

// rounded-weight scratch offsets (original [k][n] layout)
constexpr size_t OFF_WQ  = 0;
constexpr size_t OFF_WK  = OFF_WQ  + (size_t)2048 * 2048;
constexpr size_t OFF_WV  = OFF_WK  + (size_t)2048 * 256;
constexpr size_t OFF_WO  = OFF_WV  + (size_t)2048 * 256;
constexpr size_t OFF_WG  = OFF_WO  + (size_t)2048 * 2048;
constexpr size_t OFF_WU  = OFF_WG  + (size_t)Ec * 2048 * IM;
constexpr size_t OFF_WD  = OFF_WU  + (size_t)Ec * 2048 * IM;
constexpr size_t OFF_SWG = OFF_WD  + (size_t)Ec * IM * 2048;
constexpr size_t OFF_SWU = OFF_SWG + (size_t)2048 * ISH;
constexpr size_t OFF_SWD = OFF_SWU + (size_t)2048 * ISH;
constexpr size_t WR_TOT  = OFF_SWD + (size_t)ISH * 2048;

// ---------------- scratch (device globals; no allocations allowed) ----------------
__device__ float g_wr [WR_TOT];                      // tf32-rounded weights
__device__ float g_h  [(size_t)Tc * Hc];
__device__ float g_q  [(size_t)Tc * NQc * DHc];
__device__ float g_k  [(size_t)Tc * NKVc * DHc];
__device__ float g_v  [(size_t)Tc * NKVc * DHc];
__device__ float g_kT [(size_t)Bc * NKVc * DHc * Sc];
__device__ float g_sc [(size_t)Bc * NQc * Sc * Sc];  // scores -> probs in place
__device__ float g_ao [(size_t)Tc * Hc];
__device__ float g_x  [(size_t)Tc * Hc];
__device__ float g_t2 [(size_t)Tc * Hc];             // exact (router/sgate)
__device__ float g_t2r[(size_t)Tc * Hc];             // tf32-rounded (GEMM A)
__device__ float g_dw [Tc * Ec];
__device__ int   g_cnt[Ec];
__device__ int   g_list[Ec * Tc];
__device__ float g_mg [(size_t)Ec * Tc * IM];
__device__ float g_mu [(size_t)Ec * Tc * IM];
__device__ float g_moe[(size_t)Tc * Hc];
__device__ float g_sgv[(size_t)Tc * ISH];
__device__ float g_suv[(size_t)Tc * ISH];
__device__ float g_sh [(size_t)Tc * Hc];
__device__ float g_sgate[Tc];

__device__ __forceinline__ float tf32r(float x) {
    uint32_t u;
    asm("cvt.rna.tf32.f32 %0, %1;" : "=r"(u) : "f"(x));
    return __uint_as_float(u);
}

// ---------------- weight rounding ----------------
template<size_t OFF>
__global__ void round_copy_kernel(const float* __restrict__ src, int n) {
    const int i = blockIdx.x * 256 + threadIdx.x;
    if (i < n) g_wr[OFF + i] = tf32r(src[i]);
}

// ---------------- small kernels ----------------
__global__ void clear_cnt_kernel() {
    if (threadIdx.x < Ec) g_cnt[threadIdx.x] = 0;
}
__global__ void clear_moe_kernel() {
    g_moe[(size_t)blockIdx.x * 256 + threadIdx.x] = 0.f;
}

template<int PHASE>
__global__ void rmsnorm_kernel(const float* __restrict__ xin,
                               const float* __restrict__ scale) {
    __shared__ float red[256];
    const int row = blockIdx.x;
    const float* x = (PHASE == 0) ? (xin + (size_t)row * Hc) : (g_x + (size_t)row * Hc);
    float s = 0.f;
    for (int i = threadIdx.x; i < Hc; i += 256) { float v = x[i]; s += v * v; }
    red[threadIdx.x] = s; __syncthreads();
    for (int o = 128; o > 0; o >>= 1) {
        if (threadIdx.x < o) red[threadIdx.x] += red[threadIdx.x + o];
        __syncthreads();
    }
    const float inv = rsqrtf(red[0] / (float)Hc + EPSc);
    for (int i = threadIdx.x; i < Hc; i += 256) {
        const float v = x[i] * inv * scale[i];
        if (PHASE == 0) {
            g_h[(size_t)row * Hc + i] = tf32r(v);
        } else {
            g_t2 [(size_t)row * Hc + i] = v;
            g_t2r[(size_t)row * Hc + i] = tf32r(v);
        }
    }
}

__global__ void rope_kernel() {
    const int tok  = blockIdx.x;
    const int head = blockIdx.y;
    const int j    = threadIdx.x;         // 0..63
    const int s    = tok & (Sc - 1);
    const float inv = powf(10000.f, -(float)(2 * j) / 128.f);
    const float ang = (float)s * inv;
    float si, c;
    sincosf(ang, &si, &c);
    float* p = (head < NQc) ? (g_q + (size_t)tok * (NQc * DHc) + head * DHc)
                            : (g_k + (size_t)tok * (NKVc * DHc) + (head - NQc) * DHc);
    const float x1 = p[j], x2 = p[j + 64];
    p[j]      = tf32r(x1 * c - x2 * si);
    p[j + 64] = tf32r(x2 * c + x1 * si);
}

__global__ void kT_kernel() {
    const int i  = blockIdx.x * 256 + threadIdx.x;
    const int s  = i & (Sc - 1);
    const int d  = (i >> 11) & 127;
    const int bk = i >> 18;
    g_kT[i] = g_k[((size_t)((bk >> 1) * Sc + s)) * (NKVc * DHc) + (bk & 1) * DHc + d];
}

// single-pass register-resident causal softmax
__global__ void softmax_kernel() {
    __shared__ float red[256];
    const size_t rid = blockIdx.x;
    const int r   = (int)(rid & (Sc - 1));
    float* sc = g_sc + rid * Sc;
    const int lim = r + 1;
    const int nf4 = (lim + 3) >> 2;
    const int tid = threadIdx.x;

    float4 v4[2];
    float m = -1e30f;
#pragma unroll
    for (int s4 = 0; s4 < 2; s4++) {
        const int j = tid + s4 * 256;
        if (j < nf4) {
            float4 v = *(const float4*)(sc + j * 4);
            const int c0 = j * 4;
            if (c0 + 0 >= lim) v.x = -1e30f;
            if (c0 + 1 >= lim) v.y = -1e30f;
            if (c0 + 2 >= lim) v.z = -1e30f;
            if (c0 + 3 >= lim) v.w = -1e30f;
            v4[s4] = v;
            m = fmaxf(m, fmaxf(fmaxf(v.x, v.y), fmaxf(v.z, v.w)));
        } else {
            v4[s4] = make_float4(-1e30f, -1e30f, -1e30f, -1e30f);
        }
    }
    red[tid] = m; __syncthreads();
    for (int o = 128; o > 0; o >>= 1) {
        if (tid < o) red[tid] = fmaxf(red[tid], red[tid + o]);
        __syncthreads();
    }
    m = red[0]; __syncthreads();

    float s = 0.f;
#pragma unroll
    for (int s4 = 0; s4 < 2; s4++) {
        float4& v = v4[s4];
        v.x = (v.x > -1e29f) ? expf(v.x - m) : 0.f;
        v.y = (v.y > -1e29f) ? expf(v.y - m) : 0.f;
        v.z = (v.z > -1e29f) ? expf(v.z - m) : 0.f;
        v.w = (v.w > -1e29f) ? expf(v.w - m) : 0.f;
        s += v.x + v.y + v.z + v.w;
    }
    red[tid] = s; __syncthreads();
    for (int o = 128; o > 0; o >>= 1) {
        if (tid < o) red[tid] += red[tid + o];
        __syncthreads();
    }
    const float inv = 1.f / red[0];

#pragma unroll
    for (int s4 = 0; s4 < 2; s4++) {
        const int j = tid + s4 * 256;
        float4 o4;
        const float4 v = v4[s4];
        o4.x = tf32r(v.x * inv); o4.y = tf32r(v.y * inv);
        o4.z = tf32r(v.z * inv); o4.w = tf32r(v.w * inv);
        *(float4*)(sc + j * 4) = o4;
    }
}

__global__ void router_kernel(const float* __restrict__ rw) {
    const int tok  = blockIdx.x * 8 + (threadIdx.x >> 5);
    const int lane = threadIdx.x & 31;
    const float* tr = g_t2 + (size_t)tok * Hc;
    float acc[8];
#pragma unroll
    for (int e = 0; e < 8; e++) acc[e] = 0.f;
    for (int h = lane; h < Hc; h += 32) {
        const float tv = tr[h];
        const float* rp = rw + h * 8;
#pragma unroll
        for (int e = 0; e < 8; e++) acc[e] += tv * rp[e];
    }
#pragma unroll
    for (int e = 0; e < 8; e++)
        for (int o = 16; o; o >>= 1) acc[e] += __shfl_xor_sync(0xffffffffu, acc[e], o);
    if (lane == 0) {
        float m = acc[0];
        for (int e = 1; e < 8; e++) m = fmaxf(m, acc[e]);
        float p[8], s = 0.f;
        for (int e = 0; e < 8; e++) { p[e] = expf(acc[e] - m); s += p[e]; }
        for (int e = 0; e < 8; e++) p[e] /= s;
        bool used[8] = {false,false,false,false,false,false,false,false};
        int isel[4]; float wsel[4]; float tsum = 0.f;
        for (int kk = 0; kk < 4; kk++) {
            int best = 0; float bv = -1.f;
            for (int e = 0; e < 8; e++)
                if (!used[e] && p[e] > bv) { bv = p[e]; best = e; }
            used[best] = true; isel[kk] = best; wsel[kk] = bv; tsum += bv;
        }
        float outw[8] = {0,0,0,0,0,0,0,0};
        for (int kk = 0; kk < 4; kk++) outw[isel[kk]] = wsel[kk] / tsum;
        for (int e = 0; e < 8; e++) g_dw[tok * 8 + e] = outw[e];
        for (int kk = 0; kk < 4; kk++) {
            const int pos = atomicAdd(&g_cnt[isel[kk]], 1);
            g_list[isel[kk] * Tc + pos] = tok;
        }
    }
}

__global__ void moe_act_kernel() {
    const int e = blockIdx.z, row = blockIdx.y;
    if (row >= g_cnt[e]) return;
    const int col = blockIdx.x * 256 + threadIdx.x;
    if (col >= IM) return;
    const size_t i = ((size_t)e * Tc + row) * IM + col;
    const float g = g_mg[i], u = g_mu[i];
    g_mg[i] = tf32r(g / (1.f + expf(-g)) * u);
}

__global__ void shared_act_kernel() {
    const size_t i = (size_t)blockIdx.x * 256 + threadIdx.x;
    const float g = g_sgv[i], u = g_suv[i];
    g_sgv[i] = tf32r(g / (1.f + expf(-g)) * u);
}

__global__ void sgate_kernel(const float* __restrict__ sgw) {
    const int tok  = blockIdx.x * 8 + (threadIdx.x >> 5);
    const int lane = threadIdx.x & 31;
    const float* tr = g_t2 + (size_t)tok * Hc;
    float s = 0.f;
    for (int h = lane; h < Hc; h += 32) s += tr[h] * sgw[h];
    for (int o = 16; o; o >>= 1) s += __shfl_xor_sync(0xffffffffu, s, o);
    if (lane == 0) g_sgate[tok] = 1.f / (1.f + expf(-s));
}

__global__ void final_kernel(float* __restrict__ out) {
    const size_t i = (size_t)blockIdx.x * 256 + threadIdx.x;
    const int row = (int)(i >> 11);
    out[i] = g_x[i] + g_moe[i] + g_sgate[row] * g_sh[i];
}

// ---------------- tf32 GEMM: cp.async + ldmatrix-A, 64x64 warp tile ----------------
enum GMode { GM_Q, GM_K, GM_V, GM_SCORES, GM_PV, GM_O,
             GM_MG, GM_MU, GM_MD, GM_SG, GM_SU, GM_SD };

__device__ __forceinline__ void mma_tf32(float* c, const uint32_t* a, const uint32_t* b) {
    asm volatile(
        "mma.sync.aligned.m16n8k8.row.col.f32.tf32.tf32.f32 "
        "{%0,%1,%2,%3}, {%4,%5,%6,%7}, {%8,%9}, {%0,%1,%2,%3};"
        : "+f"(c[0]), "+f"(c[1]), "+f"(c[2]), "+f"(c[3])
        : "r"(a[0]), "r"(a[1]), "r"(a[2]), "r"(a[3]), "r"(b[0]), "r"(b[1]));
}

__device__ __forceinline__ void ldsm4(uint32_t& r0, uint32_t& r1, uint32_t& r2, uint32_t& r3,
                                      uint32_t addr) {
    asm volatile("ldmatrix.sync.aligned.m8n8.x4.shared.b16 {%0,%1,%2,%3}, [%4];"
                 : "=r"(r0), "=r"(r1), "=r"(r2), "=r"(r3) : "r"(addr));
}

__device__ __forceinline__ void cpa16(uint32_t dst, const void* src, int sz) {
    asm volatile("cp.async.cg.shared.global [%0], [%1], 16, %2;\n"
                 :: "r"(dst), "l"(src), "r"(sz));
}
__device__ __forceinline__ void cpa_commit() {
    asm volatile("cp.async.commit_group;\n");
}
__device__ __forceinline__ void cpa_wait0() {
    asm volatile("cp.async.wait_group 0;\n" ::: "memory");
}

constexpr int AST = 20;    // As stride (floats): conflict-free LDSM + cp.async
constexpr int BST = 136;   // Bs stride (floats)

// BM=128, BN=128, BK=16; 128 threads = 4 warps (2x2), warp tile 64x64.
// 3 CTAs/SM (12 warps): reg cap 170 — fits the ~170-reg natural usage
// without the catastrophic spills the 4-CTA cap (128 regs) caused.
template<int MODE>
__global__ __launch_bounds__(128, 3) void gemm_kernel(const float* __restrict__ extra) {
    constexpr int Kv =
        (MODE==GM_SCORES) ? 128 :
        (MODE==GM_PV) ? Sc :
        (MODE==GM_MD) ? IM :
        (MODE==GM_SD) ? ISH : 2048;

    const int tid = threadIdx.x;
    const int z   = blockIdx.z;
    const int m0  = blockIdx.y * 128, n0 = blockIdx.x * 128;

    int Mz;
    if (MODE==GM_SCORES || MODE==GM_PV) Mz = Sc;
    else if (MODE==GM_MG || MODE==GM_MU || MODE==GM_MD) Mz = g_cnt[z];
    else Mz = Tc;
    if (m0 >= Mz) return;
    if (MODE==GM_SCORES && n0 > m0 + 127) return;   // fully masked tile

    int bb = 0, hh = 0;
    if (MODE==GM_SCORES || MODE==GM_PV) { bb = z >> 4; hh = z & 15; }

    const float* A; const float* Bp; int lda, ldb;
    if (MODE==GM_Q) {
        A = g_h; lda = Hc; Bp = g_wr + OFF_WQ; ldb = 2048;
    } else if (MODE==GM_K) {
        A = g_h; lda = Hc; Bp = g_wr + OFF_WK; ldb = 256;
    } else if (MODE==GM_V) {
        A = g_h; lda = Hc; Bp = g_wr + OFF_WV; ldb = 256;
    } else if (MODE==GM_SCORES) {
        A = g_q + (size_t)bb * Sc * 2048 + hh * 128; lda = 2048;
        Bp = g_kT + (size_t)(bb * 2 + (hh >> 3)) * 128 * Sc; ldb = Sc;
    } else if (MODE==GM_PV) {
        A = g_sc + (size_t)z * Sc * Sc; lda = Sc;
        Bp = g_v + (size_t)bb * Sc * 256 + (hh >> 3) * 128; ldb = 256;
    } else if (MODE==GM_O) {
        A = g_ao; lda = 2048; Bp = g_wr + OFF_WO; ldb = 2048;
    } else if (MODE==GM_MG) {
        A = g_t2r; lda = 2048; Bp = g_wr + OFF_WG + (size_t)z * 2048 * IM; ldb = IM;
    } else if (MODE==GM_MU) {
        A = g_t2r; lda = 2048; Bp = g_wr + OFF_WU + (size_t)z * 2048 * IM; ldb = IM;
    } else if (MODE==GM_MD) {
        A = g_mg + (size_t)z * Tc * IM; lda = IM;
        Bp = g_wr + OFF_WD + (size_t)z * IM * 2048; ldb = 2048;
    } else if (MODE==GM_SG) {
        A = g_t2r; lda = 2048; Bp = g_wr + OFF_SWG; ldb = ISH;
    } else if (MODE==GM_SU) {
        A = g_t2r; lda = 2048; Bp = g_wr + OFF_SWU; ldb = ISH;
    } else { // GM_SD
        A = g_sgv; lda = ISH; Bp = g_wr + OFF_SWD; ldb = 2048;
    }

    __shared__ float As[2][128][AST];   // [stage][m][k]
    __shared__ float Bs[2][16][BST];    // [stage][k][n]

    float acc[4][8][4];
#pragma unroll
    for (int i = 0; i < 4; i++)
#pragma unroll
        for (int j = 0; j < 8; j++)
#pragma unroll
            for (int r = 0; r < 4; r++) acc[i][j][r] = 0.f;

    const int lane = tid & 31, wid = tid >> 5;
    const int wm = (wid >> 1) * 64;
    const int wn = (wid & 1) * 64;

    // A loader: one row per thread
    const int lm = tid;
    const int agl = m0 + lm;
    const bool aval = agl < Mz;
    const float* arp;
    if (MODE==GM_MG || MODE==GM_MU)
        arp = A + (size_t)(aval ? g_list[z * Tc + agl] : 0) * lda;
    else
        arp = A + (size_t)(aval ? agl : 0) * lda;
    const int asz = aval ? 16 : 0;
    const int arot = (lm >> 3) & 3;   // chunk rotation -> conflict-free cp.async stores

    // B loader: per warp one k-row per chunk, 128 cols split across lanes
    const int bw = tid >> 5;          // k sub-row
    const int bn = (tid & 31) * 4;
    const float* bbase = Bp + n0;

    const int Kend = (MODE==GM_PV) ? (m0 + 128) : Kv;
    const int nt = Kend / 16;

    uint32_t sA[2], sB[2];
    sA[0] = (uint32_t)__cvta_generic_to_shared(&As[0][0][0]);
    sA[1] = (uint32_t)__cvta_generic_to_shared(&As[1][0][0]);
    sB[0] = (uint32_t)__cvta_generic_to_shared(&Bs[0][0][0]);
    sB[1] = (uint32_t)__cvta_generic_to_shared(&Bs[1][0][0]);

    auto load_stage = [&](int s, int k0) {
#pragma unroll
        for (int c = 0; c < 4; c++) {
            const int cc = (c + arot) & 3;
            cpa16(sA[s] + (uint32_t)(lm * AST + cc * 4) * 4, arp + k0 + cc * 4, asz);
        }
#pragma unroll
        for (int c = 0; c < 4; c++) {
            const int k = c * 4 + bw;
            cpa16(sB[s] + (uint32_t)(k * BST + bn) * 4,
                  bbase + (size_t)(k0 + k) * ldb + bn, 16);
        }
    };

    load_stage(0, 0);
    cpa_commit();

    const int cb = wn + (lane >> 2);
    const int kq = lane & 3;
    const int lrow = lane & 15;
    const int lcol = (lane >> 4) << 2;

    for (int t = 0; t < nt; t++) {
        cpa_wait0();
        __syncthreads();
        if (t + 1 < nt) load_stage((t + 1) & 1, (t + 1) * 16);
        cpa_commit();

        const int buf = t & 1;
#pragma unroll
        for (int ks = 0; ks < 2; ks++) {
            const int klo = ks * 8;
            const int kk = klo + kq;
            uint32_t af[4][4], bf[8][2];
#pragma unroll
            for (int i = 0; i < 4; i++) {
                const uint32_t addr = sA[buf] +
                    (uint32_t)((wm + i * 16 + lrow) * AST + klo + lcol) * 4;
                ldsm4(af[i][0], af[i][1], af[i][2], af[i][3], addr);
            }
#pragma unroll
            for (int j = 0; j < 8; j++) {
                bf[j][0] = __float_as_uint(Bs[buf][kk][cb + j * 8]);
                bf[j][1] = __float_as_uint(Bs[buf][kk + 4][cb + j * 8]);
            }
#pragma unroll
            for (int i = 0; i < 4; i++)
#pragma unroll
                for (int j = 0; j < 8; j++)
                    mma_tf32(acc[i][j], af[i], bf[j]);
        }
        __syncthreads();
    }

    // ---------------- epilogues ----------------
    const float scl = 0.08838834764831845f;  // 1/sqrt(128)
    constexpr bool RND = (MODE==GM_V || MODE==GM_PV);
#pragma unroll
    for (int i = 0; i < 4; i++) {
#pragma unroll
        for (int rr = 0; rr < 2; rr++) {
            const int r = m0 + wm + i * 16 + (lane >> 2) + rr * 8;
            if (r >= Mz) continue;
            if (MODE==GM_SCORES) {
                const size_t base = (size_t)z * Sc * Sc + (size_t)r * Sc;
#pragma unroll
                for (int j = 0; j < 8; j++) {
                    const int c = n0 + wn + j * 8 + (lane & 3) * 2;
                    float v0 = acc[i][j][rr * 2 + 0] * scl;
                    float v1 = acc[i][j][rr * 2 + 1] * scl;
                    if (c > r)     v0 = -1e9f;
                    if (c + 1 > r) v1 = -1e9f;
                    g_sc[base + c]     = v0;
                    g_sc[base + c + 1] = v1;
                }
            } else if (MODE==GM_MD) {
                const int tok = g_list[z * Tc + r];
                const float w = g_dw[tok * Ec + z];
                float* dst = g_moe + (size_t)tok * 2048;
#pragma unroll
                for (int j = 0; j < 8; j++) {
                    const int c = n0 + wn + j * 8 + (lane & 3) * 2;
                    atomicAdd(dst + c,     acc[i][j][rr * 2 + 0] * w);
                    atomicAdd(dst + c + 1, acc[i][j][rr * 2 + 1] * w);
                }
            } else {
                float* Cp; int ldc; const float* bias = nullptr; const float* res = nullptr;
                if (MODE==GM_Q)       { Cp = g_q;  ldc = 2048; bias = extra; }
                else if (MODE==GM_K)  { Cp = g_k;  ldc = 256;  bias = extra; }
                else if (MODE==GM_V)  { Cp = g_v;  ldc = 256;  bias = extra; }
                else if (MODE==GM_PV) { Cp = g_ao + (size_t)bb * Sc * 2048 + hh * 128; ldc = 2048; }
                else if (MODE==GM_O)  { Cp = g_x;  ldc = 2048; res = extra; }
                else if (MODE==GM_MG) { Cp = g_mg + (size_t)z * Tc * IM; ldc = IM; }
                else if (MODE==GM_MU) { Cp = g_mu + (size_t)z * Tc * IM; ldc = IM; }
                else if (MODE==GM_SG) { Cp = g_sgv; ldc = ISH; }
                else if (MODE==GM_SU) { Cp = g_suv; ldc = ISH; }
                else                  { Cp = g_sh;  ldc = 2048; }
                const size_t rowoff = (size_t)r * ldc;
#pragma unroll
                for (int j = 0; j < 8; j++) {
                    const int c = n0 + wn + j * 8 + (lane & 3) * 2;
                    float v0 = acc[i][j][rr * 2 + 0];
                    float v1 = acc[i][j][rr * 2 + 1];
                    if (bias) { v0 += bias[c]; v1 += bias[c + 1]; }
                    if (res)  { v0 += res[rowoff + c]; v1 += res[rowoff + c + 1]; }
                    if (RND)  { v0 = tf32r(v0); v1 = tf32r(v1); }
                    Cp[rowoff + c]     = v0;
                    Cp[rowoff + c + 1] = v1;
                }
            }
        }
    }
}

// ---------------- launch ----------------
extern "C" void kernel_launch(void* const* d_in, const int* in_sizes, int n_in,
                              void* d_out, int out_size) {
    (void)in_sizes; (void)n_in; (void)out_size;
    const float* x0  = (const float*)d_in[0];
    const float* ln1 = (const float*)d_in[1];
    const float* wq  = (const float*)d_in[2];
    const float* bq  = (const float*)d_in[3];
    const float* wk  = (const float*)d_in[4];
    const float* bk  = (const float*)d_in[5];
    const float* wv  = (const float*)d_in[6];
    const float* bv  = (const float*)d_in[7];
    const float* wo  = (const float*)d_in[8];
    const float* ln2 = (const float*)d_in[9];
    const float* rw  = (const float*)d_in[10];
    const float* wg  = (const float*)d_in[11];
    const float* wu  = (const float*)d_in[12];
    const float* wd  = (const float*)d_in[13];
    const float* swg = (const float*)d_in[14];
    const float* swu = (const float*)d_in[15];
    const float* swd = (const float*)d_in[16];
    const float* sgw = (const float*)d_in[17];
    float* out = (float*)d_out;

    auto blocks = [](size_t n) { return (unsigned)((n + 255) / 256); };

    round_copy_kernel<OFF_WQ ><<<blocks((size_t)2048*2048), 256>>>(wq,  2048*2048);
    round_copy_kernel<OFF_WK ><<<blocks((size_t)2048*256),  256>>>(wk,  2048*256);
    round_copy_kernel<OFF_WV ><<<blocks((size_t)2048*256),  256>>>(wv,  2048*256);
    round_copy_kernel<OFF_WO ><<<blocks((size_t)2048*2048), 256>>>(wo,  2048*2048);
    round_copy_kernel<OFF_WG ><<<blocks((size_t)Ec*2048*IM),256>>>(wg,  Ec*2048*IM);
    round_copy_kernel<OFF_WU ><<<blocks((size_t)Ec*2048*IM),256>>>(wu,  Ec*2048*IM);
    round_copy_kernel<OFF_WD ><<<blocks((size_t)Ec*IM*2048),256>>>(wd,  Ec*IM*2048);
    round_copy_kernel<OFF_SWG><<<blocks((size_t)2048*ISH),  256>>>(swg, 2048*ISH);
    round_copy_kernel<OFF_SWU><<<blocks((size_t)2048*ISH),  256>>>(swu, 2048*ISH);
    round_copy_kernel<OFF_SWD><<<blocks((size_t)ISH*2048),  256>>>(swd, ISH*2048);

    clear_cnt_kernel<<<1, 32>>>();
    clear_moe_kernel<<<(Tc * Hc) / 256, 256>>>();

    // attention
    rmsnorm_kernel<0><<<Tc, 256>>>(x0, ln1);
    gemm_kernel<GM_Q><<<dim3(16, 32, 1), 128>>>(bq);
    gemm_kernel<GM_K><<<dim3(2, 32, 1), 128>>>(bk);
    gemm_kernel<GM_V><<<dim3(2, 32, 1), 128>>>(bv);
    rope_kernel<<<dim3(Tc, NQc + NKVc), 64>>>();
    kT_kernel<<<(Bc * NKVc * DHc * Sc) / 256, 256>>>();
    gemm_kernel<GM_SCORES><<<dim3(16, 16, 32), 128>>>(nullptr);
    softmax_kernel<<<Bc * NQc * Sc, 256>>>();
    gemm_kernel<GM_PV><<<dim3(1, 16, 32), 128>>>(nullptr);
    gemm_kernel<GM_O><<<dim3(16, 32, 1), 128>>>(x0);

    // MoE block
    rmsnorm_kernel<1><<<Tc, 256>>>(nullptr, ln2);
    router_kernel<<<Tc / 8, 256>>>(rw);
    gemm_kernel<GM_MG><<<dim3(11, 32, 8), 128>>>(nullptr);
    gemm_kernel<GM_MU><<<dim3(11, 32, 8), 128>>>(nullptr);
    moe_act_kernel<<<dim3(6, Tc, 8), 256>>>();
    gemm_kernel<GM_MD><<<dim3(16, 32, 8), 128>>>(nullptr);

    // shared expert
    gemm_kernel<GM_SG><<<dim3(44, 32, 1), 128>>>(nullptr);
    gemm_kernel<GM_SU><<<dim3(44, 32, 1), 128>>>(nullptr);
    shared_act_kernel<<<(size_t)(Tc) * ISH / 256, 256>>>();
    sgate_kernel<<<Tc / 8, 256>>>(sgw);
    gemm_kernel<GM_SD><<<dim3(16, 32, 1), 128>>>(nullptr);

    final_kernel<<<(Tc * Hc) / 256, 256>>>(out);
}

// round 12
// speedup vs baseline: 2.1186x; 1.1054x over previous
#include <cuda_runtime.h>
#include <math.h>
#include <stdint.h>

// ---------------- problem constants ----------------
constexpr int Bc   = 2;
constexpr int Sc   = 2048;
constexpr int Hc   = 2048;
constexpr int Tc   = Bc * Sc;      // 4096 tokens
constexpr int Ec   = 8;
constexpr int IM   = 1408;
constexpr int ISH  = 5632;
constexpr int NQc  = 16;
constexpr int NKVc = 2;
constexpr int DHc  = 128;
constexpr float EPSc = 1e-5f;
constexpr int NQKV = 2560;         // 2048 (Q) + 256 (K) + 256 (V)

// rounded-weight scratch offsets
constexpr size_t OFF_QKV = 0;                              // [2048][2560] interleaved
constexpr size_t OFF_WO  = OFF_QKV + (size_t)2048 * NQKV;
constexpr size_t OFF_WG  = OFF_WO  + (size_t)2048 * 2048;
constexpr size_t OFF_WU  = OFF_WG  + (size_t)Ec * 2048 * IM;
constexpr size_t OFF_WD  = OFF_WU  + (size_t)Ec * 2048 * IM;
constexpr size_t OFF_SWG = OFF_WD  + (size_t)Ec * IM * 2048;
constexpr size_t OFF_SWU = OFF_SWG + (size_t)2048 * ISH;
constexpr size_t OFF_SWD = OFF_SWU + (size_t)2048 * ISH;
constexpr size_t WR_TOT  = OFF_SWD + (size_t)ISH * 2048;

// ---------------- scratch (device globals; no allocations allowed) ----------------
__device__ float g_wr [WR_TOT];                      // tf32-rounded weights
__device__ float g_bqkv[NQKV];                       // concatenated q/k/v biases
__device__ float g_h  [(size_t)Tc * Hc];
__device__ float g_q  [(size_t)Tc * NQc * DHc];
__device__ float g_k  [(size_t)Tc * NKVc * DHc];
__device__ float g_v  [(size_t)Tc * NKVc * DHc];
__device__ float g_kT [(size_t)Bc * NKVc * DHc * Sc];
__device__ float g_sc [(size_t)Bc * NQc * Sc * Sc];  // scores -> probs in place
__device__ float g_ao [(size_t)Tc * Hc];
__device__ float g_x  [(size_t)Tc * Hc];
__device__ float g_t2 [(size_t)Tc * Hc];             // exact (router/sgate)
__device__ float g_t2r[(size_t)Tc * Hc];             // tf32-rounded (GEMM A)
__device__ float g_dw [Tc * Ec];
__device__ int   g_cnt[Ec];
__device__ int   g_list[Ec * Tc];
__device__ float g_mg [(size_t)Ec * Tc * IM];
__device__ float g_mu [(size_t)Ec * Tc * IM];
__device__ float g_moe[(size_t)Tc * Hc];
__device__ float g_sgv[(size_t)Tc * ISH];
__device__ float g_suv[(size_t)Tc * ISH];
__device__ float g_sh [(size_t)Tc * Hc];
__device__ float g_sgate[Tc];

__device__ __forceinline__ float tf32r(float x) {
    uint32_t u;
    asm("cvt.rna.tf32.f32 %0, %1;" : "=r"(u) : "f"(x));
    return __uint_as_float(u);
}

// ---------------- weight rounding ----------------
template<size_t OFF>
__global__ void round_copy_kernel(const float* __restrict__ src, int n) {
    const int i = blockIdx.x * 256 + threadIdx.x;
    if (i < n) g_wr[OFF + i] = tf32r(src[i]);
}

// strided: dst[k*ldDst + colOff + c] = tf32r(src[k*srcN + c])
__global__ void round_copy_str_kernel(const float* __restrict__ src, int n,
                                      int srcN, int ldDst, int colOff) {
    const int i = blockIdx.x * 256 + threadIdx.x;
    if (i < n) {
        const int k = i / srcN, c = i % srcN;
        g_wr[OFF_QKV + (size_t)k * ldDst + colOff + c] = tf32r(src[i]);
    }
}

__global__ void bias_concat_kernel(const float* __restrict__ bq,
                                   const float* __restrict__ bk,
                                   const float* __restrict__ bv) {
    const int i = blockIdx.x * 256 + threadIdx.x;
    if (i < 2048)       g_bqkv[i] = bq[i];
    else if (i < 2304)  g_bqkv[i] = bk[i - 2048];
    else if (i < NQKV)  g_bqkv[i] = bv[i - 2304];
}

// ---------------- small kernels ----------------
__global__ void clear_cnt_kernel() {
    if (threadIdx.x < Ec) g_cnt[threadIdx.x] = 0;
}
__global__ void clear_moe_kernel() {
    g_moe[(size_t)blockIdx.x * 256 + threadIdx.x] = 0.f;
}

template<int PHASE>
__global__ void rmsnorm_kernel(const float* __restrict__ xin,
                               const float* __restrict__ scale) {
    __shared__ float red[256];
    const int row = blockIdx.x;
    const float* x = (PHASE == 0) ? (xin + (size_t)row * Hc) : (g_x + (size_t)row * Hc);
    float s = 0.f;
    for (int i = threadIdx.x; i < Hc; i += 256) { float v = x[i]; s += v * v; }
    red[threadIdx.x] = s; __syncthreads();
    for (int o = 128; o > 0; o >>= 1) {
        if (threadIdx.x < o) red[threadIdx.x] += red[threadIdx.x + o];
        __syncthreads();
    }
    const float inv = rsqrtf(red[0] / (float)Hc + EPSc);
    for (int i = threadIdx.x; i < Hc; i += 256) {
        const float v = x[i] * inv * scale[i];
        if (PHASE == 0) {
            g_h[(size_t)row * Hc + i] = tf32r(v);
        } else {
            g_t2 [(size_t)row * Hc + i] = v;
            g_t2r[(size_t)row * Hc + i] = tf32r(v);
        }
    }
}

__global__ void rope_kernel() {
    const int tok  = blockIdx.x;
    const int head = blockIdx.y;
    const int j    = threadIdx.x;         // 0..63
    const int s    = tok & (Sc - 1);
    const float inv = powf(10000.f, -(float)(2 * j) / 128.f);
    const float ang = (float)s * inv;
    float si, c;
    sincosf(ang, &si, &c);
    float* p = (head < NQc) ? (g_q + (size_t)tok * (NQc * DHc) + head * DHc)
                            : (g_k + (size_t)tok * (NKVc * DHc) + (head - NQc) * DHc);
    const float x1 = p[j], x2 = p[j + 64];
    p[j]      = tf32r(x1 * c - x2 * si);
    p[j + 64] = tf32r(x2 * c + x1 * si);
}

__global__ void kT_kernel() {
    const int i  = blockIdx.x * 256 + threadIdx.x;
    const int s  = i & (Sc - 1);
    const int d  = (i >> 11) & 127;
    const int bk = i >> 18;
    g_kT[i] = g_k[((size_t)((bk >> 1) * Sc + s)) * (NKVc * DHc) + (bk & 1) * DHc + d];
}

// single-pass register-resident causal softmax.
// Writes only columns [0, round_up(lim,128)) — PV never reads beyond.
__global__ void softmax_kernel() {
    __shared__ float red[256];
    const size_t rid = blockIdx.x;
    const int r   = (int)(rid & (Sc - 1));
    float* sc = g_sc + rid * Sc;
    const int lim = r + 1;
    const int nf4 = (lim + 3) >> 2;                 // live float4's
    const int nf4w = ((lim + 127) & ~127) >> 2;     // float4's to write (tile-aligned)
    const int tid = threadIdx.x;

    float4 v4[2];
    float m = -1e30f;
#pragma unroll
    for (int s4 = 0; s4 < 2; s4++) {
        const int j = tid + s4 * 256;
        if (j < nf4) {
            float4 v = *(const float4*)(sc + j * 4);
            const int c0 = j * 4;
            if (c0 + 0 >= lim) v.x = -1e30f;
            if (c0 + 1 >= lim) v.y = -1e30f;
            if (c0 + 2 >= lim) v.z = -1e30f;
            if (c0 + 3 >= lim) v.w = -1e30f;
            v4[s4] = v;
            m = fmaxf(m, fmaxf(fmaxf(v.x, v.y), fmaxf(v.z, v.w)));
        } else {
            v4[s4] = make_float4(-1e30f, -1e30f, -1e30f, -1e30f);
        }
    }
    red[tid] = m; __syncthreads();
    for (int o = 128; o > 0; o >>= 1) {
        if (tid < o) red[tid] = fmaxf(red[tid], red[tid + o]);
        __syncthreads();
    }
    m = red[0]; __syncthreads();

    float s = 0.f;
#pragma unroll
    for (int s4 = 0; s4 < 2; s4++) {
        float4& v = v4[s4];
        v.x = (v.x > -1e29f) ? expf(v.x - m) : 0.f;
        v.y = (v.y > -1e29f) ? expf(v.y - m) : 0.f;
        v.z = (v.z > -1e29f) ? expf(v.z - m) : 0.f;
        v.w = (v.w > -1e29f) ? expf(v.w - m) : 0.f;
        s += v.x + v.y + v.z + v.w;
    }
    red[tid] = s; __syncthreads();
    for (int o = 128; o > 0; o >>= 1) {
        if (tid < o) red[tid] += red[tid + o];
        __syncthreads();
    }
    const float inv = 1.f / red[0];

#pragma unroll
    for (int s4 = 0; s4 < 2; s4++) {
        const int j = tid + s4 * 256;
        if (j < nf4w) {
            float4 o4;
            const float4 v = v4[s4];
            o4.x = tf32r(v.x * inv); o4.y = tf32r(v.y * inv);
            o4.z = tf32r(v.z * inv); o4.w = tf32r(v.w * inv);
            *(float4*)(sc + j * 4) = o4;
        }
    }
}

__global__ void router_kernel(const float* __restrict__ rw) {
    const int tok  = blockIdx.x * 8 + (threadIdx.x >> 5);
    const int lane = threadIdx.x & 31;
    const float* tr = g_t2 + (size_t)tok * Hc;
    float acc[8];
#pragma unroll
    for (int e = 0; e < 8; e++) acc[e] = 0.f;
    for (int h = lane; h < Hc; h += 32) {
        const float tv = tr[h];
        const float* rp = rw + h * 8;
#pragma unroll
        for (int e = 0; e < 8; e++) acc[e] += tv * rp[e];
    }
#pragma unroll
    for (int e = 0; e < 8; e++)
        for (int o = 16; o; o >>= 1) acc[e] += __shfl_xor_sync(0xffffffffu, acc[e], o);
    if (lane == 0) {
        float m = acc[0];
        for (int e = 1; e < 8; e++) m = fmaxf(m, acc[e]);
        float p[8], s = 0.f;
        for (int e = 0; e < 8; e++) { p[e] = expf(acc[e] - m); s += p[e]; }
        for (int e = 0; e < 8; e++) p[e] /= s;
        bool used[8] = {false,false,false,false,false,false,false,false};
        int isel[4]; float wsel[4]; float tsum = 0.f;
        for (int kk = 0; kk < 4; kk++) {
            int best = 0; float bv = -1.f;
            for (int e = 0; e < 8; e++)
                if (!used[e] && p[e] > bv) { bv = p[e]; best = e; }
            used[best] = true; isel[kk] = best; wsel[kk] = bv; tsum += bv;
        }
        float outw[8] = {0,0,0,0,0,0,0,0};
        for (int kk = 0; kk < 4; kk++) outw[isel[kk]] = wsel[kk] / tsum;
        for (int e = 0; e < 8; e++) g_dw[tok * 8 + e] = outw[e];
        for (int kk = 0; kk < 4; kk++) {
            const int pos = atomicAdd(&g_cnt[isel[kk]], 1);
            g_list[isel[kk] * Tc + pos] = tok;
        }
    }
}

__global__ void moe_act_kernel() {
    const int e = blockIdx.z, row = blockIdx.y;
    if (row >= g_cnt[e]) return;
    const int col = blockIdx.x * 256 + threadIdx.x;
    if (col >= IM) return;
    const size_t i = ((size_t)e * Tc + row) * IM + col;
    const float g = g_mg[i], u = g_mu[i];
    g_mg[i] = tf32r(g / (1.f + expf(-g)) * u);
}

__global__ void shared_act_kernel() {
    const size_t i = (size_t)blockIdx.x * 256 + threadIdx.x;
    const float g = g_sgv[i], u = g_suv[i];
    g_sgv[i] = tf32r(g / (1.f + expf(-g)) * u);
}

__global__ void sgate_kernel(const float* __restrict__ sgw) {
    const int tok  = blockIdx.x * 8 + (threadIdx.x >> 5);
    const int lane = threadIdx.x & 31;
    const float* tr = g_t2 + (size_t)tok * Hc;
    float s = 0.f;
    for (int h = lane; h < Hc; h += 32) s += tr[h] * sgw[h];
    for (int o = 16; o; o >>= 1) s += __shfl_xor_sync(0xffffffffu, s, o);
    if (lane == 0) g_sgate[tok] = 1.f / (1.f + expf(-s));
}

__global__ void final_kernel(float* __restrict__ out) {
    const size_t i = (size_t)blockIdx.x * 256 + threadIdx.x;
    const int row = (int)(i >> 11);
    out[i] = g_x[i] + g_moe[i] + g_sgate[row] * g_sh[i];
}

// ---------------- tf32 GEMM: cp.async + ldmatrix-A, 64x64 warp tile ----------------
enum GMode { GM_QKV, GM_SCORES, GM_PV, GM_O,
             GM_MG, GM_MU, GM_MD, GM_SG, GM_SU, GM_SD };

__device__ __forceinline__ void mma_tf32(float* c, const uint32_t* a, const uint32_t* b) {
    asm volatile(
        "mma.sync.aligned.m16n8k8.row.col.f32.tf32.tf32.f32 "
        "{%0,%1,%2,%3}, {%4,%5,%6,%7}, {%8,%9}, {%0,%1,%2,%3};"
        : "+f"(c[0]), "+f"(c[1]), "+f"(c[2]), "+f"(c[3])
        : "r"(a[0]), "r"(a[1]), "r"(a[2]), "r"(a[3]), "r"(b[0]), "r"(b[1]));
}

__device__ __forceinline__ void ldsm4(uint32_t& r0, uint32_t& r1, uint32_t& r2, uint32_t& r3,
                                      uint32_t addr) {
    asm volatile("ldmatrix.sync.aligned.m8n8.x4.shared.b16 {%0,%1,%2,%3}, [%4];"
                 : "=r"(r0), "=r"(r1), "=r"(r2), "=r"(r3) : "r"(addr));
}

__device__ __forceinline__ void cpa16(uint32_t dst, const void* src, int sz) {
    asm volatile("cp.async.cg.shared.global [%0], [%1], 16, %2;\n"
                 :: "r"(dst), "l"(src), "r"(sz));
}
__device__ __forceinline__ void cpa_commit() {
    asm volatile("cp.async.commit_group;\n");
}
__device__ __forceinline__ void cpa_wait0() {
    asm volatile("cp.async.wait_group 0;\n" ::: "memory");
}

constexpr int AST = 20;    // As stride (floats): conflict-free LDSM + cp.async
constexpr int BST = 136;   // Bs stride (floats)

// BM=128, BN=128, BK=16; 128 threads = 4 warps (2x2), warp tile 64x64. 2 CTAs/SM.
template<int MODE>
__global__ __launch_bounds__(128, 2) void gemm_kernel(const float* __restrict__ extra) {
    constexpr int Kv =
        (MODE==GM_SCORES) ? 128 :
        (MODE==GM_PV) ? Sc :
        (MODE==GM_MD) ? IM :
        (MODE==GM_SD) ? ISH : 2048;

    const int tid = threadIdx.x;
    const int z   = blockIdx.z;
    const int m0  = blockIdx.y * 128, n0 = blockIdx.x * 128;

    int Mz;
    if (MODE==GM_SCORES || MODE==GM_PV) Mz = Sc;
    else if (MODE==GM_MG || MODE==GM_MU || MODE==GM_MD) Mz = g_cnt[z];
    else Mz = Tc;
    if (m0 >= Mz) return;
    if (MODE==GM_SCORES && n0 > m0 + 127) return;   // fully masked tile

    int bb = 0, hh = 0;
    if (MODE==GM_SCORES || MODE==GM_PV) { bb = z >> 4; hh = z & 15; }

    const float* A; const float* Bp; int lda, ldb;
    if (MODE==GM_QKV) {
        A = g_h; lda = Hc; Bp = g_wr + OFF_QKV; ldb = NQKV;
    } else if (MODE==GM_SCORES) {
        A = g_q + (size_t)bb * Sc * 2048 + hh * 128; lda = 2048;
        Bp = g_kT + (size_t)(bb * 2 + (hh >> 3)) * 128 * Sc; ldb = Sc;
    } else if (MODE==GM_PV) {
        A = g_sc + (size_t)z * Sc * Sc; lda = Sc;
        Bp = g_v + (size_t)bb * Sc * 256 + (hh >> 3) * 128; ldb = 256;
    } else if (MODE==GM_O) {
        A = g_ao; lda = 2048; Bp = g_wr + OFF_WO; ldb = 2048;
    } else if (MODE==GM_MG) {
        A = g_t2r; lda = 2048; Bp = g_wr + OFF_WG + (size_t)z * 2048 * IM; ldb = IM;
    } else if (MODE==GM_MU) {
        A = g_t2r; lda = 2048; Bp = g_wr + OFF_WU + (size_t)z * 2048 * IM; ldb = IM;
    } else if (MODE==GM_MD) {
        A = g_mg + (size_t)z * Tc * IM; lda = IM;
        Bp = g_wr + OFF_WD + (size_t)z * IM * 2048; ldb = 2048;
    } else if (MODE==GM_SG) {
        A = g_t2r; lda = 2048; Bp = g_wr + OFF_SWG; ldb = ISH;
    } else if (MODE==GM_SU) {
        A = g_t2r; lda = 2048; Bp = g_wr + OFF_SWU; ldb = ISH;
    } else { // GM_SD
        A = g_sgv; lda = ISH; Bp = g_wr + OFF_SWD; ldb = 2048;
    }

    __shared__ float As[2][128][AST];   // [stage][m][k]
    __shared__ float Bs[2][16][BST];    // [stage][k][n]

    float acc[4][8][4];
#pragma unroll
    for (int i = 0; i < 4; i++)
#pragma unroll
        for (int j = 0; j < 8; j++)
#pragma unroll
            for (int r = 0; r < 4; r++) acc[i][j][r] = 0.f;

    const int lane = tid & 31, wid = tid >> 5;
    const int wm = (wid >> 1) * 64;
    const int wn = (wid & 1) * 64;

    // A loader: one row per thread
    const int lm = tid;
    const int agl = m0 + lm;
    const bool aval = agl < Mz;
    const float* arp;
    if (MODE==GM_MG || MODE==GM_MU)
        arp = A + (size_t)(aval ? g_list[z * Tc + agl] : 0) * lda;
    else
        arp = A + (size_t)(aval ? agl : 0) * lda;
    const int asz = aval ? 16 : 0;
    const int arot = (lm >> 3) & 3;   // chunk rotation -> conflict-free cp.async stores

    // B loader: per warp one k-row per chunk, 128 cols split across lanes
    const int bw = tid >> 5;          // k sub-row
    const int bn = (tid & 31) * 4;
    const float* bbase = Bp + n0;

    const int Kend = (MODE==GM_PV) ? (m0 + 128) : Kv;
    const int nt = Kend / 16;

    uint32_t sA[2], sB[2];
    sA[0] = (uint32_t)__cvta_generic_to_shared(&As[0][0][0]);
    sA[1] = (uint32_t)__cvta_generic_to_shared(&As[1][0][0]);
    sB[0] = (uint32_t)__cvta_generic_to_shared(&Bs[0][0][0]);
    sB[1] = (uint32_t)__cvta_generic_to_shared(&Bs[1][0][0]);

    auto load_stage = [&](int s, int k0) {
#pragma unroll
        for (int c = 0; c < 4; c++) {
            const int cc = (c + arot) & 3;
            cpa16(sA[s] + (uint32_t)(lm * AST + cc * 4) * 4, arp + k0 + cc * 4, asz);
        }
#pragma unroll
        for (int c = 0; c < 4; c++) {
            const int k = c * 4 + bw;
            cpa16(sB[s] + (uint32_t)(k * BST + bn) * 4,
                  bbase + (size_t)(k0 + k) * ldb + bn, 16);
        }
    };

    load_stage(0, 0);
    cpa_commit();

    const int cb = wn + (lane >> 2);
    const int kq = lane & 3;
    const int lrow = lane & 15;
    const int lcol = (lane >> 4) << 2;

    for (int t = 0; t < nt; t++) {
        cpa_wait0();
        __syncthreads();
        if (t + 1 < nt) load_stage((t + 1) & 1, (t + 1) * 16);
        cpa_commit();

        const int buf = t & 1;
#pragma unroll
        for (int ks = 0; ks < 2; ks++) {
            const int klo = ks * 8;
            const int kk = klo + kq;
            uint32_t af[4][4], bf[8][2];
#pragma unroll
            for (int i = 0; i < 4; i++) {
                const uint32_t addr = sA[buf] +
                    (uint32_t)((wm + i * 16 + lrow) * AST + klo + lcol) * 4;
                ldsm4(af[i][0], af[i][1], af[i][2], af[i][3], addr);
            }
#pragma unroll
            for (int j = 0; j < 8; j++) {
                bf[j][0] = __float_as_uint(Bs[buf][kk][cb + j * 8]);
                bf[j][1] = __float_as_uint(Bs[buf][kk + 4][cb + j * 8]);
            }
#pragma unroll
            for (int i = 0; i < 4; i++)
#pragma unroll
                for (int j = 0; j < 8; j++)
                    mma_tf32(acc[i][j], af[i], bf[j]);
        }
        __syncthreads();
    }

    // ---------------- epilogues ----------------
    const float scl = 0.08838834764831845f;  // 1/sqrt(128)
#pragma unroll
    for (int i = 0; i < 4; i++) {
#pragma unroll
        for (int rr = 0; rr < 2; rr++) {
            const int r = m0 + wm + i * 16 + (lane >> 2) + rr * 8;
            if (r >= Mz) continue;
            if (MODE==GM_QKV) {
#pragma unroll
                for (int j = 0; j < 8; j++) {
                    const int c = n0 + wn + j * 8 + (lane & 3) * 2;
                    float v0 = acc[i][j][rr * 2 + 0] + g_bqkv[c];
                    float v1 = acc[i][j][rr * 2 + 1] + g_bqkv[c + 1];
                    if (c < 2048) {
                        g_q[(size_t)r * 2048 + c]     = v0;
                        g_q[(size_t)r * 2048 + c + 1] = v1;
                    } else if (c < 2304) {
                        g_k[(size_t)r * 256 + c - 2048]     = v0;
                        g_k[(size_t)r * 256 + c - 2048 + 1] = v1;
                    } else {
                        g_v[(size_t)r * 256 + c - 2304]     = tf32r(v0);
                        g_v[(size_t)r * 256 + c - 2304 + 1] = tf32r(v1);
                    }
                }
            } else if (MODE==GM_SCORES) {
                const size_t base = (size_t)z * Sc * Sc + (size_t)r * Sc;
#pragma unroll
                for (int j = 0; j < 8; j++) {
                    const int c = n0 + wn + j * 8 + (lane & 3) * 2;
                    float v0 = acc[i][j][rr * 2 + 0] * scl;
                    float v1 = acc[i][j][rr * 2 + 1] * scl;
                    if (c > r)     v0 = -1e9f;
                    if (c + 1 > r) v1 = -1e9f;
                    g_sc[base + c]     = v0;
                    g_sc[base + c + 1] = v1;
                }
            } else if (MODE==GM_MD) {
                const int tok = g_list[z * Tc + r];
                const float w = g_dw[tok * Ec + z];
                float* dst = g_moe + (size_t)tok * 2048;
#pragma unroll
                for (int j = 0; j < 8; j++) {
                    const int c = n0 + wn + j * 8 + (lane & 3) * 2;
                    atomicAdd(dst + c,     acc[i][j][rr * 2 + 0] * w);
                    atomicAdd(dst + c + 1, acc[i][j][rr * 2 + 1] * w);
                }
            } else {
                float* Cp; int ldc; const float* res = nullptr;
                constexpr bool RND = (MODE==GM_PV);
                if (MODE==GM_PV)      { Cp = g_ao + (size_t)bb * Sc * 2048 + hh * 128; ldc = 2048; }
                else if (MODE==GM_O)  { Cp = g_x;  ldc = 2048; res = extra; }
                else if (MODE==GM_MG) { Cp = g_mg + (size_t)z * Tc * IM; ldc = IM; }
                else if (MODE==GM_MU) { Cp = g_mu + (size_t)z * Tc * IM; ldc = IM; }
                else if (MODE==GM_SG) { Cp = g_sgv; ldc = ISH; }
                else if (MODE==GM_SU) { Cp = g_suv; ldc = ISH; }
                else                  { Cp = g_sh;  ldc = 2048; }
                const size_t rowoff = (size_t)r * ldc;
#pragma unroll
                for (int j = 0; j < 8; j++) {
                    const int c = n0 + wn + j * 8 + (lane & 3) * 2;
                    float v0 = acc[i][j][rr * 2 + 0];
                    float v1 = acc[i][j][rr * 2 + 1];
                    if (res)  { v0 += res[rowoff + c]; v1 += res[rowoff + c + 1]; }
                    if (RND)  { v0 = tf32r(v0); v1 = tf32r(v1); }
                    Cp[rowoff + c]     = v0;
                    Cp[rowoff + c + 1] = v1;
                }
            }
        }
    }
}

// ---------------- launch ----------------
extern "C" void kernel_launch(void* const* d_in, const int* in_sizes, int n_in,
                              void* d_out, int out_size) {
    (void)in_sizes; (void)n_in; (void)out_size;
    const float* x0  = (const float*)d_in[0];
    const float* ln1 = (const float*)d_in[1];
    const float* wq  = (const float*)d_in[2];
    const float* bq  = (const float*)d_in[3];
    const float* wk  = (const float*)d_in[4];
    const float* bk  = (const float*)d_in[5];
    const float* wv  = (const float*)d_in[6];
    const float* bv  = (const float*)d_in[7];
    const float* wo  = (const float*)d_in[8];
    const float* ln2 = (const float*)d_in[9];
    const float* rw  = (const float*)d_in[10];
    const float* wg  = (const float*)d_in[11];
    const float* wu  = (const float*)d_in[12];
    const float* wd  = (const float*)d_in[13];
    const float* swg = (const float*)d_in[14];
    const float* swu = (const float*)d_in[15];
    const float* swd = (const float*)d_in[16];
    const float* sgw = (const float*)d_in[17];
    float* out = (float*)d_out;

    auto blocks = [](size_t n) { return (unsigned)((n + 255) / 256); };

    // QKV interleaved into [2048][2560]
    round_copy_str_kernel<<<blocks((size_t)2048*2048), 256>>>(wq, 2048*2048, 2048, NQKV, 0);
    round_copy_str_kernel<<<blocks((size_t)2048*256),  256>>>(wk, 2048*256,  256,  NQKV, 2048);
    round_copy_str_kernel<<<blocks((size_t)2048*256),  256>>>(wv, 2048*256,  256,  NQKV, 2304);
    bias_concat_kernel<<<10, 256>>>(bq, bk, bv);
    round_copy_kernel<OFF_WO ><<<blocks((size_t)2048*2048), 256>>>(wo,  2048*2048);
    round_copy_kernel<OFF_WG ><<<blocks((size_t)Ec*2048*IM),256>>>(wg,  Ec*2048*IM);
    round_copy_kernel<OFF_WU ><<<blocks((size_t)Ec*2048*IM),256>>>(wu,  Ec*2048*IM);
    round_copy_kernel<OFF_WD ><<<blocks((size_t)Ec*IM*2048),256>>>(wd,  Ec*IM*2048);
    round_copy_kernel<OFF_SWG><<<blocks((size_t)2048*ISH),  256>>>(swg, 2048*ISH);
    round_copy_kernel<OFF_SWU><<<blocks((size_t)2048*ISH),  256>>>(swu, 2048*ISH);
    round_copy_kernel<OFF_SWD><<<blocks((size_t)ISH*2048),  256>>>(swd, ISH*2048);

    clear_cnt_kernel<<<1, 32>>>();
    clear_moe_kernel<<<(Tc * Hc) / 256, 256>>>();

    // attention
    rmsnorm_kernel<0><<<Tc, 256>>>(x0, ln1);
    gemm_kernel<GM_QKV><<<dim3(20, 32, 1), 128>>>(nullptr);
    rope_kernel<<<dim3(Tc, NQc + NKVc), 64>>>();
    kT_kernel<<<(Bc * NKVc * DHc * Sc) / 256, 256>>>();
    gemm_kernel<GM_SCORES><<<dim3(16, 16, 32), 128>>>(nullptr);
    softmax_kernel<<<Bc * NQc * Sc, 256>>>();
    gemm_kernel<GM_PV><<<dim3(1, 16, 32), 128>>>(nullptr);
    gemm_kernel<GM_O><<<dim3(16, 32, 1), 128>>>(x0);

    // MoE block
    rmsnorm_kernel<1><<<Tc, 256>>>(nullptr, ln2);
    router_kernel<<<Tc / 8, 256>>>(rw);
    gemm_kernel<GM_MG><<<dim3(11, 32, 8), 128>>>(nullptr);
    gemm_kernel<GM_MU><<<dim3(11, 32, 8), 128>>>(nullptr);
    moe_act_kernel<<<dim3(6, Tc, 8), 256>>>();
    gemm_kernel<GM_MD><<<dim3(16, 32, 8), 128>>>(nullptr);

    // shared expert
    gemm_kernel<GM_SG><<<dim3(44, 32, 1), 128>>>(nullptr);
    gemm_kernel<GM_SU><<<dim3(44, 32, 1), 128>>>(nullptr);
    shared_act_kernel<<<(size_t)(Tc) * ISH / 256, 256>>>();
    sgate_kernel<<<Tc / 8, 256>>>(sgw);
    gemm_kernel<GM_SD><<<dim3(16, 32, 1), 128>>>(nullptr);

    final_kernel<<<(Tc * Hc) / 256, 256>>>(out);
}

// round 13
// speedup vs baseline: 2.1841x; 1.0309x over previous
#include <cuda_runtime.h>
#include <math.h>
#include <stdint.h>

// ---------------- problem constants ----------------
constexpr int Bc   = 2;
constexpr int Sc   = 2048;
constexpr int Hc   = 2048;
constexpr int Tc   = Bc * Sc;      // 4096 tokens
constexpr int Ec   = 8;
constexpr int IM   = 1408;
constexpr int ISH  = 5632;
constexpr int NQc  = 16;
constexpr int NKVc = 2;
constexpr int DHc  = 128;
constexpr float EPSc = 1e-5f;
constexpr int NQKV = 2560;         // 2048 (Q) + 256 (K) + 256 (V)

// rounded-weight scratch offsets
constexpr size_t OFF_QKV = 0;                              // [2048][2560] interleaved
constexpr size_t OFF_WO  = OFF_QKV + (size_t)2048 * NQKV;
constexpr size_t OFF_WG  = OFF_WO  + (size_t)2048 * 2048;
constexpr size_t OFF_WU  = OFF_WG  + (size_t)Ec * 2048 * IM;
constexpr size_t OFF_WD  = OFF_WU  + (size_t)Ec * 2048 * IM;
constexpr size_t OFF_SWG = OFF_WD  + (size_t)Ec * IM * 2048;
constexpr size_t OFF_SWU = OFF_SWG + (size_t)2048 * ISH;
constexpr size_t OFF_SWD = OFF_SWU + (size_t)2048 * ISH;
constexpr size_t WR_TOT  = OFF_SWD + (size_t)ISH * 2048;

// ---------------- scratch (device globals; no allocations allowed) ----------------
__device__ float g_wr [WR_TOT];                      // tf32-rounded weights
__device__ float g_bqkv[NQKV];                       // concatenated q/k/v biases
__device__ float g_h  [(size_t)Tc * Hc];
__device__ float g_q  [(size_t)Tc * NQc * DHc];
__device__ float g_k  [(size_t)Tc * NKVc * DHc];
__device__ float g_v  [(size_t)Tc * NKVc * DHc];
__device__ float g_kT [(size_t)Bc * NKVc * DHc * Sc];
__device__ float g_sc [(size_t)Bc * NQc * Sc * Sc];  // scores -> probs in place
__device__ float g_ao [(size_t)Tc * Hc];
__device__ float g_x  [(size_t)Tc * Hc];
__device__ float g_t2 [(size_t)Tc * Hc];             // exact (router/sgate)
__device__ float g_t2r[(size_t)Tc * Hc];             // tf32-rounded (GEMM A)
__device__ float g_dw [Tc * Ec];
__device__ int   g_cnt[Ec];
__device__ int   g_list[Ec * Tc];
__device__ float g_mg [(size_t)Ec * Tc * IM];
__device__ float g_mu [(size_t)Ec * Tc * IM];
__device__ float g_moe[(size_t)Tc * Hc];
__device__ float g_sgv[(size_t)Tc * ISH];
__device__ float g_suv[(size_t)Tc * ISH];
__device__ float g_sh [(size_t)Tc * Hc];
__device__ float g_sgate[Tc];

__device__ __forceinline__ float tf32r(float x) {
    uint32_t u;
    asm("cvt.rna.tf32.f32 %0, %1;" : "=r"(u) : "f"(x));
    return __uint_as_float(u);
}

// ---------------- weight rounding ----------------
template<size_t OFF>
__global__ void round_copy_kernel(const float* __restrict__ src, int n) {
    const int i = blockIdx.x * 256 + threadIdx.x;
    if (i < n) g_wr[OFF + i] = tf32r(src[i]);
}

__global__ void round_copy_str_kernel(const float* __restrict__ src, int n,
                                      int srcN, int ldDst, int colOff) {
    const int i = blockIdx.x * 256 + threadIdx.x;
    if (i < n) {
        const int k = i / srcN, c = i % srcN;
        g_wr[OFF_QKV + (size_t)k * ldDst + colOff + c] = tf32r(src[i]);
    }
}

__global__ void bias_concat_kernel(const float* __restrict__ bq,
                                   const float* __restrict__ bk,
                                   const float* __restrict__ bv) {
    const int i = blockIdx.x * 256 + threadIdx.x;
    if (i < 2048)       g_bqkv[i] = bq[i];
    else if (i < 2304)  g_bqkv[i] = bk[i - 2048];
    else if (i < NQKV)  g_bqkv[i] = bv[i - 2304];
}

// ---------------- small kernels ----------------
__global__ void clear_cnt_kernel() {
    if (threadIdx.x < Ec) g_cnt[threadIdx.x] = 0;
}
__global__ void clear_moe_kernel() {
    g_moe[(size_t)blockIdx.x * 256 + threadIdx.x] = 0.f;
}

template<int PHASE>
__global__ void rmsnorm_kernel(const float* __restrict__ xin,
                               const float* __restrict__ scale) {
    __shared__ float red[256];
    const int row = blockIdx.x;
    const float* x = (PHASE == 0) ? (xin + (size_t)row * Hc) : (g_x + (size_t)row * Hc);
    float s = 0.f;
    for (int i = threadIdx.x; i < Hc; i += 256) { float v = x[i]; s += v * v; }
    red[threadIdx.x] = s; __syncthreads();
    for (int o = 128; o > 0; o >>= 1) {
        if (threadIdx.x < o) red[threadIdx.x] += red[threadIdx.x + o];
        __syncthreads();
    }
    const float inv = rsqrtf(red[0] / (float)Hc + EPSc);
    for (int i = threadIdx.x; i < Hc; i += 256) {
        const float v = x[i] * inv * scale[i];
        if (PHASE == 0) {
            g_h[(size_t)row * Hc + i] = tf32r(v);
        } else {
            g_t2 [(size_t)row * Hc + i] = v;
            g_t2r[(size_t)row * Hc + i] = tf32r(v);
        }
    }
}

__global__ void rope_kernel() {
    const int tok  = blockIdx.x;
    const int head = blockIdx.y;
    const int j    = threadIdx.x;         // 0..63
    const int s    = tok & (Sc - 1);
    const float inv = powf(10000.f, -(float)(2 * j) / 128.f);
    const float ang = (float)s * inv;
    float si, c;
    sincosf(ang, &si, &c);
    float* p = (head < NQc) ? (g_q + (size_t)tok * (NQc * DHc) + head * DHc)
                            : (g_k + (size_t)tok * (NKVc * DHc) + (head - NQc) * DHc);
    const float x1 = p[j], x2 = p[j + 64];
    p[j]      = tf32r(x1 * c - x2 * si);
    p[j + 64] = tf32r(x2 * c + x1 * si);
}

__global__ void kT_kernel() {
    const int i  = blockIdx.x * 256 + threadIdx.x;
    const int s  = i & (Sc - 1);
    const int d  = (i >> 11) & 127;
    const int bk = i >> 18;
    g_kT[i] = g_k[((size_t)((bk >> 1) * Sc + s)) * (NKVc * DHc) + (bk & 1) * DHc + d];
}

// single-pass register-resident causal softmax; writes only live 128-tiles
__global__ void softmax_kernel() {
    __shared__ float red[256];
    const size_t rid = blockIdx.x;
    const int r   = (int)(rid & (Sc - 1));
    float* sc = g_sc + rid * Sc;
    const int lim = r + 1;
    const int nf4 = (lim + 3) >> 2;
    const int nf4w = ((lim + 127) & ~127) >> 2;
    const int tid = threadIdx.x;

    float4 v4[2];
    float m = -1e30f;
#pragma unroll
    for (int s4 = 0; s4 < 2; s4++) {
        const int j = tid + s4 * 256;
        if (j < nf4) {
            float4 v = *(const float4*)(sc + j * 4);
            const int c0 = j * 4;
            if (c0 + 0 >= lim) v.x = -1e30f;
            if (c0 + 1 >= lim) v.y = -1e30f;
            if (c0 + 2 >= lim) v.z = -1e30f;
            if (c0 + 3 >= lim) v.w = -1e30f;
            v4[s4] = v;
            m = fmaxf(m, fmaxf(fmaxf(v.x, v.y), fmaxf(v.z, v.w)));
        } else {
            v4[s4] = make_float4(-1e30f, -1e30f, -1e30f, -1e30f);
        }
    }
    red[tid] = m; __syncthreads();
    for (int o = 128; o > 0; o >>= 1) {
        if (tid < o) red[tid] = fmaxf(red[tid], red[tid + o]);
        __syncthreads();
    }
    m = red[0]; __syncthreads();

    float s = 0.f;
#pragma unroll
    for (int s4 = 0; s4 < 2; s4++) {
        float4& v = v4[s4];
        v.x = (v.x > -1e29f) ? expf(v.x - m) : 0.f;
        v.y = (v.y > -1e29f) ? expf(v.y - m) : 0.f;
        v.z = (v.z > -1e29f) ? expf(v.z - m) : 0.f;
        v.w = (v.w > -1e29f) ? expf(v.w - m) : 0.f;
        s += v.x + v.y + v.z + v.w;
    }
    red[tid] = s; __syncthreads();
    for (int o = 128; o > 0; o >>= 1) {
        if (tid < o) red[tid] += red[tid + o];
        __syncthreads();
    }
    const float inv = 1.f / red[0];

#pragma unroll
    for (int s4 = 0; s4 < 2; s4++) {
        const int j = tid + s4 * 256;
        if (j < nf4w) {
            float4 o4;
            const float4 v = v4[s4];
            o4.x = tf32r(v.x * inv); o4.y = tf32r(v.y * inv);
            o4.z = tf32r(v.z * inv); o4.w = tf32r(v.w * inv);
            *(float4*)(sc + j * 4) = o4;
        }
    }
}

__global__ void router_kernel(const float* __restrict__ rw) {
    const int tok  = blockIdx.x * 8 + (threadIdx.x >> 5);
    const int lane = threadIdx.x & 31;
    const float* tr = g_t2 + (size_t)tok * Hc;
    float acc[8];
#pragma unroll
    for (int e = 0; e < 8; e++) acc[e] = 0.f;
    for (int h = lane; h < Hc; h += 32) {
        const float tv = tr[h];
        const float* rp = rw + h * 8;
#pragma unroll
        for (int e = 0; e < 8; e++) acc[e] += tv * rp[e];
    }
#pragma unroll
    for (int e = 0; e < 8; e++)
        for (int o = 16; o; o >>= 1) acc[e] += __shfl_xor_sync(0xffffffffu, acc[e], o);
    if (lane == 0) {
        float m = acc[0];
        for (int e = 1; e < 8; e++) m = fmaxf(m, acc[e]);
        float p[8], s = 0.f;
        for (int e = 0; e < 8; e++) { p[e] = expf(acc[e] - m); s += p[e]; }
        for (int e = 0; e < 8; e++) p[e] /= s;
        bool used[8] = {false,false,false,false,false,false,false,false};
        int isel[4]; float wsel[4]; float tsum = 0.f;
        for (int kk = 0; kk < 4; kk++) {
            int best = 0; float bv = -1.f;
            for (int e = 0; e < 8; e++)
                if (!used[e] && p[e] > bv) { bv = p[e]; best = e; }
            used[best] = true; isel[kk] = best; wsel[kk] = bv; tsum += bv;
        }
        float outw[8] = {0,0,0,0,0,0,0,0};
        for (int kk = 0; kk < 4; kk++) outw[isel[kk]] = wsel[kk] / tsum;
        for (int e = 0; e < 8; e++) g_dw[tok * 8 + e] = outw[e];
        for (int kk = 0; kk < 4; kk++) {
            const int pos = atomicAdd(&g_cnt[isel[kk]], 1);
            g_list[isel[kk] * Tc + pos] = tok;
        }
    }
}

__global__ void moe_act_kernel() {
    const int e = blockIdx.z, row = blockIdx.y;
    if (row >= g_cnt[e]) return;
    const int col = blockIdx.x * 256 + threadIdx.x;
    if (col >= IM) return;
    const size_t i = ((size_t)e * Tc + row) * IM + col;
    const float g = g_mg[i], u = g_mu[i];
    g_mg[i] = tf32r(g / (1.f + expf(-g)) * u);
}

__global__ void shared_act_kernel() {
    const size_t i = (size_t)blockIdx.x * 256 + threadIdx.x;
    const float g = g_sgv[i], u = g_suv[i];
    g_sgv[i] = tf32r(g / (1.f + expf(-g)) * u);
}

__global__ void sgate_kernel(const float* __restrict__ sgw) {
    const int tok  = blockIdx.x * 8 + (threadIdx.x >> 5);
    const int lane = threadIdx.x & 31;
    const float* tr = g_t2 + (size_t)tok * Hc;
    float s = 0.f;
    for (int h = lane; h < Hc; h += 32) s += tr[h] * sgw[h];
    for (int o = 16; o; o >>= 1) s += __shfl_xor_sync(0xffffffffu, s, o);
    if (lane == 0) g_sgate[tok] = 1.f / (1.f + expf(-s));
}

__global__ void final_kernel(float* __restrict__ out) {
    const size_t i = (size_t)blockIdx.x * 256 + threadIdx.x;
    const int row = (int)(i >> 11);
    out[i] = g_x[i] + g_moe[i] + g_sgate[row] * g_sh[i];
}

// ---------------- tf32 GEMM: 3-stage cp.async + ldmatrix-A, single-sync loop ----------------
enum GMode { GM_QKV, GM_SCORES, GM_PV, GM_O,
             GM_MG, GM_MU, GM_MD, GM_SG, GM_SU, GM_SD };

__device__ __forceinline__ void mma_tf32(float* c, const uint32_t* a, const uint32_t* b) {
    asm volatile(
        "mma.sync.aligned.m16n8k8.row.col.f32.tf32.tf32.f32 "
        "{%0,%1,%2,%3}, {%4,%5,%6,%7}, {%8,%9}, {%0,%1,%2,%3};"
        : "+f"(c[0]), "+f"(c[1]), "+f"(c[2]), "+f"(c[3])
        : "r"(a[0]), "r"(a[1]), "r"(a[2]), "r"(a[3]), "r"(b[0]), "r"(b[1]));
}

__device__ __forceinline__ void ldsm4(uint32_t& r0, uint32_t& r1, uint32_t& r2, uint32_t& r3,
                                      uint32_t addr) {
    asm volatile("ldmatrix.sync.aligned.m8n8.x4.shared.b16 {%0,%1,%2,%3}, [%4];"
                 : "=r"(r0), "=r"(r1), "=r"(r2), "=r"(r3) : "r"(addr));
}

__device__ __forceinline__ void cpa16(uint32_t dst, const void* src, int sz) {
    asm volatile("cp.async.cg.shared.global [%0], [%1], 16, %2;\n"
                 :: "r"(dst), "l"(src), "r"(sz));
}
__device__ __forceinline__ void cpa_commit() {
    asm volatile("cp.async.commit_group;\n");
}
__device__ __forceinline__ void cpa_wait1() {
    asm volatile("cp.async.wait_group 1;\n" ::: "memory");
}

constexpr int AST = 20;    // As stride (floats)
constexpr int BST = 136;   // Bs stride (floats)
constexpr int A_STG = 128 * AST;          // floats per A stage
constexpr int B_STG = 16 * BST;           // floats per B stage
constexpr int GSMEM = 3 * (A_STG + B_STG) * 4;   // 56832 bytes

// BM=128, BN=128, BK=16; 128 threads = 4 warps (2x2), warp tile 64x64. 2 CTAs/SM.
template<int MODE>
__global__ __launch_bounds__(128, 2) void gemm_kernel(const float* __restrict__ extra) {
    extern __shared__ float smem[];
    constexpr int Kv =
        (MODE==GM_SCORES) ? 128 :
        (MODE==GM_PV) ? Sc :
        (MODE==GM_MD) ? IM :
        (MODE==GM_SD) ? ISH : 2048;

    const int tid = threadIdx.x;
    const int z   = blockIdx.z;
    const int m0  = blockIdx.y * 128, n0 = blockIdx.x * 128;

    int Mz;
    if (MODE==GM_SCORES || MODE==GM_PV) Mz = Sc;
    else if (MODE==GM_MG || MODE==GM_MU || MODE==GM_MD) Mz = g_cnt[z];
    else Mz = Tc;
    if (m0 >= Mz) return;
    if (MODE==GM_SCORES && n0 > m0 + 127) return;

    int bb = 0, hh = 0;
    if (MODE==GM_SCORES || MODE==GM_PV) { bb = z >> 4; hh = z & 15; }

    const float* A; const float* Bp; int lda, ldb;
    if (MODE==GM_QKV) {
        A = g_h; lda = Hc; Bp = g_wr + OFF_QKV; ldb = NQKV;
    } else if (MODE==GM_SCORES) {
        A = g_q + (size_t)bb * Sc * 2048 + hh * 128; lda = 2048;
        Bp = g_kT + (size_t)(bb * 2 + (hh >> 3)) * 128 * Sc; ldb = Sc;
    } else if (MODE==GM_PV) {
        A = g_sc + (size_t)z * Sc * Sc; lda = Sc;
        Bp = g_v + (size_t)bb * Sc * 256 + (hh >> 3) * 128; ldb = 256;
    } else if (MODE==GM_O) {
        A = g_ao; lda = 2048; Bp = g_wr + OFF_WO; ldb = 2048;
    } else if (MODE==GM_MG) {
        A = g_t2r; lda = 2048; Bp = g_wr + OFF_WG + (size_t)z * 2048 * IM; ldb = IM;
    } else if (MODE==GM_MU) {
        A = g_t2r; lda = 2048; Bp = g_wr + OFF_WU + (size_t)z * 2048 * IM; ldb = IM;
    } else if (MODE==GM_MD) {
        A = g_mg + (size_t)z * Tc * IM; lda = IM;
        Bp = g_wr + OFF_WD + (size_t)z * IM * 2048; ldb = 2048;
    } else if (MODE==GM_SG) {
        A = g_t2r; lda = 2048; Bp = g_wr + OFF_SWG; ldb = ISH;
    } else if (MODE==GM_SU) {
        A = g_t2r; lda = 2048; Bp = g_wr + OFF_SWU; ldb = ISH;
    } else { // GM_SD
        A = g_sgv; lda = ISH; Bp = g_wr + OFF_SWD; ldb = 2048;
    }

    float* Asf = smem;                     // [3][128][AST]
    float* Bsf = smem + 3 * A_STG;         // [3][16][BST]

    float acc[4][8][4];
#pragma unroll
    for (int i = 0; i < 4; i++)
#pragma unroll
        for (int j = 0; j < 8; j++)
#pragma unroll
            for (int r = 0; r < 4; r++) acc[i][j][r] = 0.f;

    const int lane = tid & 31, wid = tid >> 5;
    const int wm = (wid >> 1) * 64;
    const int wn = (wid & 1) * 64;

    const int lm = tid;
    const int agl = m0 + lm;
    const bool aval = agl < Mz;
    const float* arp;
    if (MODE==GM_MG || MODE==GM_MU)
        arp = A + (size_t)(aval ? g_list[z * Tc + agl] : 0) * lda;
    else
        arp = A + (size_t)(aval ? agl : 0) * lda;
    const int asz = aval ? 16 : 0;
    const int arot = (lm >> 3) & 3;

    const int bw = tid >> 5;
    const int bn = (tid & 31) * 4;
    const float* bbase = Bp + n0;

    const int Kend = (MODE==GM_PV) ? (m0 + 128) : Kv;
    const int nt = Kend / 16;

    const uint32_t sA = (uint32_t)__cvta_generic_to_shared(Asf);
    const uint32_t sB = (uint32_t)__cvta_generic_to_shared(Bsf);

    auto load_stage = [&](int s, int k0) {
#pragma unroll
        for (int c = 0; c < 4; c++) {
            const int cc = (c + arot) & 3;
            cpa16(sA + (uint32_t)((s * 128 + lm) * AST + cc * 4) * 4, arp + k0 + cc * 4, asz);
        }
#pragma unroll
        for (int c = 0; c < 4; c++) {
            const int k = c * 4 + bw;
            cpa16(sB + (uint32_t)((s * 16 + k) * BST + bn) * 4,
                  bbase + (size_t)(k0 + k) * ldb + bn, 16);
        }
    };

    load_stage(0, 0);
    cpa_commit();
    if (nt > 1) load_stage(1, 16);
    cpa_commit();

    const int cb = wn + (lane >> 2);
    const int kq = lane & 3;
    const int lrow = lane & 15;
    const int lcol = (lane >> 4) << 2;

    int cur = 0, n2 = 2;
    for (int t = 0; t < nt; t++) {
        cpa_wait1();
        __syncthreads();
        if (t + 2 < nt) load_stage(n2, (t + 2) * 16);
        cpa_commit();

#pragma unroll
        for (int ks = 0; ks < 2; ks++) {
            const int klo = ks * 8;
            const int kk = klo + kq;
            uint32_t af[4][4], bf[8][2];
#pragma unroll
            for (int i = 0; i < 4; i++) {
                const uint32_t addr = sA +
                    (uint32_t)((cur * 128 + wm + i * 16 + lrow) * AST + klo + lcol) * 4;
                ldsm4(af[i][0], af[i][1], af[i][2], af[i][3], addr);
            }
#pragma unroll
            for (int j = 0; j < 8; j++) {
                bf[j][0] = __float_as_uint(Bsf[(cur * 16 + kk) * BST + cb + j * 8]);
                bf[j][1] = __float_as_uint(Bsf[(cur * 16 + kk + 4) * BST + cb + j * 8]);
            }
#pragma unroll
            for (int i = 0; i < 4; i++)
#pragma unroll
                for (int j = 0; j < 8; j++)
                    mma_tf32(acc[i][j], af[i], bf[j]);
        }
        cur = (cur == 2) ? 0 : cur + 1;
        n2  = (n2  == 2) ? 0 : n2  + 1;
    }

    // ---------------- epilogues ----------------
    const float scl = 0.08838834764831845f;  // 1/sqrt(128)
#pragma unroll
    for (int i = 0; i < 4; i++) {
#pragma unroll
        for (int rr = 0; rr < 2; rr++) {
            const int r = m0 + wm + i * 16 + (lane >> 2) + rr * 8;
            if (r >= Mz) continue;
            if (MODE==GM_QKV) {
#pragma unroll
                for (int j = 0; j < 8; j++) {
                    const int c = n0 + wn + j * 8 + (lane & 3) * 2;
                    float v0 = acc[i][j][rr * 2 + 0] + g_bqkv[c];
                    float v1 = acc[i][j][rr * 2 + 1] + g_bqkv[c + 1];
                    if (c < 2048) {
                        g_q[(size_t)r * 2048 + c]     = v0;
                        g_q[(size_t)r * 2048 + c + 1] = v1;
                    } else if (c < 2304) {
                        g_k[(size_t)r * 256 + c - 2048]     = v0;
                        g_k[(size_t)r * 256 + c - 2048 + 1] = v1;
                    } else {
                        g_v[(size_t)r * 256 + c - 2304]     = tf32r(v0);
                        g_v[(size_t)r * 256 + c - 2304 + 1] = tf32r(v1);
                    }
                }
            } else if (MODE==GM_SCORES) {
                const size_t base = (size_t)z * Sc * Sc + (size_t)r * Sc;
#pragma unroll
                for (int j = 0; j < 8; j++) {
                    const int c = n0 + wn + j * 8 + (lane & 3) * 2;
                    float v0 = acc[i][j][rr * 2 + 0] * scl;
                    float v1 = acc[i][j][rr * 2 + 1] * scl;
                    if (c > r)     v0 = -1e9f;
                    if (c + 1 > r) v1 = -1e9f;
                    g_sc[base + c]     = v0;
                    g_sc[base + c + 1] = v1;
                }
            } else if (MODE==GM_MD) {
                const int tok = g_list[z * Tc + r];
                const float w = g_dw[tok * Ec + z];
                float* dst = g_moe + (size_t)tok * 2048;
#pragma unroll
                for (int j = 0; j < 8; j++) {
                    const int c = n0 + wn + j * 8 + (lane & 3) * 2;
                    atomicAdd(dst + c,     acc[i][j][rr * 2 + 0] * w);
                    atomicAdd(dst + c + 1, acc[i][j][rr * 2 + 1] * w);
                }
            } else {
                float* Cp; int ldc; const float* res = nullptr;
                constexpr bool RND = (MODE==GM_PV);
                if (MODE==GM_PV)      { Cp = g_ao + (size_t)bb * Sc * 2048 + hh * 128; ldc = 2048; }
                else if (MODE==GM_O)  { Cp = g_x;  ldc = 2048; res = extra; }
                else if (MODE==GM_MG) { Cp = g_mg + (size_t)z * Tc * IM; ldc = IM; }
                else if (MODE==GM_MU) { Cp = g_mu + (size_t)z * Tc * IM; ldc = IM; }
                else if (MODE==GM_SG) { Cp = g_sgv; ldc = ISH; }
                else if (MODE==GM_SU) { Cp = g_suv; ldc = ISH; }
                else                  { Cp = g_sh;  ldc = 2048; }
                const size_t rowoff = (size_t)r * ldc;
#pragma unroll
                for (int j = 0; j < 8; j++) {
                    const int c = n0 + wn + j * 8 + (lane & 3) * 2;
                    float v0 = acc[i][j][rr * 2 + 0];
                    float v1 = acc[i][j][rr * 2 + 1];
                    if (res)  { v0 += res[rowoff + c]; v1 += res[rowoff + c + 1]; }
                    if (RND)  { v0 = tf32r(v0); v1 = tf32r(v1); }
                    Cp[rowoff + c]     = v0;
                    Cp[rowoff + c + 1] = v1;
                }
            }
        }
    }
}

// ---------------- launch ----------------
extern "C" void kernel_launch(void* const* d_in, const int* in_sizes, int n_in,
                              void* d_out, int out_size) {
    (void)in_sizes; (void)n_in; (void)out_size;
    const float* x0  = (const float*)d_in[0];
    const float* ln1 = (const float*)d_in[1];
    const float* wq  = (const float*)d_in[2];
    const float* bq  = (const float*)d_in[3];
    const float* wk  = (const float*)d_in[4];
    const float* bk  = (const float*)d_in[5];
    const float* wv  = (const float*)d_in[6];
    const float* bv  = (const float*)d_in[7];
    const float* wo  = (const float*)d_in[8];
    const float* ln2 = (const float*)d_in[9];
    const float* rw  = (const float*)d_in[10];
    const float* wg  = (const float*)d_in[11];
    const float* wu  = (const float*)d_in[12];
    const float* wd  = (const float*)d_in[13];
    const float* swg = (const float*)d_in[14];
    const float* swu = (const float*)d_in[15];
    const float* swd = (const float*)d_in[16];
    const float* sgw = (const float*)d_in[17];
    float* out = (float*)d_out;

    cudaFuncSetAttribute(gemm_kernel<GM_QKV>,    cudaFuncAttributeMaxDynamicSharedMemorySize, GSMEM);
    cudaFuncSetAttribute(gemm_kernel<GM_SCORES>, cudaFuncAttributeMaxDynamicSharedMemorySize, GSMEM);
    cudaFuncSetAttribute(gemm_kernel<GM_PV>,     cudaFuncAttributeMaxDynamicSharedMemorySize, GSMEM);
    cudaFuncSetAttribute(gemm_kernel<GM_O>,      cudaFuncAttributeMaxDynamicSharedMemorySize, GSMEM);
    cudaFuncSetAttribute(gemm_kernel<GM_MG>,     cudaFuncAttributeMaxDynamicSharedMemorySize, GSMEM);
    cudaFuncSetAttribute(gemm_kernel<GM_MU>,     cudaFuncAttributeMaxDynamicSharedMemorySize, GSMEM);
    cudaFuncSetAttribute(gemm_kernel<GM_MD>,     cudaFuncAttributeMaxDynamicSharedMemorySize, GSMEM);
    cudaFuncSetAttribute(gemm_kernel<GM_SG>,     cudaFuncAttributeMaxDynamicSharedMemorySize, GSMEM);
    cudaFuncSetAttribute(gemm_kernel<GM_SU>,     cudaFuncAttributeMaxDynamicSharedMemorySize, GSMEM);
    cudaFuncSetAttribute(gemm_kernel<GM_SD>,     cudaFuncAttributeMaxDynamicSharedMemorySize, GSMEM);

    auto blocks = [](size_t n) { return (unsigned)((n + 255) / 256); };

    round_copy_str_kernel<<<blocks((size_t)2048*2048), 256>>>(wq, 2048*2048, 2048, NQKV, 0);
    round_copy_str_kernel<<<blocks((size_t)2048*256),  256>>>(wk, 2048*256,  256,  NQKV, 2048);
    round_copy_str_kernel<<<blocks((size_t)2048*256),  256>>>(wv, 2048*256,  256,  NQKV, 2304);
    bias_concat_kernel<<<10, 256>>>(bq, bk, bv);
    round_copy_kernel<OFF_WO ><<<blocks((size_t)2048*2048), 256>>>(wo,  2048*2048);
    round_copy_kernel<OFF_WG ><<<blocks((size_t)Ec*2048*IM),256>>>(wg,  Ec*2048*IM);
    round_copy_kernel<OFF_WU ><<<blocks((size_t)Ec*2048*IM),256>>>(wu,  Ec*2048*IM);
    round_copy_kernel<OFF_WD ><<<blocks((size_t)Ec*IM*2048),256>>>(wd,  Ec*IM*2048);
    round_copy_kernel<OFF_SWG><<<blocks((size_t)2048*ISH),  256>>>(swg, 2048*ISH);
    round_copy_kernel<OFF_SWU><<<blocks((size_t)2048*ISH),  256>>>(swu, 2048*ISH);
    round_copy_kernel<OFF_SWD><<<blocks((size_t)ISH*2048),  256>>>(swd, ISH*2048);

    clear_cnt_kernel<<<1, 32>>>();
    clear_moe_kernel<<<(Tc * Hc) / 256, 256>>>();

    // attention
    rmsnorm_kernel<0><<<Tc, 256>>>(x0, ln1);
    gemm_kernel<GM_QKV><<<dim3(20, 32, 1), 128, GSMEM>>>(nullptr);
    rope_kernel<<<dim3(Tc, NQc + NKVc), 64>>>();
    kT_kernel<<<(Bc * NKVc * DHc * Sc) / 256, 256>>>();
    gemm_kernel<GM_SCORES><<<dim3(16, 16, 32), 128, GSMEM>>>(nullptr);
    softmax_kernel<<<Bc * NQc * Sc, 256>>>();
    gemm_kernel<GM_PV><<<dim3(1, 16, 32), 128, GSMEM>>>(nullptr);
    gemm_kernel<GM_O><<<dim3(16, 32, 1), 128, GSMEM>>>(x0);

    // MoE block
    rmsnorm_kernel<1><<<Tc, 256>>>(nullptr, ln2);
    router_kernel<<<Tc / 8, 256>>>(rw);
    gemm_kernel<GM_MG><<<dim3(11, 32, 8), 128, GSMEM>>>(nullptr);
    gemm_kernel<GM_MU><<<dim3(11, 32, 8), 128, GSMEM>>>(nullptr);
    moe_act_kernel<<<dim3(6, Tc, 8), 256>>>();
    gemm_kernel<GM_MD><<<dim3(16, 32, 8), 128, GSMEM>>>(nullptr);

    // shared expert
    gemm_kernel<GM_SG><<<dim3(44, 32, 1), 128, GSMEM>>>(nullptr);
    gemm_kernel<GM_SU><<<dim3(44, 32, 1), 128, GSMEM>>>(nullptr);
    shared_act_kernel<<<(size_t)(Tc) * ISH / 256, 256>>>();
    sgate_kernel<<<Tc / 8, 256>>>(sgw);
    gemm_kernel<GM_SD><<<dim3(16, 32, 1), 128, GSMEM>>>(nullptr);

    final_kernel<<<(Tc * Hc) / 256, 256>>>(out);
}

// round 14
// speedup vs baseline: 2.2071x; 1.0105x over previous
#include <cuda_runtime.h>
#include <math.h>
#include <stdint.h>

// ---------------- problem constants ----------------
constexpr int Bc   = 2;
constexpr int Sc   = 2048;
constexpr int Hc   = 2048;
constexpr int Tc   = Bc * Sc;      // 4096 tokens
constexpr int Ec   = 8;
constexpr int IM   = 1408;
constexpr int ISH  = 5632;
constexpr int NQc  = 16;
constexpr int NKVc = 2;
constexpr int DHc  = 128;
constexpr float EPSc = 1e-5f;
constexpr int NQKV = 2560;         // 2048 (Q) + 256 (K) + 256 (V)

// rounded-weight scratch offsets
constexpr size_t OFF_QKV = 0;                              // [2048][2560] interleaved
constexpr size_t OFF_WO  = OFF_QKV + (size_t)2048 * NQKV;
constexpr size_t OFF_WG  = OFF_WO  + (size_t)2048 * 2048;
constexpr size_t OFF_WU  = OFF_WG  + (size_t)Ec * 2048 * IM;
constexpr size_t OFF_WD  = OFF_WU  + (size_t)Ec * 2048 * IM;
constexpr size_t OFF_SWG = OFF_WD  + (size_t)Ec * IM * 2048;
constexpr size_t OFF_SWU = OFF_SWG + (size_t)2048 * ISH;
constexpr size_t OFF_SWD = OFF_SWU + (size_t)2048 * ISH;
constexpr size_t WR_TOT  = OFF_SWD + (size_t)ISH * 2048;

// ---------------- scratch (device globals; no allocations allowed) ----------------
__device__ float g_wr [WR_TOT];                      // tf32-rounded weights
__device__ float g_bqkv[NQKV];                       // concatenated q/k/v biases
__device__ float g_h  [(size_t)Tc * Hc];
__device__ float g_q  [(size_t)Tc * NQc * DHc];
__device__ float g_k  [(size_t)Tc * NKVc * DHc];
__device__ float g_v  [(size_t)Tc * NKVc * DHc];
__device__ float g_kT [(size_t)Bc * NKVc * DHc * Sc];
__device__ float g_ao [(size_t)Tc * Hc];
__device__ float g_x  [(size_t)Tc * Hc];
__device__ float g_t2 [(size_t)Tc * Hc];             // exact (router/sgate)
__device__ float g_t2r[(size_t)Tc * Hc];             // tf32-rounded (GEMM A)
__device__ float g_dw [Tc * Ec];
__device__ int   g_cnt[Ec];
__device__ int   g_list[Ec * Tc];
__device__ float g_mg [(size_t)Ec * Tc * IM];
__device__ float g_mu [(size_t)Ec * Tc * IM];
__device__ float g_moe[(size_t)Tc * Hc];
__device__ float g_sgv[(size_t)Tc * ISH];
__device__ float g_suv[(size_t)Tc * ISH];
__device__ float g_sh [(size_t)Tc * Hc];
__device__ float g_sgate[Tc];

__device__ __forceinline__ float tf32r(float x) {
    uint32_t u;
    asm("cvt.rna.tf32.f32 %0, %1;" : "=r"(u) : "f"(x));
    return __uint_as_float(u);
}

// ---------------- weight rounding ----------------
template<size_t OFF>
__global__ void round_copy_kernel(const float* __restrict__ src, int n) {
    const int i = blockIdx.x * 256 + threadIdx.x;
    if (i < n) g_wr[OFF + i] = tf32r(src[i]);
}

__global__ void round_copy_str_kernel(const float* __restrict__ src, int n,
                                      int srcN, int ldDst, int colOff) {
    const int i = blockIdx.x * 256 + threadIdx.x;
    if (i < n) {
        const int k = i / srcN, c = i % srcN;
        g_wr[OFF_QKV + (size_t)k * ldDst + colOff + c] = tf32r(src[i]);
    }
}

__global__ void bias_concat_kernel(const float* __restrict__ bq,
                                   const float* __restrict__ bk,
                                   const float* __restrict__ bv) {
    const int i = blockIdx.x * 256 + threadIdx.x;
    if (i < 2048)       g_bqkv[i] = bq[i];
    else if (i < 2304)  g_bqkv[i] = bk[i - 2048];
    else if (i < NQKV)  g_bqkv[i] = bv[i - 2304];
}

// ---------------- small kernels ----------------
__global__ void clear_cnt_kernel() {
    if (threadIdx.x < Ec) g_cnt[threadIdx.x] = 0;
}
__global__ void clear_moe_kernel() {
    g_moe[(size_t)blockIdx.x * 256 + threadIdx.x] = 0.f;
}

template<int PHASE>
__global__ void rmsnorm_kernel(const float* __restrict__ xin,
                               const float* __restrict__ scale) {
    __shared__ float red[256];
    const int row = blockIdx.x;
    const float* x = (PHASE == 0) ? (xin + (size_t)row * Hc) : (g_x + (size_t)row * Hc);
    float s = 0.f;
    for (int i = threadIdx.x; i < Hc; i += 256) { float v = x[i]; s += v * v; }
    red[threadIdx.x] = s; __syncthreads();
    for (int o = 128; o > 0; o >>= 1) {
        if (threadIdx.x < o) red[threadIdx.x] += red[threadIdx.x + o];
        __syncthreads();
    }
    const float inv = rsqrtf(red[0] / (float)Hc + EPSc);
    for (int i = threadIdx.x; i < Hc; i += 256) {
        const float v = x[i] * inv * scale[i];
        if (PHASE == 0) {
            g_h[(size_t)row * Hc + i] = tf32r(v);
        } else {
            g_t2 [(size_t)row * Hc + i] = v;
            g_t2r[(size_t)row * Hc + i] = tf32r(v);
        }
    }
}

__global__ void rope_kernel() {
    const int tok  = blockIdx.x;
    const int head = blockIdx.y;
    const int j    = threadIdx.x;         // 0..63
    const int s    = tok & (Sc - 1);
    const float inv = powf(10000.f, -(float)(2 * j) / 128.f);
    const float ang = (float)s * inv;
    float si, c;
    sincosf(ang, &si, &c);
    float* p = (head < NQc) ? (g_q + (size_t)tok * (NQc * DHc) + head * DHc)
                            : (g_k + (size_t)tok * (NKVc * DHc) + (head - NQc) * DHc);
    const float x1 = p[j], x2 = p[j + 64];
    p[j]      = tf32r(x1 * c - x2 * si);
    p[j + 64] = tf32r(x2 * c + x1 * si);
}

__global__ void kT_kernel() {
    const int i  = blockIdx.x * 256 + threadIdx.x;
    const int s  = i & (Sc - 1);
    const int d  = (i >> 11) & 127;
    const int bk = i >> 18;
    g_kT[i] = g_k[((size_t)((bk >> 1) * Sc + s)) * (NKVc * DHc) + (bk & 1) * DHc + d];
}

__global__ void router_kernel(const float* __restrict__ rw) {
    const int tok  = blockIdx.x * 8 + (threadIdx.x >> 5);
    const int lane = threadIdx.x & 31;
    const float* tr = g_t2 + (size_t)tok * Hc;
    float acc[8];
#pragma unroll
    for (int e = 0; e < 8; e++) acc[e] = 0.f;
    for (int h = lane; h < Hc; h += 32) {
        const float tv = tr[h];
        const float* rp = rw + h * 8;
#pragma unroll
        for (int e = 0; e < 8; e++) acc[e] += tv * rp[e];
    }
#pragma unroll
    for (int e = 0; e < 8; e++)
        for (int o = 16; o; o >>= 1) acc[e] += __shfl_xor_sync(0xffffffffu, acc[e], o);
    if (lane == 0) {
        float m = acc[0];
        for (int e = 1; e < 8; e++) m = fmaxf(m, acc[e]);
        float p[8], s = 0.f;
        for (int e = 0; e < 8; e++) { p[e] = expf(acc[e] - m); s += p[e]; }
        for (int e = 0; e < 8; e++) p[e] /= s;
        bool used[8] = {false,false,false,false,false,false,false,false};
        int isel[4]; float wsel[4]; float tsum = 0.f;
        for (int kk = 0; kk < 4; kk++) {
            int best = 0; float bv = -1.f;
            for (int e = 0; e < 8; e++)
                if (!used[e] && p[e] > bv) { bv = p[e]; best = e; }
            used[best] = true; isel[kk] = best; wsel[kk] = bv; tsum += bv;
        }
        float outw[8] = {0,0,0,0,0,0,0,0};
        for (int kk = 0; kk < 4; kk++) outw[isel[kk]] = wsel[kk] / tsum;
        for (int e = 0; e < 8; e++) g_dw[tok * 8 + e] = outw[e];
        for (int kk = 0; kk < 4; kk++) {
            const int pos = atomicAdd(&g_cnt[isel[kk]], 1);
            g_list[isel[kk] * Tc + pos] = tok;
        }
    }
}

__global__ void moe_act_kernel() {
    const int e = blockIdx.z, row = blockIdx.y;
    if (row >= g_cnt[e]) return;
    const int col = blockIdx.x * 256 + threadIdx.x;
    if (col >= IM) return;
    const size_t i = ((size_t)e * Tc + row) * IM + col;
    const float g = g_mg[i], u = g_mu[i];
    g_mg[i] = tf32r(g / (1.f + expf(-g)) * u);
}

__global__ void shared_act_kernel() {
    const size_t i = (size_t)blockIdx.x * 256 + threadIdx.x;
    const float g = g_sgv[i], u = g_suv[i];
    g_sgv[i] = tf32r(g / (1.f + expf(-g)) * u);
}

__global__ void sgate_kernel(const float* __restrict__ sgw) {
    const int tok  = blockIdx.x * 8 + (threadIdx.x >> 5);
    const int lane = threadIdx.x & 31;
    const float* tr = g_t2 + (size_t)tok * Hc;
    float s = 0.f;
    for (int h = lane; h < Hc; h += 32) s += tr[h] * sgw[h];
    for (int o = 16; o; o >>= 1) s += __shfl_xor_sync(0xffffffffu, s, o);
    if (lane == 0) g_sgate[tok] = 1.f / (1.f + expf(-s));
}

__global__ void final_kernel(float* __restrict__ out) {
    const size_t i = (size_t)blockIdx.x * 256 + threadIdx.x;
    const int row = (int)(i >> 11);
    out[i] = g_x[i] + g_moe[i] + g_sgate[row] * g_sh[i];
}

// ---------------- shared PTX helpers ----------------
__device__ __forceinline__ void mma_tf32(float* c, const uint32_t* a, const uint32_t* b) {
    asm volatile(
        "mma.sync.aligned.m16n8k8.row.col.f32.tf32.tf32.f32 "
        "{%0,%1,%2,%3}, {%4,%5,%6,%7}, {%8,%9}, {%0,%1,%2,%3};"
        : "+f"(c[0]), "+f"(c[1]), "+f"(c[2]), "+f"(c[3])
        : "r"(a[0]), "r"(a[1]), "r"(a[2]), "r"(a[3]), "r"(b[0]), "r"(b[1]));
}

__device__ __forceinline__ void ldsm4(uint32_t& r0, uint32_t& r1, uint32_t& r2, uint32_t& r3,
                                      uint32_t addr) {
    asm volatile("ldmatrix.sync.aligned.m8n8.x4.shared.b16 {%0,%1,%2,%3}, [%4];"
                 : "=r"(r0), "=r"(r1), "=r"(r2), "=r"(r3) : "r"(addr));
}

__device__ __forceinline__ void cpa16(uint32_t dst, const void* src, int sz) {
    asm volatile("cp.async.cg.shared.global [%0], [%1], 16, %2;\n"
                 :: "r"(dst), "l"(src), "r"(sz));
}
__device__ __forceinline__ void cpa_commit() {
    asm volatile("cp.async.commit_group;\n");
}
__device__ __forceinline__ void cpa_wait0() {
    asm volatile("cp.async.wait_group 0;\n" ::: "memory");
}
__device__ __forceinline__ void cpa_wait1() {
    asm volatile("cp.async.wait_group 1;\n" ::: "memory");
}

// ---------------- fused flash attention ----------------
// Per CTA: (b, h), 128 q-rows; loop 64-key chunks; online softmax.
constexpr int FQS = 132;   // Q smem stride
constexpr int FKS = 72;    // K smem stride ([dh][key])
constexpr int FVS = 136;   // V smem stride ([key][dh])
constexpr int FPS = 68;    // P smem stride ([q][key])
constexpr int F_K0 = 128 * FQS;
constexpr int F_V0 = F_K0 + 2 * 128 * FKS;
constexpr int F_P0 = F_V0 + 64 * FVS;
constexpr int FSMEM = (F_P0 + 128 * FPS) * 4;   // 210944 bytes

__global__ __launch_bounds__(256, 1) void flash_kernel() {
    extern __shared__ float fs[];
    const int tid = threadIdx.x, lane = tid & 31, wid = tid >> 5;
    const int z  = blockIdx.z;
    const int qt = 15 - blockIdx.y;     // largest tiles first
    const int bb = z >> 4, hh = z & 15;
    const int q0 = qt * 128;
    const int nc = 2 * qt + 2;          // 64-key chunks
    const float scl = 0.08838834764831845f;

    const uint32_t sb = (uint32_t)__cvta_generic_to_shared(fs);
    const uint32_t sQ = sb, sK = sb + F_K0 * 4, sV = sb + F_V0 * 4, sP = sb + F_P0 * 4;
    float* Ksf = fs + F_K0;
    float* Vsf = fs + F_V0;
    float* Psf = fs + F_P0;

    const float* Qg  = g_q + ((size_t)bb * Sc + q0) * 2048 + hh * 128;
    const float* KTg = g_kT + (size_t)(bb * 2 + (hh >> 3)) * 128 * Sc;
    const float* Vg  = g_v + (size_t)bb * Sc * 256 + (hh >> 3) * 128;

    // prologue: Q tile + K chunk 0 (one group)
    {
        const int r = tid >> 1, hf = tid & 1;
#pragma unroll
        for (int c = 0; c < 16; c++)
            cpa16(sQ + (uint32_t)(r * FQS + hf * 64 + c * 4) * 4,
                  Qg + (size_t)r * 2048 + hf * 64 + c * 4, 16);
#pragma unroll
        for (int c = 0; c < 8; c++)
            cpa16(sK + (uint32_t)(r * FKS + hf * 32 + c * 4) * 4,
                  KTg + (size_t)r * Sc + hf * 32 + c * 4, 16);
    }
    cpa_commit();

    float oacc[16][4];
#pragma unroll
    for (int j = 0; j < 16; j++)
#pragma unroll
        for (int e = 0; e < 4; e++) oacc[j][e] = 0.f;
    float mrow[2] = {-1e30f, -1e30f};
    float lrow[2] = {0.f, 0.f};

    const int wm = wid * 16;
    const int kq = lane & 3, cbq = lane >> 2;
    const int lrw = lane & 15, lcl = (lane >> 4) << 2;

    for (int c = 0; c < nc; c++) {
        const int kc0 = c * 64;
        const int kbuf = c & 1;
        cpa_wait0();
        __syncthreads();

        // issue V_c (group A), then K_{c+1} (group B)
        {
            const int r = tid >> 2, q4 = tid & 3;
#pragma unroll
            for (int cc = 0; cc < 8; cc++)
                cpa16(sV + (uint32_t)(r * FVS + q4 * 32 + cc * 4) * 4,
                      Vg + (size_t)(kc0 + r) * 256 + q4 * 32 + cc * 4, 16);
        }
        cpa_commit();
        const bool more = (c + 1) < nc;
        if (more) {
            const int r = tid >> 1, hf = tid & 1;
            const int nb = (c + 1) & 1;
#pragma unroll
            for (int cc = 0; cc < 8; cc++)
                cpa16(sK + (uint32_t)((nb * 128 + r) * FKS + hf * 32 + cc * 4) * 4,
                      KTg + (size_t)r * Sc + (kc0 + 64) + hf * 32 + cc * 4, 16);
            cpa_commit();
        }

        // ---- S = Q K^T (warp: 16 q-rows x 64 keys) ----
        float sacc[8][4];
#pragma unroll
        for (int j = 0; j < 8; j++)
#pragma unroll
            for (int e = 0; e < 4; e++) sacc[j][e] = 0.f;

#pragma unroll
        for (int ks = 0; ks < 16; ks++) {
            uint32_t af[4];
            ldsm4(af[0], af[1], af[2], af[3],
                  sQ + (uint32_t)((wm + lrw) * FQS + ks * 8 + lcl) * 4);
            const float* kb = Ksf + (size_t)kbuf * 128 * FKS;
#pragma unroll
            for (int j = 0; j < 8; j++) {
                uint32_t bf[2];
                bf[0] = __float_as_uint(kb[(ks * 8 + kq) * FKS + cbq + j * 8]);
                bf[1] = __float_as_uint(kb[(ks * 8 + kq + 4) * FKS + cbq + j * 8]);
                mma_tf32(sacc[j], af, bf);
            }
        }

        // ---- online softmax + P to smem ----
#pragma unroll
        for (int mi = 0; mi < 2; mi++) {
            const int rg = q0 + wm + (lane >> 2) + mi * 8;
            float mx = -1e30f;
#pragma unroll
            for (int j = 0; j < 8; j++)
#pragma unroll
                for (int e = 0; e < 2; e++) {
                    const int cg = kc0 + (lane & 3) * 2 + j * 8 + e;
                    float v = (cg <= rg) ? sacc[j][mi * 2 + e] * scl : -1e30f;
                    sacc[j][mi * 2 + e] = v;
                    mx = fmaxf(mx, v);
                }
            mx = fmaxf(mx, __shfl_xor_sync(0xffffffffu, mx, 1));
            mx = fmaxf(mx, __shfl_xor_sync(0xffffffffu, mx, 2));
            const float newm = fmaxf(mrow[mi], mx);
            const float sc2 = expf(mrow[mi] - newm);
            float rs = 0.f;
#pragma unroll
            for (int j = 0; j < 8; j++)
#pragma unroll
                for (int e = 0; e < 2; e++) {
                    const float p = expf(sacc[j][mi * 2 + e] - newm);
                    sacc[j][mi * 2 + e] = p;
                    rs += p;
                }
            rs += __shfl_xor_sync(0xffffffffu, rs, 1);
            rs += __shfl_xor_sync(0xffffffffu, rs, 2);
            lrow[mi] = lrow[mi] * sc2 + rs;
            mrow[mi] = newm;
#pragma unroll
            for (int j = 0; j < 16; j++) {
                oacc[j][mi * 2 + 0] *= sc2;
                oacc[j][mi * 2 + 1] *= sc2;
            }
            const int pr = wm + (lane >> 2) + mi * 8;
#pragma unroll
            for (int j = 0; j < 8; j++) {
                Psf[pr * FPS + (lane & 3) * 2 + j * 8 + 0] = tf32r(sacc[j][mi * 2 + 0]);
                Psf[pr * FPS + (lane & 3) * 2 + j * 8 + 1] = tf32r(sacc[j][mi * 2 + 1]);
            }
        }

        if (more) cpa_wait1(); else cpa_wait0();   // V_c landed (K_{c+1} may fly)
        __syncthreads();

        // ---- O += P V ----
#pragma unroll
        for (int ks = 0; ks < 8; ks++) {
            uint32_t af[4];
            ldsm4(af[0], af[1], af[2], af[3],
                  sP + (uint32_t)((wm + lrw) * FPS + ks * 8 + lcl) * 4);
#pragma unroll
            for (int j = 0; j < 16; j++) {
                uint32_t bf[2];
                bf[0] = __float_as_uint(Vsf[(ks * 8 + kq) * FVS + cbq + j * 8]);
                bf[1] = __float_as_uint(Vsf[(ks * 8 + kq + 4) * FVS + cbq + j * 8]);
                mma_tf32(oacc[j], af, bf);
            }
        }
        __syncthreads();   // all warps done with V/P before next-iter overwrite
    }

    // ---- epilogue: O / l -> g_ao (tf32-rounded) ----
#pragma unroll
    for (int mi = 0; mi < 2; mi++) {
        const float inv = 1.f / lrow[mi];
        const int rg = q0 + wm + (lane >> 2) + mi * 8;
        float* dst = g_ao + ((size_t)bb * Sc + rg) * 2048 + hh * 128;
#pragma unroll
        for (int j = 0; j < 16; j++) {
            dst[(lane & 3) * 2 + j * 8 + 0] = tf32r(oacc[j][mi * 2 + 0] * inv);
            dst[(lane & 3) * 2 + j * 8 + 1] = tf32r(oacc[j][mi * 2 + 1] * inv);
        }
    }
}

// ---------------- tf32 GEMM: 3-stage cp.async + ldmatrix-A, single-sync loop ----------------
enum GMode { GM_QKV, GM_O, GM_MG, GM_MU, GM_MD, GM_SG, GM_SU, GM_SD };

constexpr int AST = 20;
constexpr int BST = 136;
constexpr int A_STG = 128 * AST;
constexpr int B_STG = 16 * BST;
constexpr int GSMEM = 3 * (A_STG + B_STG) * 4;

template<int MODE>
__global__ __launch_bounds__(128, 2) void gemm_kernel(const float* __restrict__ extra) {
    extern __shared__ float smem[];
    constexpr int Kv = (MODE==GM_MD) ? IM : (MODE==GM_SD) ? ISH : 2048;

    const int tid = threadIdx.x;
    const int z   = blockIdx.z;
    const int m0  = blockIdx.y * 128, n0 = blockIdx.x * 128;

    int Mz;
    if (MODE==GM_MG || MODE==GM_MU || MODE==GM_MD) Mz = g_cnt[z];
    else Mz = Tc;
    if (m0 >= Mz) return;

    const float* A; const float* Bp; int lda, ldb;
    if (MODE==GM_QKV) {
        A = g_h; lda = Hc; Bp = g_wr + OFF_QKV; ldb = NQKV;
    } else if (MODE==GM_O) {
        A = g_ao; lda = 2048; Bp = g_wr + OFF_WO; ldb = 2048;
    } else if (MODE==GM_MG) {
        A = g_t2r; lda = 2048; Bp = g_wr + OFF_WG + (size_t)z * 2048 * IM; ldb = IM;
    } else if (MODE==GM_MU) {
        A = g_t2r; lda = 2048; Bp = g_wr + OFF_WU + (size_t)z * 2048 * IM; ldb = IM;
    } else if (MODE==GM_MD) {
        A = g_mg + (size_t)z * Tc * IM; lda = IM;
        Bp = g_wr + OFF_WD + (size_t)z * IM * 2048; ldb = 2048;
    } else if (MODE==GM_SG) {
        A = g_t2r; lda = 2048; Bp = g_wr + OFF_SWG; ldb = ISH;
    } else if (MODE==GM_SU) {
        A = g_t2r; lda = 2048; Bp = g_wr + OFF_SWU; ldb = ISH;
    } else { // GM_SD
        A = g_sgv; lda = ISH; Bp = g_wr + OFF_SWD; ldb = 2048;
    }

    float* Asf = smem;
    float* Bsf = smem + 3 * A_STG;

    float acc[4][8][4];
#pragma unroll
    for (int i = 0; i < 4; i++)
#pragma unroll
        for (int j = 0; j < 8; j++)
#pragma unroll
            for (int r = 0; r < 4; r++) acc[i][j][r] = 0.f;

    const int lane = tid & 31, wid = tid >> 5;
    const int wm = (wid >> 1) * 64;
    const int wn = (wid & 1) * 64;

    const int lm = tid;
    const int agl = m0 + lm;
    const bool aval = agl < Mz;
    const float* arp;
    if (MODE==GM_MG || MODE==GM_MU)
        arp = A + (size_t)(aval ? g_list[z * Tc + agl] : 0) * lda;
    else
        arp = A + (size_t)(aval ? agl : 0) * lda;
    const int asz = aval ? 16 : 0;
    const int arot = (lm >> 3) & 3;

    const int bw = tid >> 5;
    const int bn = (tid & 31) * 4;
    const float* bbase = Bp + n0;

    const int nt = Kv / 16;

    const uint32_t sA = (uint32_t)__cvta_generic_to_shared(Asf);
    const uint32_t sB = (uint32_t)__cvta_generic_to_shared(Bsf);

    auto load_stage = [&](int s, int k0) {
#pragma unroll
        for (int c = 0; c < 4; c++) {
            const int cc = (c + arot) & 3;
            cpa16(sA + (uint32_t)((s * 128 + lm) * AST + cc * 4) * 4, arp + k0 + cc * 4, asz);
        }
#pragma unroll
        for (int c = 0; c < 4; c++) {
            const int k = c * 4 + bw;
            cpa16(sB + (uint32_t)((s * 16 + k) * BST + bn) * 4,
                  bbase + (size_t)(k0 + k) * ldb + bn, 16);
        }
    };

    load_stage(0, 0);
    cpa_commit();
    if (nt > 1) load_stage(1, 16);
    cpa_commit();

    const int cb = wn + (lane >> 2);
    const int kq = lane & 3;
    const int lrow = lane & 15;
    const int lcol = (lane >> 4) << 2;

    int cur = 0, n2 = 2;
    for (int t = 0; t < nt; t++) {
        cpa_wait1();
        __syncthreads();
        if (t + 2 < nt) load_stage(n2, (t + 2) * 16);
        cpa_commit();

#pragma unroll
        for (int ks = 0; ks < 2; ks++) {
            const int klo = ks * 8;
            const int kk = klo + kq;
            uint32_t af[4][4], bf[8][2];
#pragma unroll
            for (int i = 0; i < 4; i++) {
                const uint32_t addr = sA +
                    (uint32_t)((cur * 128 + wm + i * 16 + lrow) * AST + klo + lcol) * 4;
                ldsm4(af[i][0], af[i][1], af[i][2], af[i][3], addr);
            }
#pragma unroll
            for (int j = 0; j < 8; j++) {
                bf[j][0] = __float_as_uint(Bsf[(cur * 16 + kk) * BST + cb + j * 8]);
                bf[j][1] = __float_as_uint(Bsf[(cur * 16 + kk + 4) * BST + cb + j * 8]);
            }
#pragma unroll
            for (int i = 0; i < 4; i++)
#pragma unroll
                for (int j = 0; j < 8; j++)
                    mma_tf32(acc[i][j], af[i], bf[j]);
        }
        cur = (cur == 2) ? 0 : cur + 1;
        n2  = (n2  == 2) ? 0 : n2  + 1;
    }

    // ---------------- epilogues ----------------
#pragma unroll
    for (int i = 0; i < 4; i++) {
#pragma unroll
        for (int rr = 0; rr < 2; rr++) {
            const int r = m0 + wm + i * 16 + (lane >> 2) + rr * 8;
            if (r >= Mz) continue;
            if (MODE==GM_QKV) {
#pragma unroll
                for (int j = 0; j < 8; j++) {
                    const int c = n0 + wn + j * 8 + (lane & 3) * 2;
                    float v0 = acc[i][j][rr * 2 + 0] + g_bqkv[c];
                    float v1 = acc[i][j][rr * 2 + 1] + g_bqkv[c + 1];
                    if (c < 2048) {
                        g_q[(size_t)r * 2048 + c]     = v0;
                        g_q[(size_t)r * 2048 + c + 1] = v1;
                    } else if (c < 2304) {
                        g_k[(size_t)r * 256 + c - 2048]     = v0;
                        g_k[(size_t)r * 256 + c - 2048 + 1] = v1;
                    } else {
                        g_v[(size_t)r * 256 + c - 2304]     = tf32r(v0);
                        g_v[(size_t)r * 256 + c - 2304 + 1] = tf32r(v1);
                    }
                }
            } else if (MODE==GM_MD) {
                const int tok = g_list[z * Tc + r];
                const float w = g_dw[tok * Ec + z];
                float* dst = g_moe + (size_t)tok * 2048;
#pragma unroll
                for (int j = 0; j < 8; j++) {
                    const int c = n0 + wn + j * 8 + (lane & 3) * 2;
                    atomicAdd(dst + c,     acc[i][j][rr * 2 + 0] * w);
                    atomicAdd(dst + c + 1, acc[i][j][rr * 2 + 1] * w);
                }
            } else {
                float* Cp; int ldc; const float* res = nullptr;
                if (MODE==GM_O)       { Cp = g_x;  ldc = 2048; res = extra; }
                else if (MODE==GM_MG) { Cp = g_mg + (size_t)z * Tc * IM; ldc = IM; }
                else if (MODE==GM_MU) { Cp = g_mu + (size_t)z * Tc * IM; ldc = IM; }
                else if (MODE==GM_SG) { Cp = g_sgv; ldc = ISH; }
                else if (MODE==GM_SU) { Cp = g_suv; ldc = ISH; }
                else                  { Cp = g_sh;  ldc = 2048; }
                const size_t rowoff = (size_t)r * ldc;
#pragma unroll
                for (int j = 0; j < 8; j++) {
                    const int c = n0 + wn + j * 8 + (lane & 3) * 2;
                    float v0 = acc[i][j][rr * 2 + 0];
                    float v1 = acc[i][j][rr * 2 + 1];
                    if (res)  { v0 += res[rowoff + c]; v1 += res[rowoff + c + 1]; }
                    Cp[rowoff + c]     = v0;
                    Cp[rowoff + c + 1] = v1;
                }
            }
        }
    }
}

// ---------------- launch ----------------
extern "C" void kernel_launch(void* const* d_in, const int* in_sizes, int n_in,
                              void* d_out, int out_size) {
    (void)in_sizes; (void)n_in; (void)out_size;
    const float* x0  = (const float*)d_in[0];
    const float* ln1 = (const float*)d_in[1];
    const float* wq  = (const float*)d_in[2];
    const float* bq  = (const float*)d_in[3];
    const float* wk  = (const float*)d_in[4];
    const float* bk  = (const float*)d_in[5];
    const float* wv  = (const float*)d_in[6];
    const float* bv  = (const float*)d_in[7];
    const float* wo  = (const float*)d_in[8];
    const float* ln2 = (const float*)d_in[9];
    const float* rw  = (const float*)d_in[10];
    const float* wg  = (const float*)d_in[11];
    const float* wu  = (const float*)d_in[12];
    const float* wd  = (const float*)d_in[13];
    const float* swg = (const float*)d_in[14];
    const float* swu = (const float*)d_in[15];
    const float* swd = (const float*)d_in[16];
    const float* sgw = (const float*)d_in[17];
    float* out = (float*)d_out;

    cudaFuncSetAttribute(gemm_kernel<GM_QKV>, cudaFuncAttributeMaxDynamicSharedMemorySize, GSMEM);
    cudaFuncSetAttribute(gemm_kernel<GM_O>,   cudaFuncAttributeMaxDynamicSharedMemorySize, GSMEM);
    cudaFuncSetAttribute(gemm_kernel<GM_MG>,  cudaFuncAttributeMaxDynamicSharedMemorySize, GSMEM);
    cudaFuncSetAttribute(gemm_kernel<GM_MU>,  cudaFuncAttributeMaxDynamicSharedMemorySize, GSMEM);
    cudaFuncSetAttribute(gemm_kernel<GM_MD>,  cudaFuncAttributeMaxDynamicSharedMemorySize, GSMEM);
    cudaFuncSetAttribute(gemm_kernel<GM_SG>,  cudaFuncAttributeMaxDynamicSharedMemorySize, GSMEM);
    cudaFuncSetAttribute(gemm_kernel<GM_SU>,  cudaFuncAttributeMaxDynamicSharedMemorySize, GSMEM);
    cudaFuncSetAttribute(gemm_kernel<GM_SD>,  cudaFuncAttributeMaxDynamicSharedMemorySize, GSMEM);
    cudaFuncSetAttribute(flash_kernel,        cudaFuncAttributeMaxDynamicSharedMemorySize, FSMEM);

    auto blocks = [](size_t n) { return (unsigned)((n + 255) / 256); };

    round_copy_str_kernel<<<blocks((size_t)2048*2048), 256>>>(wq, 2048*2048, 2048, NQKV, 0);
    round_copy_str_kernel<<<blocks((size_t)2048*256),  256>>>(wk, 2048*256,  256,  NQKV, 2048);
    round_copy_str_kernel<<<blocks((size_t)2048*256),  256>>>(wv, 2048*256,  256,  NQKV, 2304);
    bias_concat_kernel<<<10, 256>>>(bq, bk, bv);
    round_copy_kernel<OFF_WO ><<<blocks((size_t)2048*2048), 256>>>(wo,  2048*2048);
    round_copy_kernel<OFF_WG ><<<blocks((size_t)Ec*2048*IM),256>>>(wg,  Ec*2048*IM);
    round_copy_kernel<OFF_WU ><<<blocks((size_t)Ec*2048*IM),256>>>(wu,  Ec*2048*IM);
    round_copy_kernel<OFF_WD ><<<blocks((size_t)Ec*IM*2048),256>>>(wd,  Ec*IM*2048);
    round_copy_kernel<OFF_SWG><<<blocks((size_t)2048*ISH),  256>>>(swg, 2048*ISH);
    round_copy_kernel<OFF_SWU><<<blocks((size_t)2048*ISH),  256>>>(swu, 2048*ISH);
    round_copy_kernel<OFF_SWD><<<blocks((size_t)ISH*2048),  256>>>(swd, ISH*2048);

    clear_cnt_kernel<<<1, 32>>>();
    clear_moe_kernel<<<(Tc * Hc) / 256, 256>>>();

    // attention
    rmsnorm_kernel<0><<<Tc, 256>>>(x0, ln1);
    gemm_kernel<GM_QKV><<<dim3(20, 32, 1), 128, GSMEM>>>(nullptr);
    rope_kernel<<<dim3(Tc, NQc + NKVc), 64>>>();
    kT_kernel<<<(Bc * NKVc * DHc * Sc) / 256, 256>>>();
    flash_kernel<<<dim3(1, 16, 32), 256, FSMEM>>>();
    gemm_kernel<GM_O><<<dim3(16, 32, 1), 128, GSMEM>>>(x0);

    // MoE block
    rmsnorm_kernel<1><<<Tc, 256>>>(nullptr, ln2);
    router_kernel<<<Tc / 8, 256>>>(rw);
    gemm_kernel<GM_MG><<<dim3(11, 32, 8), 128, GSMEM>>>(nullptr);
    gemm_kernel<GM_MU><<<dim3(11, 32, 8), 128, GSMEM>>>(nullptr);
    moe_act_kernel<<<dim3(6, Tc, 8), 256>>>();
    gemm_kernel<GM_MD><<<dim3(16, 32, 8), 128, GSMEM>>>(nullptr);

    // shared expert
    gemm_kernel<GM_SG><<<dim3(44, 32, 1), 128, GSMEM>>>(nullptr);
    gemm_kernel<GM_SU><<<dim3(44, 32, 1), 128, GSMEM>>>(nullptr);
    shared_act_kernel<<<(size_t)(Tc) * ISH / 256, 256>>>();
    sgate_kernel<<<Tc / 8, 256>>>(sgw);
    gemm_kernel<GM_SD><<<dim3(16, 32, 1), 128, GSMEM>>>(nullptr);

    final_kernel<<<(Tc * Hc) / 256, 256>>>(out);
}

// round 15
// speedup vs baseline: 2.3392x; 1.0599x over previous
#include <cuda_runtime.h>
#include <math.h>
#include <stdint.h>

// ---------------- problem constants ----------------
constexpr int Bc   = 2;
constexpr int Sc   = 2048;
constexpr int Hc   = 2048;
constexpr int Tc   = Bc * Sc;      // 4096 tokens
constexpr int Ec   = 8;
constexpr int IM   = 1408;
constexpr int ISH  = 5632;
constexpr int NQc  = 16;
constexpr int NKVc = 2;
constexpr int DHc  = 128;
constexpr float EPSc = 1e-5f;
constexpr int NQKV = 2560;         // 2048 (Q) + 256 (K) + 256 (V)

// rounded-weight scratch offsets
constexpr size_t OFF_QKV = 0;                              // [2048][2560] interleaved
constexpr size_t OFF_WO  = OFF_QKV + (size_t)2048 * NQKV;
constexpr size_t OFF_WG  = OFF_WO  + (size_t)2048 * 2048;
constexpr size_t OFF_WU  = OFF_WG  + (size_t)Ec * 2048 * IM;
constexpr size_t OFF_WD  = OFF_WU  + (size_t)Ec * 2048 * IM;
constexpr size_t OFF_SWG = OFF_WD  + (size_t)Ec * IM * 2048;
constexpr size_t OFF_SWU = OFF_SWG + (size_t)2048 * ISH;
constexpr size_t OFF_SWD = OFF_SWU + (size_t)2048 * ISH;
constexpr size_t WR_TOT  = OFF_SWD + (size_t)ISH * 2048;

// ---------------- scratch (device globals; no allocations allowed) ----------------
__device__ float g_wr [WR_TOT];                      // tf32-rounded weights
__device__ float g_bqkv[NQKV];                       // concatenated q/k/v biases
__device__ float g_h  [(size_t)Tc * Hc];
__device__ float g_q  [(size_t)Tc * NQc * DHc];
__device__ float g_k  [(size_t)Tc * NKVc * DHc];
__device__ float g_v  [(size_t)Tc * NKVc * DHc];
__device__ float g_kT [(size_t)Bc * NKVc * DHc * Sc];
__device__ float g_ao [(size_t)Tc * Hc];
__device__ float g_x  [(size_t)Tc * Hc];
__device__ float g_t2 [(size_t)Tc * Hc];             // exact (router/sgate)
__device__ float g_t2r[(size_t)Tc * Hc];             // tf32-rounded (GEMM A)
__device__ float g_dw [Tc * Ec];
__device__ int   g_cnt[Ec];
__device__ int   g_list[Ec * Tc];
__device__ float g_mg [(size_t)Ec * Tc * IM];
__device__ float g_mu [(size_t)Ec * Tc * IM];
__device__ float g_moe[(size_t)Tc * Hc];
__device__ float g_sgv[(size_t)Tc * ISH];
__device__ float g_suv[(size_t)Tc * ISH];
__device__ float g_sh [(size_t)Tc * Hc];
__device__ float g_sgate[Tc];

__device__ __forceinline__ float tf32r(float x) {
    uint32_t u;
    asm("cvt.rna.tf32.f32 %0, %1;" : "=r"(u) : "f"(x));
    return __uint_as_float(u);
}
__device__ __forceinline__ float4 tf32r4(float4 v) {
    v.x = tf32r(v.x); v.y = tf32r(v.y); v.z = tf32r(v.z); v.w = tf32r(v.w);
    return v;
}

// ---------------- weight rounding (float4) ----------------
template<size_t OFF>
__global__ void round_copy_kernel(const float* __restrict__ src, int n4) {
    const int i = blockIdx.x * 256 + threadIdx.x;
    if (i < n4)
        ((float4*)(g_wr + OFF))[i] = tf32r4(((const float4*)src)[i]);
}

// strided (float4): dst[k*ldDst + colOff + c4*4 ..] = rna(src[k*srcN + c4*4 ..])
__global__ void round_copy_str_kernel(const float* __restrict__ src, int n4,
                                      int srcN4, int ldDst, int colOff) {
    const int i = blockIdx.x * 256 + threadIdx.x;
    if (i < n4) {
        const int k = i / srcN4, c4 = i % srcN4;
        const float4 v = tf32r4(((const float4*)src)[i]);
        *(float4*)(g_wr + OFF_QKV + (size_t)k * ldDst + colOff + c4 * 4) = v;
    }
}

__global__ void bias_concat_kernel(const float* __restrict__ bq,
                                   const float* __restrict__ bk,
                                   const float* __restrict__ bv) {
    const int i = blockIdx.x * 256 + threadIdx.x;
    if (i < 2048)       g_bqkv[i] = bq[i];
    else if (i < 2304)  g_bqkv[i] = bk[i - 2048];
    else if (i < NQKV)  g_bqkv[i] = bv[i - 2304];
}

// ---------------- small kernels ----------------
__global__ void clear_cnt_kernel() {
    if (threadIdx.x < Ec) g_cnt[threadIdx.x] = 0;
}
__global__ void clear_moe_kernel() {
    ((float4*)g_moe)[(size_t)blockIdx.x * 256 + threadIdx.x] =
        make_float4(0.f, 0.f, 0.f, 0.f);
}

// single-read rmsnorm: row cached in 8 registers, float4 I/O
template<int PHASE>
__global__ void rmsnorm_kernel(const float* __restrict__ xin,
                               const float* __restrict__ scale) {
    __shared__ float red[256];
    const int row = blockIdx.x;
    const float* x = (PHASE == 0) ? (xin + (size_t)row * Hc) : (g_x + (size_t)row * Hc);
    const int tid = threadIdx.x;
    float4 v[2];
    float s = 0.f;
#pragma unroll
    for (int g = 0; g < 2; g++) {
        v[g] = ((const float4*)x)[tid + g * 256];
        s += v[g].x * v[g].x + v[g].y * v[g].y + v[g].z * v[g].z + v[g].w * v[g].w;
    }
    red[tid] = s; __syncthreads();
    for (int o = 128; o > 0; o >>= 1) {
        if (tid < o) red[tid] += red[tid + o];
        __syncthreads();
    }
    const float inv = rsqrtf(red[0] / (float)Hc + EPSc);
#pragma unroll
    for (int g = 0; g < 2; g++) {
        const int j = tid + g * 256;
        const float4 sc4 = ((const float4*)scale)[j];
        float4 o4;
        o4.x = v[g].x * inv * sc4.x;
        o4.y = v[g].y * inv * sc4.y;
        o4.z = v[g].z * inv * sc4.z;
        o4.w = v[g].w * inv * sc4.w;
        if (PHASE == 0) {
            ((float4*)(g_h + (size_t)row * Hc))[j] = tf32r4(o4);
        } else {
            ((float4*)(g_t2  + (size_t)row * Hc))[j] = o4;
            ((float4*)(g_t2r + (size_t)row * Hc))[j] = tf32r4(o4);
        }
    }
}

__global__ void rope_kernel() {
    const int tok  = blockIdx.x;
    const int head = blockIdx.y;
    const int j    = threadIdx.x;         // 0..63
    const int s    = tok & (Sc - 1);
    const float inv = powf(10000.f, -(float)(2 * j) / 128.f);
    const float ang = (float)s * inv;
    float si, c;
    sincosf(ang, &si, &c);
    float* p = (head < NQc) ? (g_q + (size_t)tok * (NQc * DHc) + head * DHc)
                            : (g_k + (size_t)tok * (NKVc * DHc) + (head - NQc) * DHc);
    const float x1 = p[j], x2 = p[j + 64];
    p[j]      = tf32r(x1 * c - x2 * si);
    p[j + 64] = tf32r(x2 * c + x1 * si);
}

__global__ void kT_kernel() {
    const int i  = blockIdx.x * 256 + threadIdx.x;
    const int s  = i & (Sc - 1);
    const int d  = (i >> 11) & 127;
    const int bk = i >> 18;
    g_kT[i] = g_k[((size_t)((bk >> 1) * Sc + s)) * (NKVc * DHc) + (bk & 1) * DHc + d];
}

__global__ void router_kernel(const float* __restrict__ rw) {
    const int tok  = blockIdx.x * 8 + (threadIdx.x >> 5);
    const int lane = threadIdx.x & 31;
    const float* tr = g_t2 + (size_t)tok * Hc;
    float acc[8];
#pragma unroll
    for (int e = 0; e < 8; e++) acc[e] = 0.f;
    for (int h = lane; h < Hc; h += 32) {
        const float tv = tr[h];
        const float* rp = rw + h * 8;
#pragma unroll
        for (int e = 0; e < 8; e++) acc[e] += tv * rp[e];
    }
#pragma unroll
    for (int e = 0; e < 8; e++)
        for (int o = 16; o; o >>= 1) acc[e] += __shfl_xor_sync(0xffffffffu, acc[e], o);
    if (lane == 0) {
        float m = acc[0];
        for (int e = 1; e < 8; e++) m = fmaxf(m, acc[e]);
        float p[8], s = 0.f;
        for (int e = 0; e < 8; e++) { p[e] = expf(acc[e] - m); s += p[e]; }
        for (int e = 0; e < 8; e++) p[e] /= s;
        bool used[8] = {false,false,false,false,false,false,false,false};
        int isel[4]; float wsel[4]; float tsum = 0.f;
        for (int kk = 0; kk < 4; kk++) {
            int best = 0; float bv = -1.f;
            for (int e = 0; e < 8; e++)
                if (!used[e] && p[e] > bv) { bv = p[e]; best = e; }
            used[best] = true; isel[kk] = best; wsel[kk] = bv; tsum += bv;
        }
        float outw[8] = {0,0,0,0,0,0,0,0};
        for (int kk = 0; kk < 4; kk++) outw[isel[kk]] = wsel[kk] / tsum;
        for (int e = 0; e < 8; e++) g_dw[tok * 8 + e] = outw[e];
        for (int kk = 0; kk < 4; kk++) {
            const int pos = atomicAdd(&g_cnt[isel[kk]], 1);
            g_list[isel[kk] * Tc + pos] = tok;
        }
    }
}

__global__ void moe_act_kernel() {
    const int e = blockIdx.z, row = blockIdx.y;
    if (row >= g_cnt[e]) return;
    const int c4 = blockIdx.x * 256 + threadIdx.x;
    if (c4 >= IM / 4) return;
    const size_t i4 = ((size_t)e * Tc + row) * (IM / 4) + c4;
    const float4 g4 = ((const float4*)g_mg)[i4];
    const float4 u4 = ((const float4*)g_mu)[i4];
    float4 o4;
    o4.x = tf32r(g4.x / (1.f + expf(-g4.x)) * u4.x);
    o4.y = tf32r(g4.y / (1.f + expf(-g4.y)) * u4.y);
    o4.z = tf32r(g4.z / (1.f + expf(-g4.z)) * u4.z);
    o4.w = tf32r(g4.w / (1.f + expf(-g4.w)) * u4.w);
    ((float4*)g_mg)[i4] = o4;
}

__global__ void shared_act_kernel() {
    const size_t i4 = (size_t)blockIdx.x * 256 + threadIdx.x;
    const float4 g4 = ((const float4*)g_sgv)[i4];
    const float4 u4 = ((const float4*)g_suv)[i4];
    float4 o4;
    o4.x = tf32r(g4.x / (1.f + expf(-g4.x)) * u4.x);
    o4.y = tf32r(g4.y / (1.f + expf(-g4.y)) * u4.y);
    o4.z = tf32r(g4.z / (1.f + expf(-g4.z)) * u4.z);
    o4.w = tf32r(g4.w / (1.f + expf(-g4.w)) * u4.w);
    ((float4*)g_sgv)[i4] = o4;
}

__global__ void sgate_kernel(const float* __restrict__ sgw) {
    const int tok  = blockIdx.x * 8 + (threadIdx.x >> 5);
    const int lane = threadIdx.x & 31;
    const float* tr = g_t2 + (size_t)tok * Hc;
    float s = 0.f;
    for (int h = lane; h < Hc; h += 32) s += tr[h] * sgw[h];
    for (int o = 16; o; o >>= 1) s += __shfl_xor_sync(0xffffffffu, s, o);
    if (lane == 0) g_sgate[tok] = 1.f / (1.f + expf(-s));
}

__global__ void final_kernel(float* __restrict__ out) {
    const size_t i4 = (size_t)blockIdx.x * 256 + threadIdx.x;
    const int row = (int)(i4 >> 9);   // (i4*4)/2048
    const float sg = g_sgate[row];
    const float4 x4 = ((const float4*)g_x)[i4];
    const float4 m4 = ((const float4*)g_moe)[i4];
    const float4 s4 = ((const float4*)g_sh)[i4];
    float4 o4;
    o4.x = x4.x + m4.x + sg * s4.x;
    o4.y = x4.y + m4.y + sg * s4.y;
    o4.z = x4.z + m4.z + sg * s4.z;
    o4.w = x4.w + m4.w + sg * s4.w;
    ((float4*)out)[i4] = o4;
}

// ---------------- shared PTX helpers ----------------
__device__ __forceinline__ void mma_tf32(float* c, const uint32_t* a, const uint32_t* b) {
    asm volatile(
        "mma.sync.aligned.m16n8k8.row.col.f32.tf32.tf32.f32 "
        "{%0,%1,%2,%3}, {%4,%5,%6,%7}, {%8,%9}, {%0,%1,%2,%3};"
        : "+f"(c[0]), "+f"(c[1]), "+f"(c[2]), "+f"(c[3])
        : "r"(a[0]), "r"(a[1]), "r"(a[2]), "r"(a[3]), "r"(b[0]), "r"(b[1]));
}

__device__ __forceinline__ void ldsm4(uint32_t& r0, uint32_t& r1, uint32_t& r2, uint32_t& r3,
                                      uint32_t addr) {
    asm volatile("ldmatrix.sync.aligned.m8n8.x4.shared.b16 {%0,%1,%2,%3}, [%4];"
                 : "=r"(r0), "=r"(r1), "=r"(r2), "=r"(r3) : "r"(addr));
}

__device__ __forceinline__ void cpa16(uint32_t dst, const void* src, int sz) {
    asm volatile("cp.async.cg.shared.global [%0], [%1], 16, %2;\n"
                 :: "r"(dst), "l"(src), "r"(sz));
}
__device__ __forceinline__ void cpa_commit() {
    asm volatile("cp.async.commit_group;\n");
}
__device__ __forceinline__ void cpa_wait0() {
    asm volatile("cp.async.wait_group 0;\n" ::: "memory");
}
__device__ __forceinline__ void cpa_wait1() {
    asm volatile("cp.async.wait_group 1;\n" ::: "memory");
}

// ---------------- fused flash attention ----------------
constexpr int FQS = 132;
constexpr int FKS = 72;
constexpr int FVS = 136;
constexpr int FPS = 68;
constexpr int F_K0 = 128 * FQS;
constexpr int F_V0 = F_K0 + 2 * 128 * FKS;
constexpr int F_P0 = F_V0 + 64 * FVS;
constexpr int FSMEM = (F_P0 + 128 * FPS) * 4;

__global__ __launch_bounds__(256, 1) void flash_kernel() {
    extern __shared__ float fs[];
    const int tid = threadIdx.x, lane = tid & 31, wid = tid >> 5;
    const int z  = blockIdx.z;
    const int qt = 15 - blockIdx.y;
    const int bb = z >> 4, hh = z & 15;
    const int q0 = qt * 128;
    const int nc = 2 * qt + 2;
    const float scl = 0.08838834764831845f;

    const uint32_t sb = (uint32_t)__cvta_generic_to_shared(fs);
    const uint32_t sQ = sb, sK = sb + F_K0 * 4, sV = sb + F_V0 * 4, sP = sb + F_P0 * 4;
    float* Ksf = fs + F_K0;
    float* Vsf = fs + F_V0;
    float* Psf = fs + F_P0;

    const float* Qg  = g_q + ((size_t)bb * Sc + q0) * 2048 + hh * 128;
    const float* KTg = g_kT + (size_t)(bb * 2 + (hh >> 3)) * 128 * Sc;
    const float* Vg  = g_v + (size_t)bb * Sc * 256 + (hh >> 3) * 128;

    {
        const int r = tid >> 1, hf = tid & 1;
#pragma unroll
        for (int c = 0; c < 16; c++)
            cpa16(sQ + (uint32_t)(r * FQS + hf * 64 + c * 4) * 4,
                  Qg + (size_t)r * 2048 + hf * 64 + c * 4, 16);
#pragma unroll
        for (int c = 0; c < 8; c++)
            cpa16(sK + (uint32_t)(r * FKS + hf * 32 + c * 4) * 4,
                  KTg + (size_t)r * Sc + hf * 32 + c * 4, 16);
    }
    cpa_commit();

    float oacc[16][4];
#pragma unroll
    for (int j = 0; j < 16; j++)
#pragma unroll
        for (int e = 0; e < 4; e++) oacc[j][e] = 0.f;
    float mrow[2] = {-1e30f, -1e30f};
    float lrow[2] = {0.f, 0.f};

    const int wm = wid * 16;
    const int kq = lane & 3, cbq = lane >> 2;
    const int lrw = lane & 15, lcl = (lane >> 4) << 2;

    for (int c = 0; c < nc; c++) {
        const int kc0 = c * 64;
        const int kbuf = c & 1;
        cpa_wait0();
        __syncthreads();

        {
            const int r = tid >> 2, q4 = tid & 3;
#pragma unroll
            for (int cc = 0; cc < 8; cc++)
                cpa16(sV + (uint32_t)(r * FVS + q4 * 32 + cc * 4) * 4,
                      Vg + (size_t)(kc0 + r) * 256 + q4 * 32 + cc * 4, 16);
        }
        cpa_commit();
        const bool more = (c + 1) < nc;
        if (more) {
            const int r = tid >> 1, hf = tid & 1;
            const int nb = (c + 1) & 1;
#pragma unroll
            for (int cc = 0; cc < 8; cc++)
                cpa16(sK + (uint32_t)((nb * 128 + r) * FKS + hf * 32 + cc * 4) * 4,
                      KTg + (size_t)r * Sc + (kc0 + 64) + hf * 32 + cc * 4, 16);
            cpa_commit();
        }

        float sacc[8][4];
#pragma unroll
        for (int j = 0; j < 8; j++)
#pragma unroll
            for (int e = 0; e < 4; e++) sacc[j][e] = 0.f;

#pragma unroll
        for (int ks = 0; ks < 16; ks++) {
            uint32_t af[4];
            ldsm4(af[0], af[1], af[2], af[3],
                  sQ + (uint32_t)((wm + lrw) * FQS + ks * 8 + lcl) * 4);
            const float* kb = Ksf + (size_t)kbuf * 128 * FKS;
#pragma unroll
            for (int j = 0; j < 8; j++) {
                uint32_t bf[2];
                bf[0] = __float_as_uint(kb[(ks * 8 + kq) * FKS + cbq + j * 8]);
                bf[1] = __float_as_uint(kb[(ks * 8 + kq + 4) * FKS + cbq + j * 8]);
                mma_tf32(sacc[j], af, bf);
            }
        }

#pragma unroll
        for (int mi = 0; mi < 2; mi++) {
            const int rg = q0 + wm + (lane >> 2) + mi * 8;
            float mx = -1e30f;
#pragma unroll
            for (int j = 0; j < 8; j++)
#pragma unroll
                for (int e = 0; e < 2; e++) {
                    const int cg = kc0 + (lane & 3) * 2 + j * 8 + e;
                    float v = (cg <= rg) ? sacc[j][mi * 2 + e] * scl : -1e30f;
                    sacc[j][mi * 2 + e] = v;
                    mx = fmaxf(mx, v);
                }
            mx = fmaxf(mx, __shfl_xor_sync(0xffffffffu, mx, 1));
            mx = fmaxf(mx, __shfl_xor_sync(0xffffffffu, mx, 2));
            const float newm = fmaxf(mrow[mi], mx);
            const float sc2 = expf(mrow[mi] - newm);
            float rs = 0.f;
#pragma unroll
            for (int j = 0; j < 8; j++)
#pragma unroll
                for (int e = 0; e < 2; e++) {
                    const float p = expf(sacc[j][mi * 2 + e] - newm);
                    sacc[j][mi * 2 + e] = p;
                    rs += p;
                }
            rs += __shfl_xor_sync(0xffffffffu, rs, 1);
            rs += __shfl_xor_sync(0xffffffffu, rs, 2);
            lrow[mi] = lrow[mi] * sc2 + rs;
            mrow[mi] = newm;
#pragma unroll
            for (int j = 0; j < 16; j++) {
                oacc[j][mi * 2 + 0] *= sc2;
                oacc[j][mi * 2 + 1] *= sc2;
            }
            const int pr = wm + (lane >> 2) + mi * 8;
#pragma unroll
            for (int j = 0; j < 8; j++) {
                Psf[pr * FPS + (lane & 3) * 2 + j * 8 + 0] = tf32r(sacc[j][mi * 2 + 0]);
                Psf[pr * FPS + (lane & 3) * 2 + j * 8 + 1] = tf32r(sacc[j][mi * 2 + 1]);
            }
        }

        if (more) cpa_wait1(); else cpa_wait0();
        __syncthreads();

#pragma unroll
        for (int ks = 0; ks < 8; ks++) {
            uint32_t af[4];
            ldsm4(af[0], af[1], af[2], af[3],
                  sP + (uint32_t)((wm + lrw) * FPS + ks * 8 + lcl) * 4);
#pragma unroll
            for (int j = 0; j < 16; j++) {
                uint32_t bf[2];
                bf[0] = __float_as_uint(Vsf[(ks * 8 + kq) * FVS + cbq + j * 8]);
                bf[1] = __float_as_uint(Vsf[(ks * 8 + kq + 4) * FVS + cbq + j * 8]);
                mma_tf32(oacc[j], af, bf);
            }
        }
        __syncthreads();
    }

#pragma unroll
    for (int mi = 0; mi < 2; mi++) {
        const float inv = 1.f / lrow[mi];
        const int rg = q0 + wm + (lane >> 2) + mi * 8;
        float* dst = g_ao + ((size_t)bb * Sc + rg) * 2048 + hh * 128;
#pragma unroll
        for (int j = 0; j < 16; j++) {
            dst[(lane & 3) * 2 + j * 8 + 0] = tf32r(oacc[j][mi * 2 + 0] * inv);
            dst[(lane & 3) * 2 + j * 8 + 1] = tf32r(oacc[j][mi * 2 + 1] * inv);
        }
    }
}

// ---------------- tf32 GEMM: 3-stage cp.async + ldmatrix-A, single-sync loop ----------------
enum GMode { GM_QKV, GM_O, GM_MG, GM_MU, GM_MD, GM_SG, GM_SU, GM_SD };

constexpr int AST = 20;
constexpr int BST = 136;
constexpr int A_STG = 128 * AST;
constexpr int B_STG = 16 * BST;
constexpr int GSMEM = 3 * (A_STG + B_STG) * 4;

template<int MODE>
__global__ __launch_bounds__(128, 2) void gemm_kernel(const float* __restrict__ extra) {
    extern __shared__ float smem[];
    constexpr int Kv = (MODE==GM_MD) ? IM : (MODE==GM_SD) ? ISH : 2048;

    const int tid = threadIdx.x;
    const int z   = blockIdx.z;
    const int m0  = blockIdx.y * 128, n0 = blockIdx.x * 128;

    int Mz;
    if (MODE==GM_MG || MODE==GM_MU || MODE==GM_MD) Mz = g_cnt[z];
    else Mz = Tc;
    if (m0 >= Mz) return;

    const float* A; const float* Bp; int lda, ldb;
    if (MODE==GM_QKV) {
        A = g_h; lda = Hc; Bp = g_wr + OFF_QKV; ldb = NQKV;
    } else if (MODE==GM_O) {
        A = g_ao; lda = 2048; Bp = g_wr + OFF_WO; ldb = 2048;
    } else if (MODE==GM_MG) {
        A = g_t2r; lda = 2048; Bp = g_wr + OFF_WG + (size_t)z * 2048 * IM; ldb = IM;
    } else if (MODE==GM_MU) {
        A = g_t2r; lda = 2048; Bp = g_wr + OFF_WU + (size_t)z * 2048 * IM; ldb = IM;
    } else if (MODE==GM_MD) {
        A = g_mg + (size_t)z * Tc * IM; lda = IM;
        Bp = g_wr + OFF_WD + (size_t)z * IM * 2048; ldb = 2048;
    } else if (MODE==GM_SG) {
        A = g_t2r; lda = 2048; Bp = g_wr + OFF_SWG; ldb = ISH;
    } else if (MODE==GM_SU) {
        A = g_t2r; lda = 2048; Bp = g_wr + OFF_SWU; ldb = ISH;
    } else { // GM_SD
        A = g_sgv; lda = ISH; Bp = g_wr + OFF_SWD; ldb = 2048;
    }

    float* Asf = smem;
    float* Bsf = smem + 3 * A_STG;

    float acc[4][8][4];
#pragma unroll
    for (int i = 0; i < 4; i++)
#pragma unroll
        for (int j = 0; j < 8; j++)
#pragma unroll
            for (int r = 0; r < 4; r++) acc[i][j][r] = 0.f;

    const int lane = tid & 31, wid = tid >> 5;
    const int wm = (wid >> 1) * 64;
    const int wn = (wid & 1) * 64;

    const int lm = tid;
    const int agl = m0 + lm;
    const bool aval = agl < Mz;
    const float* arp;
    if (MODE==GM_MG || MODE==GM_MU)
        arp = A + (size_t)(aval ? g_list[z * Tc + agl] : 0) * lda;
    else
        arp = A + (size_t)(aval ? agl : 0) * lda;
    const int asz = aval ? 16 : 0;
    const int arot = (lm >> 3) & 3;

    const int bw = tid >> 5;
    const int bn = (tid & 31) * 4;
    const float* bbase = Bp + n0;

    const int nt = Kv / 16;

    const uint32_t sA = (uint32_t)__cvta_generic_to_shared(Asf);
    const uint32_t sB = (uint32_t)__cvta_generic_to_shared(Bsf);

    auto load_stage = [&](int s, int k0) {
#pragma unroll
        for (int c = 0; c < 4; c++) {
            const int cc = (c + arot) & 3;
            cpa16(sA + (uint32_t)((s * 128 + lm) * AST + cc * 4) * 4, arp + k0 + cc * 4, asz);
        }
#pragma unroll
        for (int c = 0; c < 4; c++) {
            const int k = c * 4 + bw;
            cpa16(sB + (uint32_t)((s * 16 + k) * BST + bn) * 4,
                  bbase + (size_t)(k0 + k) * ldb + bn, 16);
        }
    };

    load_stage(0, 0);
    cpa_commit();
    if (nt > 1) load_stage(1, 16);
    cpa_commit();

    const int cb = wn + (lane >> 2);
    const int kq = lane & 3;
    const int lrow = lane & 15;
    const int lcol = (lane >> 4) << 2;

    int cur = 0, n2 = 2;
    for (int t = 0; t < nt; t++) {
        cpa_wait1();
        __syncthreads();
        if (t + 2 < nt) load_stage(n2, (t + 2) * 16);
        cpa_commit();

#pragma unroll
        for (int ks = 0; ks < 2; ks++) {
            const int klo = ks * 8;
            const int kk = klo + kq;
            uint32_t af[4][4], bf[8][2];
#pragma unroll
            for (int i = 0; i < 4; i++) {
                const uint32_t addr = sA +
                    (uint32_t)((cur * 128 + wm + i * 16 + lrow) * AST + klo + lcol) * 4;
                ldsm4(af[i][0], af[i][1], af[i][2], af[i][3], addr);
            }
#pragma unroll
            for (int j = 0; j < 8; j++) {
                bf[j][0] = __float_as_uint(Bsf[(cur * 16 + kk) * BST + cb + j * 8]);
                bf[j][1] = __float_as_uint(Bsf[(cur * 16 + kk + 4) * BST + cb + j * 8]);
            }
#pragma unroll
            for (int i = 0; i < 4; i++)
#pragma unroll
                for (int j = 0; j < 8; j++)
                    mma_tf32(acc[i][j], af[i], bf[j]);
        }
        cur = (cur == 2) ? 0 : cur + 1;
        n2  = (n2  == 2) ? 0 : n2  + 1;
    }

    // ---------------- epilogues ----------------
#pragma unroll
    for (int i = 0; i < 4; i++) {
#pragma unroll
        for (int rr = 0; rr < 2; rr++) {
            const int r = m0 + wm + i * 16 + (lane >> 2) + rr * 8;
            if (r >= Mz) continue;
            if (MODE==GM_QKV) {
#pragma unroll
                for (int j = 0; j < 8; j++) {
                    const int c = n0 + wn + j * 8 + (lane & 3) * 2;
                    float v0 = acc[i][j][rr * 2 + 0] + g_bqkv[c];
                    float v1 = acc[i][j][rr * 2 + 1] + g_bqkv[c + 1];
                    if (c < 2048) {
                        g_q[(size_t)r * 2048 + c]     = v0;
                        g_q[(size_t)r * 2048 + c + 1] = v1;
                    } else if (c < 2304) {
                        g_k[(size_t)r * 256 + c - 2048]     = v0;
                        g_k[(size_t)r * 256 + c - 2048 + 1] = v1;
                    } else {
                        g_v[(size_t)r * 256 + c - 2304]     = tf32r(v0);
                        g_v[(size_t)r * 256 + c - 2304 + 1] = tf32r(v1);
                    }
                }
            } else if (MODE==GM_MD) {
                const int tok = g_list[z * Tc + r];
                const float w = g_dw[tok * Ec + z];
                float* dst = g_moe + (size_t)tok * 2048;
#pragma unroll
                for (int j = 0; j < 8; j++) {
                    const int c = n0 + wn + j * 8 + (lane & 3) * 2;
                    atomicAdd(dst + c,     acc[i][j][rr * 2 + 0] * w);
                    atomicAdd(dst + c + 1, acc[i][j][rr * 2 + 1] * w);
                }
            } else {
                float* Cp; int ldc; const float* res = nullptr;
                if (MODE==GM_O)       { Cp = g_x;  ldc = 2048; res = extra; }
                else if (MODE==GM_MG) { Cp = g_mg + (size_t)z * Tc * IM; ldc = IM; }
                else if (MODE==GM_MU) { Cp = g_mu + (size_t)z * Tc * IM; ldc = IM; }
                else if (MODE==GM_SG) { Cp = g_sgv; ldc = ISH; }
                else if (MODE==GM_SU) { Cp = g_suv; ldc = ISH; }
                else                  { Cp = g_sh;  ldc = 2048; }
                const size_t rowoff = (size_t)r * ldc;
#pragma unroll
                for (int j = 0; j < 8; j++) {
                    const int c = n0 + wn + j * 8 + (lane & 3) * 2;
                    float v0 = acc[i][j][rr * 2 + 0];
                    float v1 = acc[i][j][rr * 2 + 1];
                    if (res)  { v0 += res[rowoff + c]; v1 += res[rowoff + c + 1]; }
                    Cp[rowoff + c]     = v0;
                    Cp[rowoff + c + 1] = v1;
                }
            }
        }
    }
}

// ---------------- launch ----------------
extern "C" void kernel_launch(void* const* d_in, const int* in_sizes, int n_in,
                              void* d_out, int out_size) {
    (void)in_sizes; (void)n_in; (void)out_size;
    const float* x0  = (const float*)d_in[0];
    const float* ln1 = (const float*)d_in[1];
    const float* wq  = (const float*)d_in[2];
    const float* bq  = (const float*)d_in[3];
    const float* wk  = (const float*)d_in[4];
    const float* bk  = (const float*)d_in[5];
    const float* wv  = (const float*)d_in[6];
    const float* bv  = (const float*)d_in[7];
    const float* wo  = (const float*)d_in[8];
    const float* ln2 = (const float*)d_in[9];
    const float* rw  = (const float*)d_in[10];
    const float* wg  = (const float*)d_in[11];
    const float* wu  = (const float*)d_in[12];
    const float* wd  = (const float*)d_in[13];
    const float* swg = (const float*)d_in[14];
    const float* swu = (const float*)d_in[15];
    const float* swd = (const float*)d_in[16];
    const float* sgw = (const float*)d_in[17];
    float* out = (float*)d_out;

    cudaFuncSetAttribute(gemm_kernel<GM_QKV>, cudaFuncAttributeMaxDynamicSharedMemorySize, GSMEM);
    cudaFuncSetAttribute(gemm_kernel<GM_O>,   cudaFuncAttributeMaxDynamicSharedMemorySize, GSMEM);
    cudaFuncSetAttribute(gemm_kernel<GM_MG>,  cudaFuncAttributeMaxDynamicSharedMemorySize, GSMEM);
    cudaFuncSetAttribute(gemm_kernel<GM_MU>,  cudaFuncAttributeMaxDynamicSharedMemorySize, GSMEM);
    cudaFuncSetAttribute(gemm_kernel<GM_MD>,  cudaFuncAttributeMaxDynamicSharedMemorySize, GSMEM);
    cudaFuncSetAttribute(gemm_kernel<GM_SG>,  cudaFuncAttributeMaxDynamicSharedMemorySize, GSMEM);
    cudaFuncSetAttribute(gemm_kernel<GM_SU>,  cudaFuncAttributeMaxDynamicSharedMemorySize, GSMEM);
    cudaFuncSetAttribute(gemm_kernel<GM_SD>,  cudaFuncAttributeMaxDynamicSharedMemorySize, GSMEM);
    cudaFuncSetAttribute(flash_kernel,        cudaFuncAttributeMaxDynamicSharedMemorySize, FSMEM);

    auto b4 = [](size_t n4) { return (unsigned)((n4 + 255) / 256); };

    // QKV interleaved into [2048][2560] (float4 granularity)
    round_copy_str_kernel<<<b4((size_t)2048*512), 256>>>(wq, 2048*512, 512, NQKV, 0);
    round_copy_str_kernel<<<b4((size_t)2048*64),  256>>>(wk, 2048*64,  64,  NQKV, 2048);
    round_copy_str_kernel<<<b4((size_t)2048*64),  256>>>(wv, 2048*64,  64,  NQKV, 2304);
    bias_concat_kernel<<<10, 256>>>(bq, bk, bv);
    round_copy_kernel<OFF_WO ><<<b4((size_t)2048*512),    256>>>(wo,  2048*512);
    round_copy_kernel<OFF_WG ><<<b4((size_t)Ec*2048*IM/4),256>>>(wg,  Ec*2048*IM/4);
    round_copy_kernel<OFF_WU ><<<b4((size_t)Ec*2048*IM/4),256>>>(wu,  Ec*2048*IM/4);
    round_copy_kernel<OFF_WD ><<<b4((size_t)Ec*IM*512),   256>>>(wd,  Ec*IM*512);
    round_copy_kernel<OFF_SWG><<<b4((size_t)2048*ISH/4),  256>>>(swg, 2048*ISH/4);
    round_copy_kernel<OFF_SWU><<<b4((size_t)2048*ISH/4),  256>>>(swu, 2048*ISH/4);
    round_copy_kernel<OFF_SWD><<<b4((size_t)ISH*512),     256>>>(swd, ISH*512);

    clear_cnt_kernel<<<1, 32>>>();
    clear_moe_kernel<<<(Tc * Hc) / 1024, 256>>>();

    // attention
    rmsnorm_kernel<0><<<Tc, 256>>>(x0, ln1);
    gemm_kernel<GM_QKV><<<dim3(20, 32, 1), 128, GSMEM>>>(nullptr);
    rope_kernel<<<dim3(Tc, NQc + NKVc), 64>>>();
    kT_kernel<<<(Bc * NKVc * DHc * Sc) / 256, 256>>>();
    flash_kernel<<<dim3(1, 16, 32), 256, FSMEM>>>();
    gemm_kernel<GM_O><<<dim3(16, 32, 1), 128, GSMEM>>>(x0);

    // MoE block
    rmsnorm_kernel<1><<<Tc, 256>>>(nullptr, ln2);
    router_kernel<<<Tc / 8, 256>>>(rw);
    gemm_kernel<GM_MG><<<dim3(11, 32, 8), 128, GSMEM>>>(nullptr);
    gemm_kernel<GM_MU><<<dim3(11, 32, 8), 128, GSMEM>>>(nullptr);
    moe_act_kernel<<<dim3(2, Tc, 8), 256>>>();
    gemm_kernel<GM_MD><<<dim3(16, 32, 8), 128, GSMEM>>>(nullptr);

    // shared expert
    gemm_kernel<GM_SG><<<dim3(44, 32, 1), 128, GSMEM>>>(nullptr);
    gemm_kernel<GM_SU><<<dim3(44, 32, 1), 128, GSMEM>>>(nullptr);
    shared_act_kernel<<<(size_t)(Tc) * ISH / 1024, 256>>>();
    sgate_kernel<<<Tc / 8, 256>>>(sgw);
    gemm_kernel<GM_SD><<<dim3(16, 32, 1), 128, GSMEM>>>(nullptr);

    final_kernel<<<(Tc * Hc) / 1024, 256>>>(out);
}

// round 16
// speedup vs baseline: 2.3920x; 1.0226x over previous
#include <cuda_runtime.h>
#include <math.h>
#include <stdint.h>

// ---------------- problem constants ----------------
constexpr int Bc   = 2;
constexpr int Sc   = 2048;
constexpr int Hc   = 2048;
constexpr int Tc   = Bc * Sc;      // 4096 tokens
constexpr int Ec   = 8;
constexpr int IM   = 1408;
constexpr int ISH  = 5632;
constexpr int NQc  = 16;
constexpr int NKVc = 2;
constexpr int DHc  = 128;
constexpr float EPSc = 1e-5f;
constexpr int NQKV = 2560;         // 2048 (Q) + 256 (K) + 256 (V)

// rounded-weight scratch offsets
constexpr size_t OFF_QKV  = 0;                              // [2048][2560]
constexpr size_t OFF_WO   = OFF_QKV  + (size_t)2048 * NQKV;
constexpr size_t OFF_WGU  = OFF_WO   + (size_t)2048 * 2048;  // [E][2048][2816] gate/up interleaved
constexpr size_t OFF_WD   = OFF_WGU  + (size_t)Ec * 2048 * 2 * IM;
constexpr size_t OFF_SWGU = OFF_WD   + (size_t)Ec * IM * 2048; // [2048][11264] interleaved
constexpr size_t OFF_SWD  = OFF_SWGU + (size_t)2048 * 2 * ISH;
constexpr size_t WR_TOT   = OFF_SWD  + (size_t)ISH * 2048;

// ---------------- scratch (device globals; no allocations allowed) ----------------
__device__ float g_wr [WR_TOT];                      // tf32-rounded weights
__device__ float g_bqkv[NQKV];                       // concatenated q/k/v biases
__device__ float g_h  [(size_t)Tc * Hc];
__device__ float g_q  [(size_t)Tc * NQc * DHc];
__device__ float g_k  [(size_t)Tc * NKVc * DHc];
__device__ float g_v  [(size_t)Tc * NKVc * DHc];
__device__ float g_kT [(size_t)Bc * NKVc * DHc * Sc];
__device__ float g_ao [(size_t)Tc * Hc];
__device__ float g_x  [(size_t)Tc * Hc];
__device__ float g_t2 [(size_t)Tc * Hc];             // exact (router/sgate)
__device__ float g_t2r[(size_t)Tc * Hc];             // tf32-rounded (GEMM A)
__device__ float g_dw [Tc * Ec];
__device__ int   g_cnt[Ec];
__device__ int   g_list[Ec * Tc];
__device__ float g_mg [(size_t)Ec * Tc * IM];        // activated expert hidden
__device__ float g_moe[(size_t)Tc * Hc];
__device__ float g_sgv[(size_t)Tc * ISH];            // activated shared hidden
__device__ float g_sh [(size_t)Tc * Hc];
__device__ float g_sgate[Tc];

__device__ __forceinline__ float tf32r(float x) {
    uint32_t u;
    asm("cvt.rna.tf32.f32 %0, %1;" : "=r"(u) : "f"(x));
    return __uint_as_float(u);
}
__device__ __forceinline__ float4 tf32r4(float4 v) {
    v.x = tf32r(v.x); v.y = tf32r(v.y); v.z = tf32r(v.z); v.w = tf32r(v.w);
    return v;
}
__device__ __forceinline__ float silu(float x) {
    return x / (1.f + expf(-x));
}

// ---------------- weight rounding (float4) ----------------
template<size_t OFF>
__global__ void round_copy_kernel(const float* __restrict__ src, int n4) {
    const int i = blockIdx.x * 256 + threadIdx.x;
    if (i < n4)
        ((float4*)(g_wr + OFF))[i] = tf32r4(((const float4*)src)[i]);
}

// interleave two sources pairwise: out4[s2] = {a.x, b.x, a.y, b.y}
template<size_t OFF>
__global__ void round_ilv_kernel(const float* __restrict__ srcA,
                                 const float* __restrict__ srcB, int n2) {
    const int i = blockIdx.x * 256 + threadIdx.x;
    if (i < n2) {
        const float2 a = ((const float2*)srcA)[i];
        const float2 b = ((const float2*)srcB)[i];
        float4 o;
        o.x = tf32r(a.x); o.y = tf32r(b.x);
        o.z = tf32r(a.y); o.w = tf32r(b.y);
        ((float4*)(g_wr + OFF))[i] = o;
    }
}

// strided (float4): QKV interleaved layout
__global__ void round_copy_str_kernel(const float* __restrict__ src, int n4,
                                      int srcN4, int ldDst, int colOff) {
    const int i = blockIdx.x * 256 + threadIdx.x;
    if (i < n4) {
        const int k = i / srcN4, c4 = i % srcN4;
        const float4 v = tf32r4(((const float4*)src)[i]);
        *(float4*)(g_wr + OFF_QKV + (size_t)k * ldDst + colOff + c4 * 4) = v;
    }
}

__global__ void bias_concat_kernel(const float* __restrict__ bq,
                                   const float* __restrict__ bk,
                                   const float* __restrict__ bv) {
    const int i = blockIdx.x * 256 + threadIdx.x;
    if (i < 2048)       g_bqkv[i] = bq[i];
    else if (i < 2304)  g_bqkv[i] = bk[i - 2048];
    else if (i < NQKV)  g_bqkv[i] = bv[i - 2304];
}

// ---------------- small kernels ----------------
__global__ void clear_cnt_kernel() {
    if (threadIdx.x < Ec) g_cnt[threadIdx.x] = 0;
}
__global__ void clear_moe_kernel() {
    ((float4*)g_moe)[(size_t)blockIdx.x * 256 + threadIdx.x] =
        make_float4(0.f, 0.f, 0.f, 0.f);
}

template<int PHASE>
__global__ void rmsnorm_kernel(const float* __restrict__ xin,
                               const float* __restrict__ scale) {
    __shared__ float red[256];
    const int row = blockIdx.x;
    const float* x = (PHASE == 0) ? (xin + (size_t)row * Hc) : (g_x + (size_t)row * Hc);
    const int tid = threadIdx.x;
    float4 v[2];
    float s = 0.f;
#pragma unroll
    for (int g = 0; g < 2; g++) {
        v[g] = ((const float4*)x)[tid + g * 256];
        s += v[g].x * v[g].x + v[g].y * v[g].y + v[g].z * v[g].z + v[g].w * v[g].w;
    }
    red[tid] = s; __syncthreads();
    for (int o = 128; o > 0; o >>= 1) {
        if (tid < o) red[tid] += red[tid + o];
        __syncthreads();
    }
    const float inv = rsqrtf(red[0] / (float)Hc + EPSc);
#pragma unroll
    for (int g = 0; g < 2; g++) {
        const int j = tid + g * 256;
        const float4 sc4 = ((const float4*)scale)[j];
        float4 o4;
        o4.x = v[g].x * inv * sc4.x;
        o4.y = v[g].y * inv * sc4.y;
        o4.z = v[g].z * inv * sc4.z;
        o4.w = v[g].w * inv * sc4.w;
        if (PHASE == 0) {
            ((float4*)(g_h + (size_t)row * Hc))[j] = tf32r4(o4);
        } else {
            ((float4*)(g_t2  + (size_t)row * Hc))[j] = o4;
            ((float4*)(g_t2r + (size_t)row * Hc))[j] = tf32r4(o4);
        }
    }
}

__global__ void rope_kernel() {
    const int tok  = blockIdx.x;
    const int head = blockIdx.y;
    const int j    = threadIdx.x;         // 0..63
    const int s    = tok & (Sc - 1);
    const float inv = powf(10000.f, -(float)(2 * j) / 128.f);
    const float ang = (float)s * inv;
    float si, c;
    sincosf(ang, &si, &c);
    float* p = (head < NQc) ? (g_q + (size_t)tok * (NQc * DHc) + head * DHc)
                            : (g_k + (size_t)tok * (NKVc * DHc) + (head - NQc) * DHc);
    const float x1 = p[j], x2 = p[j + 64];
    p[j]      = tf32r(x1 * c - x2 * si);
    p[j + 64] = tf32r(x2 * c + x1 * si);
}

__global__ void kT_kernel() {
    const int i  = blockIdx.x * 256 + threadIdx.x;
    const int s  = i & (Sc - 1);
    const int d  = (i >> 11) & 127;
    const int bk = i >> 18;
    g_kT[i] = g_k[((size_t)((bk >> 1) * Sc + s)) * (NKVc * DHc) + (bk & 1) * DHc + d];
}

__global__ void router_kernel(const float* __restrict__ rw) {
    const int tok  = blockIdx.x * 8 + (threadIdx.x >> 5);
    const int lane = threadIdx.x & 31;
    const float* tr = g_t2 + (size_t)tok * Hc;
    float acc[8];
#pragma unroll
    for (int e = 0; e < 8; e++) acc[e] = 0.f;
    for (int h = lane; h < Hc; h += 32) {
        const float tv = tr[h];
        const float* rp = rw + h * 8;
#pragma unroll
        for (int e = 0; e < 8; e++) acc[e] += tv * rp[e];
    }
#pragma unroll
    for (int e = 0; e < 8; e++)
        for (int o = 16; o; o >>= 1) acc[e] += __shfl_xor_sync(0xffffffffu, acc[e], o);
    if (lane == 0) {
        float m = acc[0];
        for (int e = 1; e < 8; e++) m = fmaxf(m, acc[e]);
        float p[8], s = 0.f;
        for (int e = 0; e < 8; e++) { p[e] = expf(acc[e] - m); s += p[e]; }
        for (int e = 0; e < 8; e++) p[e] /= s;
        bool used[8] = {false,false,false,false,false,false,false,false};
        int isel[4]; float wsel[4]; float tsum = 0.f;
        for (int kk = 0; kk < 4; kk++) {
            int best = 0; float bv = -1.f;
            for (int e = 0; e < 8; e++)
                if (!used[e] && p[e] > bv) { bv = p[e]; best = e; }
            used[best] = true; isel[kk] = best; wsel[kk] = bv; tsum += bv;
        }
        float outw[8] = {0,0,0,0,0,0,0,0};
        for (int kk = 0; kk < 4; kk++) outw[isel[kk]] = wsel[kk] / tsum;
        for (int e = 0; e < 8; e++) g_dw[tok * 8 + e] = outw[e];
        for (int kk = 0; kk < 4; kk++) {
            const int pos = atomicAdd(&g_cnt[isel[kk]], 1);
            g_list[isel[kk] * Tc + pos] = tok;
        }
    }
}

__global__ void sgate_kernel(const float* __restrict__ sgw) {
    const int tok  = blockIdx.x * 8 + (threadIdx.x >> 5);
    const int lane = threadIdx.x & 31;
    const float* tr = g_t2 + (size_t)tok * Hc;
    float s = 0.f;
    for (int h = lane; h < Hc; h += 32) s += tr[h] * sgw[h];
    for (int o = 16; o; o >>= 1) s += __shfl_xor_sync(0xffffffffu, s, o);
    if (lane == 0) g_sgate[tok] = 1.f / (1.f + expf(-s));
}

__global__ void final_kernel(float* __restrict__ out) {
    const size_t i4 = (size_t)blockIdx.x * 256 + threadIdx.x;
    const int row = (int)(i4 >> 9);
    const float sg = g_sgate[row];
    const float4 x4 = ((const float4*)g_x)[i4];
    const float4 m4 = ((const float4*)g_moe)[i4];
    const float4 s4 = ((const float4*)g_sh)[i4];
    float4 o4;
    o4.x = x4.x + m4.x + sg * s4.x;
    o4.y = x4.y + m4.y + sg * s4.y;
    o4.z = x4.z + m4.z + sg * s4.z;
    o4.w = x4.w + m4.w + sg * s4.w;
    ((float4*)out)[i4] = o4;
}

// ---------------- shared PTX helpers ----------------
__device__ __forceinline__ void mma_tf32(float* c, const uint32_t* a, const uint32_t* b) {
    asm volatile(
        "mma.sync.aligned.m16n8k8.row.col.f32.tf32.tf32.f32 "
        "{%0,%1,%2,%3}, {%4,%5,%6,%7}, {%8,%9}, {%0,%1,%2,%3};"
        : "+f"(c[0]), "+f"(c[1]), "+f"(c[2]), "+f"(c[3])
        : "r"(a[0]), "r"(a[1]), "r"(a[2]), "r"(a[3]), "r"(b[0]), "r"(b[1]));
}

__device__ __forceinline__ void ldsm4(uint32_t& r0, uint32_t& r1, uint32_t& r2, uint32_t& r3,
                                      uint32_t addr) {
    asm volatile("ldmatrix.sync.aligned.m8n8.x4.shared.b16 {%0,%1,%2,%3}, [%4];"
                 : "=r"(r0), "=r"(r1), "=r"(r2), "=r"(r3) : "r"(addr));
}

__device__ __forceinline__ void cpa16(uint32_t dst, const void* src, int sz) {
    asm volatile("cp.async.cg.shared.global [%0], [%1], 16, %2;\n"
                 :: "r"(dst), "l"(src), "r"(sz));
}
__device__ __forceinline__ void cpa_commit() {
    asm volatile("cp.async.commit_group;\n");
}
__device__ __forceinline__ void cpa_wait0() {
    asm volatile("cp.async.wait_group 0;\n" ::: "memory");
}
__device__ __forceinline__ void cpa_wait1() {
    asm volatile("cp.async.wait_group 1;\n" ::: "memory");
}

// ---------------- fused flash attention ----------------
constexpr int FQS = 132;
constexpr int FKS = 72;
constexpr int FVS = 136;
constexpr int FPS = 68;
constexpr int F_K0 = 128 * FQS;
constexpr int F_V0 = F_K0 + 2 * 128 * FKS;
constexpr int F_P0 = F_V0 + 64 * FVS;
constexpr int FSMEM = (F_P0 + 128 * FPS) * 4;

__global__ __launch_bounds__(256, 1) void flash_kernel() {
    extern __shared__ float fs[];
    const int tid = threadIdx.x, lane = tid & 31, wid = tid >> 5;
    const int z  = blockIdx.z;
    const int qt = 15 - blockIdx.y;
    const int bb = z >> 4, hh = z & 15;
    const int q0 = qt * 128;
    const int nc = 2 * qt + 2;
    const float scl = 0.08838834764831845f;

    const uint32_t sb = (uint32_t)__cvta_generic_to_shared(fs);
    const uint32_t sQ = sb, sK = sb + F_K0 * 4, sV = sb + F_V0 * 4, sP = sb + F_P0 * 4;
    float* Ksf = fs + F_K0;
    float* Vsf = fs + F_V0;
    float* Psf = fs + F_P0;

    const float* Qg  = g_q + ((size_t)bb * Sc + q0) * 2048 + hh * 128;
    const float* KTg = g_kT + (size_t)(bb * 2 + (hh >> 3)) * 128 * Sc;
    const float* Vg  = g_v + (size_t)bb * Sc * 256 + (hh >> 3) * 128;

    {
        const int r = tid >> 1, hf = tid & 1;
#pragma unroll
        for (int c = 0; c < 16; c++)
            cpa16(sQ + (uint32_t)(r * FQS + hf * 64 + c * 4) * 4,
                  Qg + (size_t)r * 2048 + hf * 64 + c * 4, 16);
#pragma unroll
        for (int c = 0; c < 8; c++)
            cpa16(sK + (uint32_t)(r * FKS + hf * 32 + c * 4) * 4,
                  KTg + (size_t)r * Sc + hf * 32 + c * 4, 16);
    }
    cpa_commit();

    float oacc[16][4];
#pragma unroll
    for (int j = 0; j < 16; j++)
#pragma unroll
        for (int e = 0; e < 4; e++) oacc[j][e] = 0.f;
    float mrow[2] = {-1e30f, -1e30f};
    float lrow[2] = {0.f, 0.f};

    const int wm = wid * 16;
    const int kq = lane & 3, cbq = lane >> 2;
    const int lrw = lane & 15, lcl = (lane >> 4) << 2;

    for (int c = 0; c < nc; c++) {
        const int kc0 = c * 64;
        const int kbuf = c & 1;
        cpa_wait0();
        __syncthreads();

        {
            const int r = tid >> 2, q4 = tid & 3;
#pragma unroll
            for (int cc = 0; cc < 8; cc++)
                cpa16(sV + (uint32_t)(r * FVS + q4 * 32 + cc * 4) * 4,
                      Vg + (size_t)(kc0 + r) * 256 + q4 * 32 + cc * 4, 16);
        }
        cpa_commit();
        const bool more = (c + 1) < nc;
        if (more) {
            const int r = tid >> 1, hf = tid & 1;
            const int nb = (c + 1) & 1;
#pragma unroll
            for (int cc = 0; cc < 8; cc++)
                cpa16(sK + (uint32_t)((nb * 128 + r) * FKS + hf * 32 + cc * 4) * 4,
                      KTg + (size_t)r * Sc + (kc0 + 64) + hf * 32 + cc * 4, 16);
            cpa_commit();
        }

        float sacc[8][4];
#pragma unroll
        for (int j = 0; j < 8; j++)
#pragma unroll
            for (int e = 0; e < 4; e++) sacc[j][e] = 0.f;

#pragma unroll
        for (int ks = 0; ks < 16; ks++) {
            uint32_t af[4];
            ldsm4(af[0], af[1], af[2], af[3],
                  sQ + (uint32_t)((wm + lrw) * FQS + ks * 8 + lcl) * 4);
            const float* kb = Ksf + (size_t)kbuf * 128 * FKS;
#pragma unroll
            for (int j = 0; j < 8; j++) {
                uint32_t bf[2];
                bf[0] = __float_as_uint(kb[(ks * 8 + kq) * FKS + cbq + j * 8]);
                bf[1] = __float_as_uint(kb[(ks * 8 + kq + 4) * FKS + cbq + j * 8]);
                mma_tf32(sacc[j], af, bf);
            }
        }

#pragma unroll
        for (int mi = 0; mi < 2; mi++) {
            const int rg = q0 + wm + (lane >> 2) + mi * 8;
            float mx = -1e30f;
#pragma unroll
            for (int j = 0; j < 8; j++)
#pragma unroll
                for (int e = 0; e < 2; e++) {
                    const int cg = kc0 + (lane & 3) * 2 + j * 8 + e;
                    float v = (cg <= rg) ? sacc[j][mi * 2 + e] * scl : -1e30f;
                    sacc[j][mi * 2 + e] = v;
                    mx = fmaxf(mx, v);
                }
            mx = fmaxf(mx, __shfl_xor_sync(0xffffffffu, mx, 1));
            mx = fmaxf(mx, __shfl_xor_sync(0xffffffffu, mx, 2));
            const float newm = fmaxf(mrow[mi], mx);
            const float sc2 = expf(mrow[mi] - newm);
            float rs = 0.f;
#pragma unroll
            for (int j = 0; j < 8; j++)
#pragma unroll
                for (int e = 0; e < 2; e++) {
                    const float p = expf(sacc[j][mi * 2 + e] - newm);
                    sacc[j][mi * 2 + e] = p;
                    rs += p;
                }
            rs += __shfl_xor_sync(0xffffffffu, rs, 1);
            rs += __shfl_xor_sync(0xffffffffu, rs, 2);
            lrow[mi] = lrow[mi] * sc2 + rs;
            mrow[mi] = newm;
#pragma unroll
            for (int j = 0; j < 16; j++) {
                oacc[j][mi * 2 + 0] *= sc2;
                oacc[j][mi * 2 + 1] *= sc2;
            }
            const int pr = wm + (lane >> 2) + mi * 8;
#pragma unroll
            for (int j = 0; j < 8; j++) {
                Psf[pr * FPS + (lane & 3) * 2 + j * 8 + 0] = tf32r(sacc[j][mi * 2 + 0]);
                Psf[pr * FPS + (lane & 3) * 2 + j * 8 + 1] = tf32r(sacc[j][mi * 2 + 1]);
            }
        }

        if (more) cpa_wait1(); else cpa_wait0();
        __syncthreads();

#pragma unroll
        for (int ks = 0; ks < 8; ks++) {
            uint32_t af[4];
            ldsm4(af[0], af[1], af[2], af[3],
                  sP + (uint32_t)((wm + lrw) * FPS + ks * 8 + lcl) * 4);
#pragma unroll
            for (int j = 0; j < 16; j++) {
                uint32_t bf[2];
                bf[0] = __float_as_uint(Vsf[(ks * 8 + kq) * FVS + cbq + j * 8]);
                bf[1] = __float_as_uint(Vsf[(ks * 8 + kq + 4) * FVS + cbq + j * 8]);
                mma_tf32(oacc[j], af, bf);
            }
        }
        __syncthreads();
    }

#pragma unroll
    for (int mi = 0; mi < 2; mi++) {
        const float inv = 1.f / lrow[mi];
        const int rg = q0 + wm + (lane >> 2) + mi * 8;
        float* dst = g_ao + ((size_t)bb * Sc + rg) * 2048 + hh * 128;
#pragma unroll
        for (int j = 0; j < 16; j++) {
            dst[(lane & 3) * 2 + j * 8 + 0] = tf32r(oacc[j][mi * 2 + 0] * inv);
            dst[(lane & 3) * 2 + j * 8 + 1] = tf32r(oacc[j][mi * 2 + 1] * inv);
        }
    }
}

// ---------------- tf32 GEMM: 3-stage cp.async + ldmatrix-A, single-sync loop ----------------
enum GMode { GM_QKV, GM_O, GM_MGU, GM_MD, GM_SGU, GM_SD };

constexpr int AST = 20;
constexpr int BST = 136;
constexpr int A_STG = 128 * AST;
constexpr int B_STG = 16 * BST;
constexpr int GSMEM = 3 * (A_STG + B_STG) * 4;

template<int MODE>
__global__ __launch_bounds__(128, 2) void gemm_kernel(const float* __restrict__ extra) {
    extern __shared__ float smem[];
    constexpr int Kv = (MODE==GM_MD) ? IM : (MODE==GM_SD) ? ISH : 2048;

    const int tid = threadIdx.x;
    const int z   = blockIdx.z;
    const int m0  = blockIdx.y * 128, n0 = blockIdx.x * 128;

    int Mz;
    if (MODE==GM_MGU || MODE==GM_MD) Mz = g_cnt[z];
    else Mz = Tc;
    if (m0 >= Mz) return;

    const float* A; const float* Bp; int lda, ldb;
    if (MODE==GM_QKV) {
        A = g_h; lda = Hc; Bp = g_wr + OFF_QKV; ldb = NQKV;
    } else if (MODE==GM_O) {
        A = g_ao; lda = 2048; Bp = g_wr + OFF_WO; ldb = 2048;
    } else if (MODE==GM_MGU) {
        A = g_t2r; lda = 2048; Bp = g_wr + OFF_WGU + (size_t)z * 2048 * 2 * IM; ldb = 2 * IM;
    } else if (MODE==GM_MD) {
        A = g_mg + (size_t)z * Tc * IM; lda = IM;
        Bp = g_wr + OFF_WD + (size_t)z * IM * 2048; ldb = 2048;
    } else if (MODE==GM_SGU) {
        A = g_t2r; lda = 2048; Bp = g_wr + OFF_SWGU; ldb = 2 * ISH;
    } else { // GM_SD
        A = g_sgv; lda = ISH; Bp = g_wr + OFF_SWD; ldb = 2048;
    }

    float* Asf = smem;
    float* Bsf = smem + 3 * A_STG;

    float acc[4][8][4];
#pragma unroll
    for (int i = 0; i < 4; i++)
#pragma unroll
        for (int j = 0; j < 8; j++)
#pragma unroll
            for (int r = 0; r < 4; r++) acc[i][j][r] = 0.f;

    const int lane = tid & 31, wid = tid >> 5;
    const int wm = (wid >> 1) * 64;
    const int wn = (wid & 1) * 64;

    const int lm = tid;
    const int agl = m0 + lm;
    const bool aval = agl < Mz;
    const float* arp;
    if (MODE==GM_MGU)
        arp = A + (size_t)(aval ? g_list[z * Tc + agl] : 0) * lda;
    else
        arp = A + (size_t)(aval ? agl : 0) * lda;
    const int asz = aval ? 16 : 0;
    const int arot = (lm >> 3) & 3;

    const int bw = tid >> 5;
    const int bn = (tid & 31) * 4;
    const float* bbase = Bp + n0;

    const int nt = Kv / 16;

    const uint32_t sA = (uint32_t)__cvta_generic_to_shared(Asf);
    const uint32_t sB = (uint32_t)__cvta_generic_to_shared(Bsf);

    auto load_stage = [&](int s, int k0) {
#pragma unroll
        for (int c = 0; c < 4; c++) {
            const int cc = (c + arot) & 3;
            cpa16(sA + (uint32_t)((s * 128 + lm) * AST + cc * 4) * 4, arp + k0 + cc * 4, asz);
        }
#pragma unroll
        for (int c = 0; c < 4; c++) {
            const int k = c * 4 + bw;
            cpa16(sB + (uint32_t)((s * 16 + k) * BST + bn) * 4,
                  bbase + (size_t)(k0 + k) * ldb + bn, 16);
        }
    };

    load_stage(0, 0);
    cpa_commit();
    if (nt > 1) load_stage(1, 16);
    cpa_commit();

    const int cb = wn + (lane >> 2);
    const int kq = lane & 3;
    const int lrow = lane & 15;
    const int lcol = (lane >> 4) << 2;

    int cur = 0, n2 = 2;
    for (int t = 0; t < nt; t++) {
        cpa_wait1();
        __syncthreads();
        if (t + 2 < nt) load_stage(n2, (t + 2) * 16);
        cpa_commit();

#pragma unroll
        for (int ks = 0; ks < 2; ks++) {
            const int klo = ks * 8;
            const int kk = klo + kq;
            uint32_t af[4][4], bf[8][2];
#pragma unroll
            for (int i = 0; i < 4; i++) {
                const uint32_t addr = sA +
                    (uint32_t)((cur * 128 + wm + i * 16 + lrow) * AST + klo + lcol) * 4;
                ldsm4(af[i][0], af[i][1], af[i][2], af[i][3], addr);
            }
#pragma unroll
            for (int j = 0; j < 8; j++) {
                bf[j][0] = __float_as_uint(Bsf[(cur * 16 + kk) * BST + cb + j * 8]);
                bf[j][1] = __float_as_uint(Bsf[(cur * 16 + kk + 4) * BST + cb + j * 8]);
            }
#pragma unroll
            for (int i = 0; i < 4; i++)
#pragma unroll
                for (int j = 0; j < 8; j++)
                    mma_tf32(acc[i][j], af[i], bf[j]);
        }
        cur = (cur == 2) ? 0 : cur + 1;
        n2  = (n2  == 2) ? 0 : n2  + 1;
    }

    // ---------------- epilogues ----------------
#pragma unroll
    for (int i = 0; i < 4; i++) {
#pragma unroll
        for (int rr = 0; rr < 2; rr++) {
            const int r = m0 + wm + i * 16 + (lane >> 2) + rr * 8;
            if (r >= Mz) continue;
            if (MODE==GM_QKV) {
#pragma unroll
                for (int j = 0; j < 8; j++) {
                    const int c = n0 + wn + j * 8 + (lane & 3) * 2;
                    float v0 = acc[i][j][rr * 2 + 0] + g_bqkv[c];
                    float v1 = acc[i][j][rr * 2 + 1] + g_bqkv[c + 1];
                    if (c < 2048) {
                        g_q[(size_t)r * 2048 + c]     = v0;
                        g_q[(size_t)r * 2048 + c + 1] = v1;
                    } else if (c < 2304) {
                        g_k[(size_t)r * 256 + c - 2048]     = v0;
                        g_k[(size_t)r * 256 + c - 2048 + 1] = v1;
                    } else {
                        g_v[(size_t)r * 256 + c - 2304]     = tf32r(v0);
                        g_v[(size_t)r * 256 + c - 2304 + 1] = tf32r(v1);
                    }
                }
            } else if (MODE==GM_MGU) {
                // interleaved gate/up: v0 = gate_i, v1 = up_i, i = c/2
                float* dst = g_mg + ((size_t)z * Tc + r) * IM;
#pragma unroll
                for (int j = 0; j < 8; j++) {
                    const int c = n0 + wn + j * 8 + (lane & 3) * 2;
                    const float g0 = acc[i][j][rr * 2 + 0];
                    const float u0 = acc[i][j][rr * 2 + 1];
                    dst[c >> 1] = tf32r(silu(g0) * u0);
                }
            } else if (MODE==GM_SGU) {
                float* dst = g_sgv + (size_t)r * ISH;
#pragma unroll
                for (int j = 0; j < 8; j++) {
                    const int c = n0 + wn + j * 8 + (lane & 3) * 2;
                    const float g0 = acc[i][j][rr * 2 + 0];
                    const float u0 = acc[i][j][rr * 2 + 1];
                    dst[c >> 1] = tf32r(silu(g0) * u0);
                }
            } else if (MODE==GM_MD) {
                const int tok = g_list[z * Tc + r];
                const float w = g_dw[tok * Ec + z];
                float* dst = g_moe + (size_t)tok * 2048;
#pragma unroll
                for (int j = 0; j < 8; j++) {
                    const int c = n0 + wn + j * 8 + (lane & 3) * 2;
                    atomicAdd(dst + c,     acc[i][j][rr * 2 + 0] * w);
                    atomicAdd(dst + c + 1, acc[i][j][rr * 2 + 1] * w);
                }
            } else {
                float* Cp; const float* res = nullptr;
                if (MODE==GM_O) { Cp = g_x; res = extra; }
                else            { Cp = g_sh; }    // GM_SD
                const size_t rowoff = (size_t)r * 2048;
#pragma unroll
                for (int j = 0; j < 8; j++) {
                    const int c = n0 + wn + j * 8 + (lane & 3) * 2;
                    float v0 = acc[i][j][rr * 2 + 0];
                    float v1 = acc[i][j][rr * 2 + 1];
                    if (res)  { v0 += res[rowoff + c]; v1 += res[rowoff + c + 1]; }
                    Cp[rowoff + c]     = v0;
                    Cp[rowoff + c + 1] = v1;
                }
            }
        }
    }
}

// ---------------- launch ----------------
extern "C" void kernel_launch(void* const* d_in, const int* in_sizes, int n_in,
                              void* d_out, int out_size) {
    (void)in_sizes; (void)n_in; (void)out_size;
    const float* x0  = (const float*)d_in[0];
    const float* ln1 = (const float*)d_in[1];
    const float* wq  = (const float*)d_in[2];
    const float* bq  = (const float*)d_in[3];
    const float* wk  = (const float*)d_in[4];
    const float* bk  = (const float*)d_in[5];
    const float* wv  = (const float*)d_in[6];
    const float* bv  = (const float*)d_in[7];
    const float* wo  = (const float*)d_in[8];
    const float* ln2 = (const float*)d_in[9];
    const float* rw  = (const float*)d_in[10];
    const float* wg  = (const float*)d_in[11];
    const float* wu  = (const float*)d_in[12];
    const float* wd  = (const float*)d_in[13];
    const float* swg = (const float*)d_in[14];
    const float* swu = (const float*)d_in[15];
    const float* swd = (const float*)d_in[16];
    const float* sgw = (const float*)d_in[17];
    float* out = (float*)d_out;

    cudaFuncSetAttribute(gemm_kernel<GM_QKV>, cudaFuncAttributeMaxDynamicSharedMemorySize, GSMEM);
    cudaFuncSetAttribute(gemm_kernel<GM_O>,   cudaFuncAttributeMaxDynamicSharedMemorySize, GSMEM);
    cudaFuncSetAttribute(gemm_kernel<GM_MGU>, cudaFuncAttributeMaxDynamicSharedMemorySize, GSMEM);
    cudaFuncSetAttribute(gemm_kernel<GM_MD>,  cudaFuncAttributeMaxDynamicSharedMemorySize, GSMEM);
    cudaFuncSetAttribute(gemm_kernel<GM_SGU>, cudaFuncAttributeMaxDynamicSharedMemorySize, GSMEM);
    cudaFuncSetAttribute(gemm_kernel<GM_SD>,  cudaFuncAttributeMaxDynamicSharedMemorySize, GSMEM);
    cudaFuncSetAttribute(flash_kernel,        cudaFuncAttributeMaxDynamicSharedMemorySize, FSMEM);

    auto b4 = [](size_t n) { return (unsigned)((n + 255) / 256); };

    // QKV interleaved into [2048][2560] (float4 granularity)
    round_copy_str_kernel<<<b4((size_t)2048*512), 256>>>(wq, 2048*512, 512, NQKV, 0);
    round_copy_str_kernel<<<b4((size_t)2048*64),  256>>>(wk, 2048*64,  64,  NQKV, 2048);
    round_copy_str_kernel<<<b4((size_t)2048*64),  256>>>(wv, 2048*64,  64,  NQKV, 2304);
    bias_concat_kernel<<<10, 256>>>(bq, bk, bv);
    round_copy_kernel<OFF_WO ><<<b4((size_t)2048*512), 256>>>(wo, 2048*512);
    // gate/up interleaved (pairwise): out4[s2] = {g.x,u.x,g.y,u.y}
    round_ilv_kernel<OFF_WGU ><<<b4((size_t)Ec*2048*IM/2), 256>>>(wg, wu, Ec*2048*IM/2);
    round_copy_kernel<OFF_WD ><<<b4((size_t)Ec*IM*512), 256>>>(wd, Ec*IM*512);
    round_ilv_kernel<OFF_SWGU><<<b4((size_t)2048*ISH/2), 256>>>(swg, swu, 2048*ISH/2);
    round_copy_kernel<OFF_SWD><<<b4((size_t)ISH*512), 256>>>(swd, ISH*512);

    clear_cnt_kernel<<<1, 32>>>();
    clear_moe_kernel<<<(Tc * Hc) / 1024, 256>>>();

    // attention
    rmsnorm_kernel<0><<<Tc, 256>>>(x0, ln1);
    gemm_kernel<GM_QKV><<<dim3(20, 32, 1), 128, GSMEM>>>(nullptr);
    rope_kernel<<<dim3(Tc, NQc + NKVc), 64>>>();
    kT_kernel<<<(Bc * NKVc * DHc * Sc) / 256, 256>>>();
    flash_kernel<<<dim3(1, 16, 32), 256, FSMEM>>>();
    gemm_kernel<GM_O><<<dim3(16, 32, 1), 128, GSMEM>>>(x0);

    // MoE block (fused gate/up + act in one GEMM)
    rmsnorm_kernel<1><<<Tc, 256>>>(nullptr, ln2);
    router_kernel<<<Tc / 8, 256>>>(rw);
    gemm_kernel<GM_MGU><<<dim3(22, 32, 8), 128, GSMEM>>>(nullptr);
    gemm_kernel<GM_MD><<<dim3(16, 32, 8), 128, GSMEM>>>(nullptr);

    // shared expert (fused gate/up + act in one GEMM)
    gemm_kernel<GM_SGU><<<dim3(88, 32, 1), 128, GSMEM>>>(nullptr);
    sgate_kernel<<<Tc / 8, 256>>>(sgw);
    gemm_kernel<GM_SD><<<dim3(16, 32, 1), 128, GSMEM>>>(nullptr);

    final_kernel<<<(Tc * Hc) / 1024, 256>>>(out);
}